// round 1
// baseline (speedup 1.0000x reference)
#include <cuda_runtime.h>
#include <math_constants.h>
#include <cstddef>

#define B_SZ 8
#define S_SZ 1024
#define D_SZ 1024
#define H_SZ 16
#define DK_SZ 64

// Scratch (allocation-free rule: __device__ globals)
__device__ float g_qp[B_SZ * S_SZ * D_SZ];
__device__ float g_kp[B_SZ * S_SZ * D_SZ];
__device__ float g_vp[B_SZ * S_SZ * D_SZ];
__device__ float g_att[B_SZ * S_SZ * D_SZ];

// ---------------------------------------------------------------------------
// C[m,n] = sum_k A[m,k] * W[n,k] + bias[n]
// A: [M,K] row-major, W: [N,K] row-major (x @ W^T semantics)
// 128x128 block tile, BK=16, 256 threads, 8x8 micro-tile per thread.
// ---------------------------------------------------------------------------
__global__ __launch_bounds__(256) void sgemm_xwT(
    const float* __restrict__ A, const float* __restrict__ W,
    const float* __restrict__ bias, float* __restrict__ C,
    int M, int N, int K)
{
    __shared__ float As[16][128];
    __shared__ float Ws[16][128];

    const int tid = threadIdx.x;
    const int bm = blockIdx.y * 128;
    const int bn = blockIdx.x * 128;
    const int tx = tid & 15;      // 0..15  (N direction)
    const int ty = tid >> 4;      // 0..15  (M direction)
    const int lr = tid >> 2;      // 0..63  loader row
    const int lc = (tid & 3) << 2; // 0,4,8,12 loader col group

    float acc[8][8];
#pragma unroll
    for (int i = 0; i < 8; i++)
#pragma unroll
        for (int j = 0; j < 8; j++) acc[i][j] = 0.f;

    for (int k0 = 0; k0 < K; k0 += 16) {
#pragma unroll
        for (int rr = 0; rr < 2; rr++) {
            int row = lr + rr * 64;
            float4 a = *(const float4*)(A + (size_t)(bm + row) * K + k0 + lc);
            As[lc + 0][row] = a.x; As[lc + 1][row] = a.y;
            As[lc + 2][row] = a.z; As[lc + 3][row] = a.w;
            float4 w = *(const float4*)(W + (size_t)(bn + row) * K + k0 + lc);
            Ws[lc + 0][row] = w.x; Ws[lc + 1][row] = w.y;
            Ws[lc + 2][row] = w.z; Ws[lc + 3][row] = w.w;
        }
        __syncthreads();
#pragma unroll
        for (int kk = 0; kk < 16; kk++) {
            float ra[8], rb[8];
            *(float4*)(ra)     = *(const float4*)&As[kk][ty * 8];
            *(float4*)(ra + 4) = *(const float4*)&As[kk][ty * 8 + 4];
            *(float4*)(rb)     = *(const float4*)&Ws[kk][tx * 8];
            *(float4*)(rb + 4) = *(const float4*)&Ws[kk][tx * 8 + 4];
#pragma unroll
            for (int i = 0; i < 8; i++)
#pragma unroll
                for (int j = 0; j < 8; j++)
                    acc[i][j] += ra[i] * rb[j];
        }
        __syncthreads();
    }

#pragma unroll
    for (int i = 0; i < 8; i++) {
        float* crow = C + (size_t)(bm + ty * 8 + i) * N + bn + tx * 8;
#pragma unroll
        for (int j = 0; j < 8; j += 4) {
            float4 r4;
            r4.x = acc[i][j + 0] + bias[bn + tx * 8 + j + 0];
            r4.y = acc[i][j + 1] + bias[bn + tx * 8 + j + 1];
            r4.z = acc[i][j + 2] + bias[bn + tx * 8 + j + 2];
            r4.w = acc[i][j + 3] + bias[bn + tx * 8 + j + 3];
            *(float4*)(crow + j) = r4;
        }
    }
}

// ---------------------------------------------------------------------------
// RoPE (rotate_half convention over full D), in-place. One thread owns the
// pair (d, d+512) so in-place is race-free.
// x: [B,S,D]; cos/sin: [S,D]
// ---------------------------------------------------------------------------
__global__ __launch_bounds__(256) void rope_kernel(
    float* __restrict__ x, const float* __restrict__ ct,
    const float* __restrict__ st)
{
    int idx = blockIdx.x * blockDim.x + threadIdx.x;   // B*S*512 total
    int dh = idx & 511;
    int bs = idx >> 9;                                 // 0..B*S-1
    int s  = bs & 1023;
    float* row = x + (size_t)bs * D_SZ;
    float c1 = ct[s * D_SZ + dh],       s1 = st[s * D_SZ + dh];
    float c2 = ct[s * D_SZ + dh + 512], s2 = st[s * D_SZ + dh + 512];
    float x1 = row[dh], x2 = row[dh + 512];
    row[dh]       = x1 * c1 - x2 * s1;   // rot lower half = -x2
    row[dh + 512] = x2 * c2 + x1 * s2;   // rot upper half = +x1
}

// ---------------------------------------------------------------------------
// Fused attention, one thread per query row, streaming (online) softmax.
// Per block: one (b,h) pair, 128 query rows. K/V staged in 64x64 smem tiles.
// prior = -sigmoid(att_prior_bias[h]) * |q - k|  (short_matrix closed form)
// out written in concat layout [B,S,D] with d = h*64 + dk.
// ---------------------------------------------------------------------------
__global__ __launch_bounds__(128) void attn_kernel(
    const float* __restrict__ qp, const float* __restrict__ kp,
    const float* __restrict__ vp, const float* __restrict__ mask,
    const float* __restrict__ prior_bias, float* __restrict__ out)
{
    __shared__ float Ks[64][64];
    __shared__ float Vs[64][64];

    const int bh = blockIdx.y;           // 0..127
    const int b = bh >> 4;
    const int h = bh & 15;
    const int q_idx = blockIdx.x * 128 + threadIdx.x;   // 0..1023

    const float sig = 1.0f / (1.0f + __expf(-prior_bias[h]));
    const float qf = (float)q_idx;

    const float* qrow = qp + ((size_t)b * S_SZ + q_idx) * D_SZ + h * DK_SZ;
    float qv[64];
#pragma unroll
    for (int d = 0; d < 64; d += 4)
        *(float4*)&qv[d] = *(const float4*)&qrow[d];

    float o[64];
#pragma unroll
    for (int d = 0; d < 64; d++) o[d] = 0.f;
    float m = -CUDART_INF_F;
    float l = 0.f;

    const int jr = threadIdx.x >> 1;        // 0..63
    const int jc = (threadIdx.x & 1) << 5;  // 0 / 32

    for (int k0 = 0; k0 < S_SZ; k0 += 64) {
        const float* ksrc = kp + ((size_t)b * S_SZ + k0 + jr) * D_SZ + h * DK_SZ + jc;
        const float* vsrc = vp + ((size_t)b * S_SZ + k0 + jr) * D_SZ + h * DK_SZ + jc;
#pragma unroll
        for (int d = 0; d < 32; d += 4) {
            *(float4*)&Ks[jr][jc + d] = *(const float4*)&ksrc[d];
            *(float4*)&Vs[jr][jc + d] = *(const float4*)&vsrc[d];
        }
        __syncthreads();

        for (int j = 0; j < 64; j++) {
            float s = 0.f;
#pragma unroll
            for (int d = 0; d < 64; d += 4) {
                float4 k4 = *(const float4*)&Ks[j][d];
                s += qv[d] * k4.x + qv[d + 1] * k4.y
                   + qv[d + 2] * k4.z + qv[d + 3] * k4.w;
            }
            const int kidx = k0 + j;
            s = s * 0.125f + mask[b * S_SZ + kidx] - sig * fabsf(qf - (float)kidx);

            if (s <= m) {                       // common path: no max update
                float p = __expf(s - m);
                l += p;
#pragma unroll
                for (int d = 0; d < 64; d += 4) {
                    float4 v4 = *(const float4*)&Vs[j][d];
                    o[d]     += p * v4.x; o[d + 1] += p * v4.y;
                    o[d + 2] += p * v4.z; o[d + 3] += p * v4.w;
                }
            } else {                            // rare: rescale history
                float r = __expf(m - s);        // expf(-inf)=0 handles init
                m = s;
                l = l * r + 1.f;
#pragma unroll
                for (int d = 0; d < 64; d += 4) {
                    float4 v4 = *(const float4*)&Vs[j][d];
                    o[d]     = o[d]     * r + v4.x;
                    o[d + 1] = o[d + 1] * r + v4.y;
                    o[d + 2] = o[d + 2] * r + v4.z;
                    o[d + 3] = o[d + 3] * r + v4.w;
                }
            }
        }
        __syncthreads();
    }

    const float inv = 1.0f / l;
    float* dst = out + ((size_t)b * S_SZ + q_idx) * D_SZ + h * DK_SZ;
#pragma unroll
    for (int d = 0; d < 64; d += 4) {
        float4 r4 = make_float4(o[d] * inv, o[d + 1] * inv,
                                o[d + 2] * inv, o[d + 3] * inv);
        *(float4*)&dst[d] = r4;
    }
}

// ---------------------------------------------------------------------------
extern "C" void kernel_launch(void* const* d_in, const int* in_sizes, int n_in,
                              void* d_out, int out_size)
{
    const float* q     = (const float*)d_in[0];
    const float* k     = (const float*)d_in[1];
    const float* v     = (const float*)d_in[2];
    const float* cosp  = (const float*)d_in[3];
    const float* sinp  = (const float*)d_in[4];
    const float* maskp = (const float*)d_in[5];
    // d_in[6] = short_matrix (computed analytically: -|i-j|)
    const float* Wq = (const float*)d_in[7];
    const float* bq = (const float*)d_in[8];
    const float* Wk = (const float*)d_in[9];
    const float* bk = (const float*)d_in[10];
    const float* Wv = (const float*)d_in[11];
    const float* bv = (const float*)d_in[12];
    const float* Wo = (const float*)d_in[13];
    const float* bo = (const float*)d_in[14];
    const float* apb = (const float*)d_in[15];

    float *qp, *kp, *vp, *att;
    cudaGetSymbolAddress((void**)&qp,  g_qp);
    cudaGetSymbolAddress((void**)&kp,  g_kp);
    cudaGetSymbolAddress((void**)&vp,  g_vp);
    cudaGetSymbolAddress((void**)&att, g_att);

    const int M = B_SZ * S_SZ;     // 8192
    const int N = D_SZ;            // 1024
    const int K = D_SZ;            // 1024
    dim3 gg(N / 128, M / 128);     // (8, 64)

    sgemm_xwT<<<gg, 256>>>(q, Wq, bq, qp, M, N, K);
    sgemm_xwT<<<gg, 256>>>(k, Wk, bk, kp, M, N, K);
    sgemm_xwT<<<gg, 256>>>(v, Wv, bv, vp, M, N, K);

    const int rope_threads = B_SZ * S_SZ * (D_SZ / 2);   // 4,194,304
    rope_kernel<<<rope_threads / 256, 256>>>(qp, cosp, sinp);
    rope_kernel<<<rope_threads / 256, 256>>>(kp, cosp, sinp);

    attn_kernel<<<dim3(S_SZ / 128, B_SZ * H_SZ), 128>>>(qp, kp, vp, maskp, apb, att);

    sgemm_xwT<<<gg, 256>>>(att, Wo, bo, (float*)d_out, M, N, K);
}

// round 3
// speedup vs baseline: 1.4163x; 1.4163x over previous
#include <cuda_runtime.h>
#include <cuda_bf16.h>
#include <math_constants.h>
#include <cstdint>
#include <cstddef>

#define B_SZ 8
#define S_SZ 1024
#define D_SZ 1024
#define H_SZ 16
#define DK_SZ 64
#define MROWS (B_SZ * S_SZ)   /* 8192 */

// ---------------------------------------------------------------------------
// Scratch (allocation-free rule: __device__ globals)
// ---------------------------------------------------------------------------
__device__ float g_qp[MROWS * D_SZ];
__device__ float g_kp[MROWS * D_SZ];
__device__ float g_vp[MROWS * D_SZ];
__device__ float g_att[MROWS * D_SZ];
__device__ __nv_bfloat16 g_ahi[MROWS * D_SZ];
__device__ __nv_bfloat16 g_alo[MROWS * D_SZ];
__device__ __nv_bfloat16 g_whi[4][D_SZ * D_SZ];
__device__ __nv_bfloat16 g_wlo[4][D_SZ * D_SZ];

// ---------------------------------------------------------------------------
__device__ __forceinline__ uint32_t smem_u32(const void* p) {
    uint32_t a;
    asm("{ .reg .u64 t; cvta.to.shared.u64 t, %1; cvt.u32.u64 %0, t; }"
        : "=r"(a) : "l"(p));
    return a;
}

__device__ __forceinline__ void cp_async16(uint32_t dst, const void* src) {
    asm volatile("cp.async.cg.shared.global [%0], [%1], 16;\n"
                 :: "r"(dst), "l"(src) : "memory");
}
#define CP_COMMIT() asm volatile("cp.async.commit_group;\n" ::: "memory")
#define CP_WAIT(n)  asm volatile("cp.async.wait_group %0;\n" :: "n"(n) : "memory")

__device__ __forceinline__ void mma16816(
    float& d0, float& d1, float& d2, float& d3,
    uint32_t a0, uint32_t a1, uint32_t a2, uint32_t a3,
    uint32_t b0, uint32_t b1)
{
    asm volatile(
        "mma.sync.aligned.m16n8k16.row.col.f32.bf16.bf16.f32 "
        "{%0,%1,%2,%3}, {%4,%5,%6,%7}, {%8,%9}, {%0,%1,%2,%3};\n"
        : "+f"(d0), "+f"(d1), "+f"(d2), "+f"(d3)
        : "r"(a0), "r"(a1), "r"(a2), "r"(a3), "r"(b0), "r"(b1));
}

// ---------------------------------------------------------------------------
// fp32 -> (bf16 hi, bf16 lo) split. x ~= hi + lo (residual ~2^-18 |x|)
// ---------------------------------------------------------------------------
__global__ __launch_bounds__(256) void cvt_hilo(
    const float* __restrict__ x, __nv_bfloat16* __restrict__ hi,
    __nv_bfloat16* __restrict__ lo)
{
    int i = blockIdx.x * blockDim.x + threadIdx.x;   // one float4
    float4 v = ((const float4*)x)[i];
    __nv_bfloat16 h0 = __float2bfloat16_rn(v.x);
    __nv_bfloat16 h1 = __float2bfloat16_rn(v.y);
    __nv_bfloat16 h2 = __float2bfloat16_rn(v.z);
    __nv_bfloat16 h3 = __float2bfloat16_rn(v.w);
    __nv_bfloat16 l0 = __float2bfloat16_rn(v.x - __bfloat162float(h0));
    __nv_bfloat16 l1 = __float2bfloat16_rn(v.y - __bfloat162float(h1));
    __nv_bfloat16 l2 = __float2bfloat16_rn(v.z - __bfloat162float(h2));
    __nv_bfloat16 l3 = __float2bfloat16_rn(v.w - __bfloat162float(h3));
    __nv_bfloat162* hp = (__nv_bfloat162*)hi;
    __nv_bfloat162* lp = (__nv_bfloat162*)lo;
    hp[2 * i]     = __nv_bfloat162(h0, h1);
    hp[2 * i + 1] = __nv_bfloat162(h2, h3);
    lp[2 * i]     = __nv_bfloat162(l0, l1);
    lp[2 * i + 1] = __nv_bfloat162(l2, l3);
}

// ---------------------------------------------------------------------------
// Tensor-core GEMM via mma.sync (HMMA): C[m,n] = sum_k A[m,k]*W[n,k] + bias[n]
// hi/lo bf16 split, 3 accumulation terms. Block 128x128x32, 8 warps (4Mx2N),
// warp tile 32x64 (2x8 m16n8k16 frags). cp.async double buffer.
// M=8192, N=K=1024 fixed.
// ---------------------------------------------------------------------------
#define GBK 32
#define GPAD 40                         /* padded row stride (bf16 elems) */
#define TILE_ELEMS (128 * GPAD)         /* 5120 */
#define BUF_ELEMS (4 * TILE_ELEMS)      /* 20480 */
#define GEMM_SMEM_BYTES (2 * BUF_ELEMS * 2)  /* 81920 */

__global__ __launch_bounds__(256) void gemm_mma(
    const __nv_bfloat16* __restrict__ Ahi, const __nv_bfloat16* __restrict__ Alo,
    const __nv_bfloat16* __restrict__ Whi, const __nv_bfloat16* __restrict__ Wlo,
    const float* __restrict__ bias, float* __restrict__ C)
{
    extern __shared__ __nv_bfloat16 sm[];
    const uint32_t sb = smem_u32(sm);

    const int tid = threadIdx.x;
    const int wid = tid >> 5;
    const int lane = tid & 31;
    const int group = lane >> 2;        // 0..7
    const int tig = lane & 3;           // 0..3
    const int wm = wid & 3;             // warp M index (0..3)
    const int wn = wid >> 2;            // warp N index (0..1)
    const int bm = blockIdx.y * 128;
    const int bn = blockIdx.x * 128;

    const __nv_bfloat16* gsrc[4] = {
        Ahi + (size_t)bm * D_SZ, Alo + (size_t)bm * D_SZ,
        Whi + (size_t)bn * D_SZ, Wlo + (size_t)bn * D_SZ };

    // per-thread loader indices: 8 x uint4 covering 4 tiles x 128 rows x 32 cols
    // linear t in [0,2048): tile = t>>9, row = (t>>2)&127, c4 = t&3
    float acc[2][8][4];
#pragma unroll
    for (int i = 0; i < 2; i++)
#pragma unroll
        for (int j = 0; j < 8; j++)
#pragma unroll
            for (int r = 0; r < 4; r++) acc[i][j][r] = 0.f;

    auto load_chunk = [&](int c, int buf) {
        const int k0 = c * GBK;
        const uint32_t bbase = sb + (uint32_t)buf * (BUF_ELEMS * 2);
#pragma unroll
        for (int it = 0; it < 8; it++) {
            int t = tid + it * 256;
            int tile = t >> 9;
            int r = (t >> 2) & 127;
            int c4 = t & 3;
            const __nv_bfloat16* src = gsrc[tile] + (size_t)r * D_SZ + k0 + c4 * 8;
            uint32_t dst = bbase + (uint32_t)(tile * TILE_ELEMS + r * GPAD + c4 * 8) * 2u;
            cp_async16(dst, src);
        }
    };

    load_chunk(0, 0);
    CP_COMMIT();

    for (int c = 0; c < D_SZ / GBK; ++c) {
        if (c + 1 < D_SZ / GBK) {
            load_chunk(c + 1, (c + 1) & 1);
            CP_COMMIT();
            CP_WAIT(1);
        } else {
            CP_WAIT(0);
        }
        __syncthreads();

        const uint32_t bbase = sb + (uint32_t)(c & 1) * (BUF_ELEMS * 2);
        // 3 passes: (Ahi,Whi), (Ahi,Wlo), (Alo,Whi)
#pragma unroll
        for (int pass = 0; pass < 3; ++pass) {
            const int at = (pass == 2) ? 1 : 0;
            const int wt = (pass == 1) ? 3 : 2;
            const uint32_t aB = bbase + (uint32_t)(at * TILE_ELEMS) * 2u;
            const uint32_t wB = bbase + (uint32_t)(wt * TILE_ELEMS) * 2u;
#pragma unroll
            for (int ks = 0; ks < 2; ++ks) {
                const int kk = ks * 16 + tig * 2;
                uint32_t a[2][4];
#pragma unroll
                for (int mt = 0; mt < 2; ++mt) {
                    const int r0 = wm * 32 + mt * 16 + group;
                    uint32_t p00 = aB + (uint32_t)(r0 * GPAD + kk) * 2u;
                    uint32_t p10 = aB + (uint32_t)((r0 + 8) * GPAD + kk) * 2u;
                    asm volatile("ld.shared.b32 %0, [%1];" : "=r"(a[mt][0]) : "r"(p00));
                    asm volatile("ld.shared.b32 %0, [%1];" : "=r"(a[mt][1]) : "r"(p10));
                    asm volatile("ld.shared.b32 %0, [%1];" : "=r"(a[mt][2]) : "r"(p00 + 16));
                    asm volatile("ld.shared.b32 %0, [%1];" : "=r"(a[mt][3]) : "r"(p10 + 16));
                }
#pragma unroll
                for (int nt = 0; nt < 8; ++nt) {
                    const int nr = wn * 64 + nt * 8 + group;
                    uint32_t pb = wB + (uint32_t)(nr * GPAD + kk) * 2u;
                    uint32_t b0, b1;
                    asm volatile("ld.shared.b32 %0, [%1];" : "=r"(b0) : "r"(pb));
                    asm volatile("ld.shared.b32 %0, [%1];" : "=r"(b1) : "r"(pb + 16));
                    mma16816(acc[0][nt][0], acc[0][nt][1], acc[0][nt][2], acc[0][nt][3],
                             a[0][0], a[0][1], a[0][2], a[0][3], b0, b1);
                    mma16816(acc[1][nt][0], acc[1][nt][1], acc[1][nt][2], acc[1][nt][3],
                             a[1][0], a[1][1], a[1][2], a[1][3], b0, b1);
                }
            }
        }
        __syncthreads();
    }

    // epilogue: C[m][n] = acc + bias[n]
#pragma unroll
    for (int mt = 0; mt < 2; ++mt) {
        const int m0 = bm + wm * 32 + mt * 16 + group;
#pragma unroll
        for (int nt = 0; nt < 8; ++nt) {
            const int col = bn + wn * 64 + nt * 8 + tig * 2;
            const float bx = bias[col], by = bias[col + 1];
            float2 r0 = make_float2(acc[mt][nt][0] + bx, acc[mt][nt][1] + by);
            float2 r1 = make_float2(acc[mt][nt][2] + bx, acc[mt][nt][3] + by);
            *(float2*)(C + (size_t)m0 * D_SZ + col) = r0;
            *(float2*)(C + (size_t)(m0 + 8) * D_SZ + col) = r1;
        }
    }
}

// ---------------------------------------------------------------------------
// RoPE (rotate_half over full D), in-place.
// ---------------------------------------------------------------------------
__global__ __launch_bounds__(256) void rope_kernel(
    float* __restrict__ x, const float* __restrict__ ct,
    const float* __restrict__ st)
{
    int idx = blockIdx.x * blockDim.x + threadIdx.x;
    int dh = idx & 511;
    int bs = idx >> 9;
    int s  = bs & 1023;
    float* row = x + (size_t)bs * D_SZ;
    float c1 = ct[s * D_SZ + dh],       s1 = st[s * D_SZ + dh];
    float c2 = ct[s * D_SZ + dh + 512], s2 = st[s * D_SZ + dh + 512];
    float x1 = row[dh], x2 = row[dh + 512];
    row[dh]       = x1 * c1 - x2 * s1;
    row[dh + 512] = x2 * c2 + x1 * s2;
}

// ---------------------------------------------------------------------------
// Fused attention, one thread per query row, streaming softmax.
// ---------------------------------------------------------------------------
__global__ __launch_bounds__(128) void attn_kernel(
    const float* __restrict__ qp, const float* __restrict__ kp,
    const float* __restrict__ vp, const float* __restrict__ mask,
    const float* __restrict__ prior_bias, float* __restrict__ out)
{
    __shared__ float Ks[64][64];
    __shared__ float Vs[64][64];

    const int bh = blockIdx.y;
    const int b = bh >> 4;
    const int h = bh & 15;
    const int q_idx = blockIdx.x * 128 + threadIdx.x;

    const float sig = 1.0f / (1.0f + __expf(-prior_bias[h]));
    const float qf = (float)q_idx;

    const float* qrow = qp + ((size_t)b * S_SZ + q_idx) * D_SZ + h * DK_SZ;
    float qv[64];
#pragma unroll
    for (int d = 0; d < 64; d += 4)
        *(float4*)&qv[d] = *(const float4*)&qrow[d];

    float o[64];
#pragma unroll
    for (int d = 0; d < 64; d++) o[d] = 0.f;
    float m = -CUDART_INF_F;
    float l = 0.f;

    const int jr = threadIdx.x >> 1;
    const int jc = (threadIdx.x & 1) << 5;

    for (int k0 = 0; k0 < S_SZ; k0 += 64) {
        const float* ksrc = kp + ((size_t)b * S_SZ + k0 + jr) * D_SZ + h * DK_SZ + jc;
        const float* vsrc = vp + ((size_t)b * S_SZ + k0 + jr) * D_SZ + h * DK_SZ + jc;
#pragma unroll
        for (int d = 0; d < 32; d += 4) {
            *(float4*)&Ks[jr][jc + d] = *(const float4*)&ksrc[d];
            *(float4*)&Vs[jr][jc + d] = *(const float4*)&vsrc[d];
        }
        __syncthreads();

        for (int j = 0; j < 64; j++) {
            float s = 0.f;
#pragma unroll
            for (int d = 0; d < 64; d += 4) {
                float4 k4 = *(const float4*)&Ks[j][d];
                s += qv[d] * k4.x + qv[d + 1] * k4.y
                   + qv[d + 2] * k4.z + qv[d + 3] * k4.w;
            }
            const int kidx = k0 + j;
            s = s * 0.125f + mask[b * S_SZ + kidx] - sig * fabsf(qf - (float)kidx);

            if (s <= m) {
                float p = __expf(s - m);
                l += p;
#pragma unroll
                for (int d = 0; d < 64; d += 4) {
                    float4 v4 = *(const float4*)&Vs[j][d];
                    o[d]     += p * v4.x; o[d + 1] += p * v4.y;
                    o[d + 2] += p * v4.z; o[d + 3] += p * v4.w;
                }
            } else {
                float r = __expf(m - s);
                m = s;
                l = l * r + 1.f;
#pragma unroll
                for (int d = 0; d < 64; d += 4) {
                    float4 v4 = *(const float4*)&Vs[j][d];
                    o[d]     = o[d]     * r + v4.x;
                    o[d + 1] = o[d + 1] * r + v4.y;
                    o[d + 2] = o[d + 2] * r + v4.z;
                    o[d + 3] = o[d + 3] * r + v4.w;
                }
            }
        }
        __syncthreads();
    }

    const float inv = 1.0f / l;
    float* dst = out + ((size_t)b * S_SZ + q_idx) * D_SZ + h * DK_SZ;
#pragma unroll
    for (int d = 0; d < 64; d += 4) {
        float4 r4 = make_float4(o[d] * inv, o[d + 1] * inv,
                                o[d + 2] * inv, o[d + 3] * inv);
        *(float4*)&dst[d] = r4;
    }
}

// ---------------------------------------------------------------------------
extern "C" void kernel_launch(void* const* d_in, const int* in_sizes, int n_in,
                              void* d_out, int out_size)
{
    const float* q     = (const float*)d_in[0];
    const float* k     = (const float*)d_in[1];
    const float* v     = (const float*)d_in[2];
    const float* cosp  = (const float*)d_in[3];
    const float* sinp  = (const float*)d_in[4];
    const float* maskp = (const float*)d_in[5];
    // d_in[6] = short_matrix (analytic: -|i-j|)
    const float* Wq = (const float*)d_in[7];
    const float* bq = (const float*)d_in[8];
    const float* Wk = (const float*)d_in[9];
    const float* bk = (const float*)d_in[10];
    const float* Wv = (const float*)d_in[11];
    const float* bv = (const float*)d_in[12];
    const float* Wo = (const float*)d_in[13];
    const float* bo = (const float*)d_in[14];
    const float* apb = (const float*)d_in[15];

    float *qp, *kp, *vp, *att;
    __nv_bfloat16 *ahi, *alo, *whi, *wlo;
    cudaGetSymbolAddress((void**)&qp,  g_qp);
    cudaGetSymbolAddress((void**)&kp,  g_kp);
    cudaGetSymbolAddress((void**)&vp,  g_vp);
    cudaGetSymbolAddress((void**)&att, g_att);
    cudaGetSymbolAddress((void**)&ahi, g_ahi);
    cudaGetSymbolAddress((void**)&alo, g_alo);
    cudaGetSymbolAddress((void**)&whi, g_whi);
    cudaGetSymbolAddress((void**)&wlo, g_wlo);

    cudaFuncSetAttribute(gemm_mma, cudaFuncAttributeMaxDynamicSharedMemorySize,
                         GEMM_SMEM_BYTES);

    const int WN = D_SZ * D_SZ;
    const int wblk = (WN / 4) / 256;
    cvt_hilo<<<wblk, 256>>>(Wq, whi + 0 * WN, wlo + 0 * WN);
    cvt_hilo<<<wblk, 256>>>(Wk, whi + 1 * WN, wlo + 1 * WN);
    cvt_hilo<<<wblk, 256>>>(Wv, whi + 2 * WN, wlo + 2 * WN);
    cvt_hilo<<<wblk, 256>>>(Wo, whi + 3 * WN, wlo + 3 * WN);

    const int AN = MROWS * D_SZ;
    const int ablk = (AN / 4) / 256;
    dim3 gg(D_SZ / 128, MROWS / 128);    // (8, 64)

    cvt_hilo<<<ablk, 256>>>(q, ahi, alo);
    gemm_mma<<<gg, 256, GEMM_SMEM_BYTES>>>(ahi, alo, whi + 0 * WN, wlo + 0 * WN, bq, qp);
    cvt_hilo<<<ablk, 256>>>(k, ahi, alo);
    gemm_mma<<<gg, 256, GEMM_SMEM_BYTES>>>(ahi, alo, whi + 1 * WN, wlo + 1 * WN, bk, kp);
    cvt_hilo<<<ablk, 256>>>(v, ahi, alo);
    gemm_mma<<<gg, 256, GEMM_SMEM_BYTES>>>(ahi, alo, whi + 2 * WN, wlo + 2 * WN, bv, vp);

    const int rope_threads = MROWS * (D_SZ / 2);
    rope_kernel<<<rope_threads / 256, 256>>>(qp, cosp, sinp);
    rope_kernel<<<rope_threads / 256, 256>>>(kp, cosp, sinp);

    attn_kernel<<<dim3(S_SZ / 128, B_SZ * H_SZ), 128>>>(qp, kp, vp, maskp, apb, att);

    cvt_hilo<<<ablk, 256>>>(att, ahi, alo);
    gemm_mma<<<gg, 256, GEMM_SMEM_BYTES>>>(ahi, alo, whi + 3 * WN, wlo + 3 * WN, bo,
                                           (float*)d_out);
}

// round 4
// speedup vs baseline: 2.8074x; 1.9822x over previous
#include <cuda_runtime.h>
#include <cuda_bf16.h>
#include <math_constants.h>
#include <cstdint>
#include <cstddef>

#define B_SZ 8
#define S_SZ 1024
#define D_SZ 1024
#define H_SZ 16
#define DK_SZ 64
#define MROWS (B_SZ * S_SZ)   /* 8192 */

// ---------------------------------------------------------------------------
// Scratch (allocation-free rule: __device__ globals)
// ---------------------------------------------------------------------------
__device__ float g_qp[MROWS * D_SZ];
__device__ float g_kp[MROWS * D_SZ];
__device__ float g_vp[MROWS * D_SZ];
__device__ float g_att[MROWS * D_SZ];
__device__ __nv_bfloat16 g_ahi[MROWS * D_SZ];
__device__ __nv_bfloat16 g_alo[MROWS * D_SZ];
__device__ __nv_bfloat16 g_whi[4][D_SZ * D_SZ];
__device__ __nv_bfloat16 g_wlo[4][D_SZ * D_SZ];

// ---------------------------------------------------------------------------
__device__ __forceinline__ uint32_t smem_u32(const void* p) {
    uint32_t a;
    asm("{ .reg .u64 t; cvta.to.shared.u64 t, %1; cvt.u32.u64 %0, t; }"
        : "=r"(a) : "l"(p));
    return a;
}

__device__ __forceinline__ void cp_async16(uint32_t dst, const void* src) {
    asm volatile("cp.async.cg.shared.global [%0], [%1], 16;\n"
                 :: "r"(dst), "l"(src) : "memory");
}
#define CP_COMMIT() asm volatile("cp.async.commit_group;\n" ::: "memory")
#define CP_WAIT(n)  asm volatile("cp.async.wait_group %0;\n" :: "n"(n) : "memory")

__device__ __forceinline__ void mma16816(
    float& d0, float& d1, float& d2, float& d3,
    uint32_t a0, uint32_t a1, uint32_t a2, uint32_t a3,
    uint32_t b0, uint32_t b1)
{
    asm volatile(
        "mma.sync.aligned.m16n8k16.row.col.f32.bf16.bf16.f32 "
        "{%0,%1,%2,%3}, {%4,%5,%6,%7}, {%8,%9}, {%0,%1,%2,%3};\n"
        : "+f"(d0), "+f"(d1), "+f"(d2), "+f"(d3)
        : "r"(a0), "r"(a1), "r"(a2), "r"(a3), "r"(b0), "r"(b1));
}

// pack two f32 -> bf16x2 reg: low half = lo, high half = hi
__device__ __forceinline__ uint32_t pack_bf16(float lo, float hi) {
    uint32_t r;
    asm("cvt.rn.bf16x2.f32 %0, %1, %2;" : "=r"(r) : "f"(hi), "f"(lo));
    return r;
}
__device__ __forceinline__ float ex2f(float x) {
    float y; asm("ex2.approx.ftz.f32 %0, %1;" : "=f"(y) : "f"(x)); return y;
}
__device__ __forceinline__ float bf16lo_f(uint32_t p) { return __uint_as_float(p << 16); }
__device__ __forceinline__ float bf16hi_f(uint32_t p) { return __uint_as_float(p & 0xffff0000u); }

// ---------------------------------------------------------------------------
// fp32 -> (bf16 hi, bf16 lo) split. x ~= hi + lo (residual ~2^-18 |x|)
// ---------------------------------------------------------------------------
__global__ __launch_bounds__(256) void cvt_hilo(
    const float* __restrict__ x, __nv_bfloat16* __restrict__ hi,
    __nv_bfloat16* __restrict__ lo)
{
    int i = blockIdx.x * blockDim.x + threadIdx.x;
    float4 v = ((const float4*)x)[i];
    __nv_bfloat16 h0 = __float2bfloat16_rn(v.x);
    __nv_bfloat16 h1 = __float2bfloat16_rn(v.y);
    __nv_bfloat16 h2 = __float2bfloat16_rn(v.z);
    __nv_bfloat16 h3 = __float2bfloat16_rn(v.w);
    __nv_bfloat16 l0 = __float2bfloat16_rn(v.x - __bfloat162float(h0));
    __nv_bfloat16 l1 = __float2bfloat16_rn(v.y - __bfloat162float(h1));
    __nv_bfloat16 l2 = __float2bfloat16_rn(v.z - __bfloat162float(h2));
    __nv_bfloat16 l3 = __float2bfloat16_rn(v.w - __bfloat162float(h3));
    __nv_bfloat162* hp = (__nv_bfloat162*)hi;
    __nv_bfloat162* lp = (__nv_bfloat162*)lo;
    hp[2 * i]     = __nv_bfloat162(h0, h1);
    hp[2 * i + 1] = __nv_bfloat162(h2, h3);
    lp[2 * i]     = __nv_bfloat162(l0, l1);
    lp[2 * i + 1] = __nv_bfloat162(l2, l3);
}

// ---------------------------------------------------------------------------
// Tensor-core GEMM (unchanged from round 3)
// ---------------------------------------------------------------------------
#define GBK 32
#define GPAD 40
#define TILE_ELEMS (128 * GPAD)
#define BUF_ELEMS (4 * TILE_ELEMS)
#define GEMM_SMEM_BYTES (2 * BUF_ELEMS * 2)

__global__ __launch_bounds__(256) void gemm_mma(
    const __nv_bfloat16* __restrict__ Ahi, const __nv_bfloat16* __restrict__ Alo,
    const __nv_bfloat16* __restrict__ Whi, const __nv_bfloat16* __restrict__ Wlo,
    const float* __restrict__ bias, float* __restrict__ C)
{
    extern __shared__ __nv_bfloat16 sm[];
    const uint32_t sb = smem_u32(sm);

    const int tid = threadIdx.x;
    const int wid = tid >> 5;
    const int lane = tid & 31;
    const int group = lane >> 2;
    const int tig = lane & 3;
    const int wm = wid & 3;
    const int wn = wid >> 2;
    const int bm = blockIdx.y * 128;
    const int bn = blockIdx.x * 128;

    const __nv_bfloat16* gsrc[4] = {
        Ahi + (size_t)bm * D_SZ, Alo + (size_t)bm * D_SZ,
        Whi + (size_t)bn * D_SZ, Wlo + (size_t)bn * D_SZ };

    float acc[2][8][4];
#pragma unroll
    for (int i = 0; i < 2; i++)
#pragma unroll
        for (int j = 0; j < 8; j++)
#pragma unroll
            for (int r = 0; r < 4; r++) acc[i][j][r] = 0.f;

    auto load_chunk = [&](int c, int buf) {
        const int k0 = c * GBK;
        const uint32_t bbase = sb + (uint32_t)buf * (BUF_ELEMS * 2);
#pragma unroll
        for (int it = 0; it < 8; it++) {
            int t = tid + it * 256;
            int tile = t >> 9;
            int r = (t >> 2) & 127;
            int c4 = t & 3;
            const __nv_bfloat16* src = gsrc[tile] + (size_t)r * D_SZ + k0 + c4 * 8;
            uint32_t dst = bbase + (uint32_t)(tile * TILE_ELEMS + r * GPAD + c4 * 8) * 2u;
            cp_async16(dst, src);
        }
    };

    load_chunk(0, 0);
    CP_COMMIT();

    for (int c = 0; c < D_SZ / GBK; ++c) {
        if (c + 1 < D_SZ / GBK) {
            load_chunk(c + 1, (c + 1) & 1);
            CP_COMMIT();
            CP_WAIT(1);
        } else {
            CP_WAIT(0);
        }
        __syncthreads();

        const uint32_t bbase = sb + (uint32_t)(c & 1) * (BUF_ELEMS * 2);
#pragma unroll
        for (int pass = 0; pass < 3; ++pass) {
            const int at = (pass == 2) ? 1 : 0;
            const int wt = (pass == 1) ? 3 : 2;
            const uint32_t aB = bbase + (uint32_t)(at * TILE_ELEMS) * 2u;
            const uint32_t wB = bbase + (uint32_t)(wt * TILE_ELEMS) * 2u;
#pragma unroll
            for (int ks = 0; ks < 2; ++ks) {
                const int kk = ks * 16 + tig * 2;
                uint32_t a[2][4];
#pragma unroll
                for (int mt = 0; mt < 2; ++mt) {
                    const int r0 = wm * 32 + mt * 16 + group;
                    uint32_t p00 = aB + (uint32_t)(r0 * GPAD + kk) * 2u;
                    uint32_t p10 = aB + (uint32_t)((r0 + 8) * GPAD + kk) * 2u;
                    asm volatile("ld.shared.b32 %0, [%1];" : "=r"(a[mt][0]) : "r"(p00));
                    asm volatile("ld.shared.b32 %0, [%1];" : "=r"(a[mt][1]) : "r"(p10));
                    asm volatile("ld.shared.b32 %0, [%1];" : "=r"(a[mt][2]) : "r"(p00 + 16));
                    asm volatile("ld.shared.b32 %0, [%1];" : "=r"(a[mt][3]) : "r"(p10 + 16));
                }
#pragma unroll
                for (int nt = 0; nt < 8; ++nt) {
                    const int nr = wn * 64 + nt * 8 + group;
                    uint32_t pb = wB + (uint32_t)(nr * GPAD + kk) * 2u;
                    uint32_t b0, b1;
                    asm volatile("ld.shared.b32 %0, [%1];" : "=r"(b0) : "r"(pb));
                    asm volatile("ld.shared.b32 %0, [%1];" : "=r"(b1) : "r"(pb + 16));
                    mma16816(acc[0][nt][0], acc[0][nt][1], acc[0][nt][2], acc[0][nt][3],
                             a[0][0], a[0][1], a[0][2], a[0][3], b0, b1);
                    mma16816(acc[1][nt][0], acc[1][nt][1], acc[1][nt][2], acc[1][nt][3],
                             a[1][0], a[1][1], a[1][2], a[1][3], b0, b1);
                }
            }
        }
        __syncthreads();
    }

#pragma unroll
    for (int mt = 0; mt < 2; ++mt) {
        const int m0 = bm + wm * 32 + mt * 16 + group;
#pragma unroll
        for (int nt = 0; nt < 8; ++nt) {
            const int col = bn + wn * 64 + nt * 8 + tig * 2;
            const float bx = bias[col], by = bias[col + 1];
            float2 r0 = make_float2(acc[mt][nt][0] + bx, acc[mt][nt][1] + by);
            float2 r1 = make_float2(acc[mt][nt][2] + bx, acc[mt][nt][3] + by);
            *(float2*)(C + (size_t)m0 * D_SZ + col) = r0;
            *(float2*)(C + (size_t)(m0 + 8) * D_SZ + col) = r1;
        }
    }
}

// ---------------------------------------------------------------------------
// RoPE (rotate_half over full D), in-place.
// ---------------------------------------------------------------------------
__global__ __launch_bounds__(256) void rope_kernel(
    float* __restrict__ x, const float* __restrict__ ct,
    const float* __restrict__ st)
{
    int idx = blockIdx.x * blockDim.x + threadIdx.x;
    int dh = idx & 511;
    int bs = idx >> 9;
    int s  = bs & 1023;
    float* row = x + (size_t)bs * D_SZ;
    float c1 = ct[s * D_SZ + dh],       s1 = st[s * D_SZ + dh];
    float c2 = ct[s * D_SZ + dh + 512], s2 = st[s * D_SZ + dh + 512];
    float x1 = row[dh], x2 = row[dh + 512];
    row[dh]       = x1 * c1 - x2 * s1;
    row[dh + 512] = x2 * c2 + x1 * s2;
}

// ---------------------------------------------------------------------------
// Flash attention on mma.sync, bf16 hi/lo 3-pass for QK^T and PV.
// One block = one (b,h) x 64 query rows. 4 warps, 16 rows each.
// Key tiles of 64. Online softmax in base-2 domain.
// ---------------------------------------------------------------------------
#define APAD 72

__global__ __launch_bounds__(128, 3) void attn_mma(
    const float* __restrict__ qp, const float* __restrict__ kp,
    const float* __restrict__ vp, const float* __restrict__ mask,
    const float* __restrict__ prior_bias, float* __restrict__ out)
{
    __shared__ __nv_bfloat16 sKhi[64][APAD];   // phase0: Qhi
    __shared__ __nv_bfloat16 sKlo[64][APAD];   // phase0: Qlo
    __shared__ __nv_bfloat16 sVhi[64][APAD];   // Vt [d][key]
    __shared__ __nv_bfloat16 sVlo[64][APAD];
    __shared__ float sMask[64];

    const int tid = threadIdx.x;
    const int wid = tid >> 5, lane = tid & 31;
    const int group = lane >> 2, tig = lane & 3;
    const int bh = blockIdx.y, b = bh >> 4, h = bh & 15;
    const int q0 = blockIdx.x * 64;

    const float LOG2E = 1.4426950408889634f;
    float sig = 1.0f / (1.0f + __expf(-prior_bias[h]));
    sig *= LOG2E;
    const float scale = 0.125f * LOG2E;

    // ---- stage Q tile into sKhi/sKlo, extract A-fragments, then free smem
    {
        const int row = tid >> 1, c0 = (tid & 1) * 32;
        const float* src = qp + ((size_t)(b * S_SZ + q0 + row)) * D_SZ + h * DK_SZ + c0;
#pragma unroll
        for (int j = 0; j < 8; ++j) {
            float4 v = ((const float4*)src)[j];
            int c = c0 + 4 * j;
            uint32_t h01 = pack_bf16(__bfloat162float(__float2bfloat16_rn(v.x)),
                                     __bfloat162float(__float2bfloat16_rn(v.y)));
            // direct pack (cvt.rn does the rounding once):
            h01 = pack_bf16(v.x, v.y);
            uint32_t h23 = pack_bf16(v.z, v.w);
            uint32_t l01 = pack_bf16(v.x - bf16lo_f(h01), v.y - bf16hi_f(h01));
            uint32_t l23 = pack_bf16(v.z - bf16lo_f(h23), v.w - bf16hi_f(h23));
            *(uint32_t*)&sKhi[row][c]     = h01;
            *(uint32_t*)&sKhi[row][c + 2] = h23;
            *(uint32_t*)&sKlo[row][c]     = l01;
            *(uint32_t*)&sKlo[row][c + 2] = l23;
        }
    }
    __syncthreads();

    uint32_t qh[4][4], ql[4][4];
    const int r0 = wid * 16 + group;
#pragma unroll
    for (int ks = 0; ks < 4; ++ks) {
        const int d0 = ks * 16 + tig * 2;
        qh[ks][0] = *(const uint32_t*)&sKhi[r0][d0];
        qh[ks][1] = *(const uint32_t*)&sKhi[r0 + 8][d0];
        qh[ks][2] = *(const uint32_t*)&sKhi[r0][d0 + 8];
        qh[ks][3] = *(const uint32_t*)&sKhi[r0 + 8][d0 + 8];
        ql[ks][0] = *(const uint32_t*)&sKlo[r0][d0];
        ql[ks][1] = *(const uint32_t*)&sKlo[r0 + 8][d0];
        ql[ks][2] = *(const uint32_t*)&sKlo[r0][d0 + 8];
        ql[ks][3] = *(const uint32_t*)&sKlo[r0 + 8][d0 + 8];
    }
    __syncthreads();

    float o[8][4];
#pragma unroll
    for (int i = 0; i < 8; i++)
#pragma unroll
        for (int j = 0; j < 4; j++) o[i][j] = 0.f;
    float m0 = -1e30f, m1 = -1e30f, l0 = 0.f, l1 = 0.f;
    const float qr0f = (float)(q0 + r0);
    const float qr1f = qr0f + 8.f;

    for (int kt = 0; kt < S_SZ / 64; ++kt) {
        const int k0 = kt * 64;
        // ---- K tile [key][d] hi/lo
        {
            const int key = tid >> 1, c0 = (tid & 1) * 32;
            const float* src = kp + ((size_t)(b * S_SZ + k0 + key)) * D_SZ + h * DK_SZ + c0;
#pragma unroll
            for (int j = 0; j < 8; ++j) {
                float4 v = ((const float4*)src)[j];
                int c = c0 + 4 * j;
                uint32_t h01 = pack_bf16(v.x, v.y);
                uint32_t h23 = pack_bf16(v.z, v.w);
                uint32_t l01 = pack_bf16(v.x - bf16lo_f(h01), v.y - bf16hi_f(h01));
                uint32_t l23 = pack_bf16(v.z - bf16lo_f(h23), v.w - bf16hi_f(h23));
                *(uint32_t*)&sKhi[key][c]     = h01;
                *(uint32_t*)&sKhi[key][c + 2] = h23;
                *(uint32_t*)&sKlo[key][c]     = l01;
                *(uint32_t*)&sKlo[key][c + 2] = l23;
            }
        }
        // ---- V tile transposed: Vt[d][key] (pack key pairs -> conflict-free)
        {
            const int kpr = (tid & 31) * 2;           // key pair base
            const int dblk = (tid >> 5) * 16;         // 16 d values
            const float* s0 = vp + ((size_t)(b * S_SZ + k0 + kpr)) * D_SZ + h * DK_SZ + dblk;
            const float* s1 = s0 + D_SZ;
            float v0[16], v1[16];
#pragma unroll
            for (int j = 0; j < 4; ++j) {
                *(float4*)&v0[j * 4] = ((const float4*)s0)[j];
                *(float4*)&v1[j * 4] = ((const float4*)s1)[j];
            }
#pragma unroll
            for (int j = 0; j < 16; ++j) {
                const int d = dblk + j;
                uint32_t hp = pack_bf16(v0[j], v1[j]);
                uint32_t lp = pack_bf16(v0[j] - bf16lo_f(hp), v1[j] - bf16hi_f(hp));
                *(uint32_t*)&sVhi[d][kpr] = hp;
                *(uint32_t*)&sVlo[d][kpr] = lp;
            }
        }
        if (tid < 64) sMask[tid] = mask[b * S_SZ + k0 + tid] * LOG2E;
        __syncthreads();

        // ---- S = Q K^T (3 passes hi/lo)
        float s[8][4];
#pragma unroll
        for (int i = 0; i < 8; i++)
#pragma unroll
            for (int j = 0; j < 4; j++) s[i][j] = 0.f;
#pragma unroll
        for (int ks = 0; ks < 4; ++ks) {
            const int d0 = ks * 16 + tig * 2;
#pragma unroll
            for (int nt = 0; nt < 8; ++nt) {
                const int kn = nt * 8 + group;
                uint32_t bh0 = *(const uint32_t*)&sKhi[kn][d0];
                uint32_t bh1 = *(const uint32_t*)&sKhi[kn][d0 + 8];
                uint32_t bl0 = *(const uint32_t*)&sKlo[kn][d0];
                uint32_t bl1 = *(const uint32_t*)&sKlo[kn][d0 + 8];
                mma16816(s[nt][0], s[nt][1], s[nt][2], s[nt][3],
                         qh[ks][0], qh[ks][1], qh[ks][2], qh[ks][3], bh0, bh1);
                mma16816(s[nt][0], s[nt][1], s[nt][2], s[nt][3],
                         qh[ks][0], qh[ks][1], qh[ks][2], qh[ks][3], bl0, bl1);
                mma16816(s[nt][0], s[nt][1], s[nt][2], s[nt][3],
                         ql[ks][0], ql[ks][1], ql[ks][2], ql[ks][3], bh0, bh1);
            }
        }

        // ---- bias + online softmax (base-2 domain)
        float mx0 = -1e30f, mx1 = -1e30f;
#pragma unroll
        for (int nt = 0; nt < 8; ++nt) {
            const int kl = nt * 8 + tig * 2;
            const float kf0 = (float)(k0 + kl), kf1 = kf0 + 1.f;
            const float mk0 = sMask[kl], mk1 = sMask[kl + 1];
            s[nt][0] = s[nt][0] * scale + mk0 - sig * fabsf(qr0f - kf0);
            s[nt][1] = s[nt][1] * scale + mk1 - sig * fabsf(qr0f - kf1);
            s[nt][2] = s[nt][2] * scale + mk0 - sig * fabsf(qr1f - kf0);
            s[nt][3] = s[nt][3] * scale + mk1 - sig * fabsf(qr1f - kf1);
            mx0 = fmaxf(mx0, fmaxf(s[nt][0], s[nt][1]));
            mx1 = fmaxf(mx1, fmaxf(s[nt][2], s[nt][3]));
        }
        mx0 = fmaxf(mx0, __shfl_xor_sync(0xffffffffu, mx0, 1));
        mx0 = fmaxf(mx0, __shfl_xor_sync(0xffffffffu, mx0, 2));
        mx1 = fmaxf(mx1, __shfl_xor_sync(0xffffffffu, mx1, 1));
        mx1 = fmaxf(mx1, __shfl_xor_sync(0xffffffffu, mx1, 2));
        const float nm0 = fmaxf(m0, mx0), nm1 = fmaxf(m1, mx1);
        const float a0 = ex2f(m0 - nm0), a1 = ex2f(m1 - nm1);
        m0 = nm0; m1 = nm1;

        float sum0 = 0.f, sum1 = 0.f;
#pragma unroll
        for (int nt = 0; nt < 8; ++nt) {
            s[nt][0] = ex2f(s[nt][0] - m0);
            s[nt][1] = ex2f(s[nt][1] - m0);
            s[nt][2] = ex2f(s[nt][2] - m1);
            s[nt][3] = ex2f(s[nt][3] - m1);
            sum0 += s[nt][0] + s[nt][1];
            sum1 += s[nt][2] + s[nt][3];
        }
        sum0 += __shfl_xor_sync(0xffffffffu, sum0, 1);
        sum0 += __shfl_xor_sync(0xffffffffu, sum0, 2);
        sum1 += __shfl_xor_sync(0xffffffffu, sum1, 1);
        sum1 += __shfl_xor_sync(0xffffffffu, sum1, 2);
        l0 = l0 * a0 + sum0;
        l1 = l1 * a1 + sum1;
#pragma unroll
        for (int nt = 0; nt < 8; ++nt) {
            o[nt][0] *= a0; o[nt][1] *= a0;
            o[nt][2] *= a1; o[nt][3] *= a1;
        }

        // ---- pack P hi fragments straight from accumulators
        uint32_t pa[4][4];
#pragma unroll
        for (int ks = 0; ks < 4; ++ks) {
            pa[ks][0] = pack_bf16(s[2 * ks][0], s[2 * ks][1]);
            pa[ks][1] = pack_bf16(s[2 * ks][2], s[2 * ks][3]);
            pa[ks][2] = pack_bf16(s[2 * ks + 1][0], s[2 * ks + 1][1]);
            pa[ks][3] = pack_bf16(s[2 * ks + 1][2], s[2 * ks + 1][3]);
        }
        // Phi*Vhi + Phi*Vlo
#pragma unroll
        for (int ks = 0; ks < 4; ++ks) {
            const int kk = ks * 16 + tig * 2;
#pragma unroll
            for (int nt = 0; nt < 8; ++nt) {
                const int dn = nt * 8 + group;
                uint32_t bh0 = *(const uint32_t*)&sVhi[dn][kk];
                uint32_t bh1 = *(const uint32_t*)&sVhi[dn][kk + 8];
                uint32_t bl0 = *(const uint32_t*)&sVlo[dn][kk];
                uint32_t bl1 = *(const uint32_t*)&sVlo[dn][kk + 8];
                mma16816(o[nt][0], o[nt][1], o[nt][2], o[nt][3],
                         pa[ks][0], pa[ks][1], pa[ks][2], pa[ks][3], bh0, bh1);
                mma16816(o[nt][0], o[nt][1], o[nt][2], o[nt][3],
                         pa[ks][0], pa[ks][1], pa[ks][2], pa[ks][3], bl0, bl1);
            }
        }
        // Plo*Vhi (overwrite pa with residual fragments)
#pragma unroll
        for (int ks = 0; ks < 4; ++ks) {
            pa[ks][0] = pack_bf16(s[2 * ks][0] - bf16lo_f(pa[ks][0]),
                                  s[2 * ks][1] - bf16hi_f(pa[ks][0]));
            pa[ks][1] = pack_bf16(s[2 * ks][2] - bf16lo_f(pa[ks][1]),
                                  s[2 * ks][3] - bf16hi_f(pa[ks][1]));
            pa[ks][2] = pack_bf16(s[2 * ks + 1][0] - bf16lo_f(pa[ks][2]),
                                  s[2 * ks + 1][1] - bf16hi_f(pa[ks][2]));
            pa[ks][3] = pack_bf16(s[2 * ks + 1][2] - bf16lo_f(pa[ks][3]),
                                  s[2 * ks + 1][3] - bf16hi_f(pa[ks][3]));
        }
#pragma unroll
        for (int ks = 0; ks < 4; ++ks) {
            const int kk = ks * 16 + tig * 2;
#pragma unroll
            for (int nt = 0; nt < 8; ++nt) {
                const int dn = nt * 8 + group;
                uint32_t bh0 = *(const uint32_t*)&sVhi[dn][kk];
                uint32_t bh1 = *(const uint32_t*)&sVhi[dn][kk + 8];
                mma16816(o[nt][0], o[nt][1], o[nt][2], o[nt][3],
                         pa[ks][0], pa[ks][1], pa[ks][2], pa[ks][3], bh0, bh1);
            }
        }
        __syncthreads();
    }

    // ---- epilogue: normalize + store (concat layout)
    const float inv0 = 1.0f / l0, inv1 = 1.0f / l1;
    const int gr0 = b * S_SZ + q0 + r0;
#pragma unroll
    for (int nt = 0; nt < 8; ++nt) {
        const int col = h * DK_SZ + nt * 8 + tig * 2;
        *(float2*)(out + (size_t)gr0 * D_SZ + col) =
            make_float2(o[nt][0] * inv0, o[nt][1] * inv0);
        *(float2*)(out + (size_t)(gr0 + 8) * D_SZ + col) =
            make_float2(o[nt][2] * inv1, o[nt][3] * inv1);
    }
}

// ---------------------------------------------------------------------------
extern "C" void kernel_launch(void* const* d_in, const int* in_sizes, int n_in,
                              void* d_out, int out_size)
{
    const float* q     = (const float*)d_in[0];
    const float* k     = (const float*)d_in[1];
    const float* v     = (const float*)d_in[2];
    const float* cosp  = (const float*)d_in[3];
    const float* sinp  = (const float*)d_in[4];
    const float* maskp = (const float*)d_in[5];
    // d_in[6] = short_matrix (analytic: -|i-j|)
    const float* Wq = (const float*)d_in[7];
    const float* bq = (const float*)d_in[8];
    const float* Wk = (const float*)d_in[9];
    const float* bk = (const float*)d_in[10];
    const float* Wv = (const float*)d_in[11];
    const float* bv = (const float*)d_in[12];
    const float* Wo = (const float*)d_in[13];
    const float* bo = (const float*)d_in[14];
    const float* apb = (const float*)d_in[15];

    float *qp, *kp, *vp, *att;
    __nv_bfloat16 *ahi, *alo, *whi, *wlo;
    cudaGetSymbolAddress((void**)&qp,  g_qp);
    cudaGetSymbolAddress((void**)&kp,  g_kp);
    cudaGetSymbolAddress((void**)&vp,  g_vp);
    cudaGetSymbolAddress((void**)&att, g_att);
    cudaGetSymbolAddress((void**)&ahi, g_ahi);
    cudaGetSymbolAddress((void**)&alo, g_alo);
    cudaGetSymbolAddress((void**)&whi, g_whi);
    cudaGetSymbolAddress((void**)&wlo, g_wlo);

    cudaFuncSetAttribute(gemm_mma, cudaFuncAttributeMaxDynamicSharedMemorySize,
                         GEMM_SMEM_BYTES);

    const int WN = D_SZ * D_SZ;
    const int wblk = (WN / 4) / 256;
    cvt_hilo<<<wblk, 256>>>(Wq, whi + 0 * WN, wlo + 0 * WN);
    cvt_hilo<<<wblk, 256>>>(Wk, whi + 1 * WN, wlo + 1 * WN);
    cvt_hilo<<<wblk, 256>>>(Wv, whi + 2 * WN, wlo + 2 * WN);
    cvt_hilo<<<wblk, 256>>>(Wo, whi + 3 * WN, wlo + 3 * WN);

    const int AN = MROWS * D_SZ;
    const int ablk = (AN / 4) / 256;
    dim3 gg(D_SZ / 128, MROWS / 128);

    cvt_hilo<<<ablk, 256>>>(q, ahi, alo);
    gemm_mma<<<gg, 256, GEMM_SMEM_BYTES>>>(ahi, alo, whi + 0 * WN, wlo + 0 * WN, bq, qp);
    cvt_hilo<<<ablk, 256>>>(k, ahi, alo);
    gemm_mma<<<gg, 256, GEMM_SMEM_BYTES>>>(ahi, alo, whi + 1 * WN, wlo + 1 * WN, bk, kp);
    cvt_hilo<<<ablk, 256>>>(v, ahi, alo);
    gemm_mma<<<gg, 256, GEMM_SMEM_BYTES>>>(ahi, alo, whi + 2 * WN, wlo + 2 * WN, bv, vp);

    const int rope_threads = MROWS * (D_SZ / 2);
    rope_kernel<<<rope_threads / 256, 256>>>(qp, cosp, sinp);
    rope_kernel<<<rope_threads / 256, 256>>>(kp, cosp, sinp);

    attn_mma<<<dim3(S_SZ / 64, B_SZ * H_SZ), 128>>>(qp, kp, vp, maskp, apb, att);

    cvt_hilo<<<ablk, 256>>>(att, ahi, alo);
    gemm_mma<<<gg, 256, GEMM_SMEM_BYTES>>>(ahi, alo, whi + 3 * WN, wlo + 3 * WN, bo,
                                           (float*)d_out);
}

// round 5
// speedup vs baseline: 3.5712x; 1.2721x over previous
#include <cuda_runtime.h>
#include <cuda_bf16.h>
#include <math_constants.h>
#include <cstdint>
#include <cstddef>

#define B_SZ 8
#define S_SZ 1024
#define D_SZ 1024
#define H_SZ 16
#define DK_SZ 64
#define MROWS (B_SZ * S_SZ)   /* 8192 */

// ---------------------------------------------------------------------------
// Scratch (allocation-free rule: __device__ globals)
// ---------------------------------------------------------------------------
__device__ float g_qp[MROWS * D_SZ];
__device__ float g_kp[MROWS * D_SZ];
__device__ float g_vp[MROWS * D_SZ];
__device__ float g_att[MROWS * D_SZ];
__device__ __nv_bfloat16 g_whi[4][D_SZ * D_SZ];
__device__ __nv_bfloat16 g_wlo[4][D_SZ * D_SZ];
__device__ __nv_bfloat16 g_qhi[MROWS * D_SZ];
__device__ __nv_bfloat16 g_qlo[MROWS * D_SZ];
__device__ __nv_bfloat16 g_khi[MROWS * D_SZ];
__device__ __nv_bfloat16 g_klo[MROWS * D_SZ];
__device__ __nv_bfloat16 g_vthi[MROWS * D_SZ];   // [b*h][d][s]
__device__ __nv_bfloat16 g_vtlo[MROWS * D_SZ];

// ---------------------------------------------------------------------------
__device__ __forceinline__ uint32_t smem_u32(const void* p) {
    uint32_t a;
    asm("{ .reg .u64 t; cvta.to.shared.u64 t, %1; cvt.u32.u64 %0, t; }"
        : "=r"(a) : "l"(p));
    return a;
}
__device__ __forceinline__ void cp_async16(uint32_t dst, const void* src) {
    asm volatile("cp.async.cg.shared.global [%0], [%1], 16;\n"
                 :: "r"(dst), "l"(src) : "memory");
}
#define CP_COMMIT() asm volatile("cp.async.commit_group;\n" ::: "memory")
#define CP_WAIT(n)  asm volatile("cp.async.wait_group %0;\n" :: "n"(n) : "memory")

__device__ __forceinline__ uint32_t lds32(uint32_t a) {
    uint32_t v;
    asm volatile("ld.shared.b32 %0, [%1];" : "=r"(v) : "r"(a));
    return v;
}
__device__ __forceinline__ void mma16816(
    float& d0, float& d1, float& d2, float& d3,
    uint32_t a0, uint32_t a1, uint32_t a2, uint32_t a3,
    uint32_t b0, uint32_t b1)
{
    asm volatile(
        "mma.sync.aligned.m16n8k16.row.col.f32.bf16.bf16.f32 "
        "{%0,%1,%2,%3}, {%4,%5,%6,%7}, {%8,%9}, {%0,%1,%2,%3};\n"
        : "+f"(d0), "+f"(d1), "+f"(d2), "+f"(d3)
        : "r"(a0), "r"(a1), "r"(a2), "r"(a3), "r"(b0), "r"(b1));
}
// pack two f32 -> bf16x2 reg: low half = first arg
__device__ __forceinline__ uint32_t pack_bf16(float lo, float hi) {
    uint32_t r;
    asm("cvt.rn.bf16x2.f32 %0, %1, %2;" : "=r"(r) : "f"(hi), "f"(lo));
    return r;
}
__device__ __forceinline__ float ex2f(float x) {
    float y; asm("ex2.approx.ftz.f32 %0, %1;" : "=f"(y) : "f"(x)); return y;
}
__device__ __forceinline__ float bf16lo_f(uint32_t p) { return __uint_as_float(p << 16); }
__device__ __forceinline__ float bf16hi_f(uint32_t p) { return __uint_as_float(p & 0xffff0000u); }

// ---------------------------------------------------------------------------
// fp32 -> (bf16 hi, bf16 lo) split (weights only; done once, tiny)
// ---------------------------------------------------------------------------
__global__ __launch_bounds__(256) void cvt_hilo(
    const float* __restrict__ x, __nv_bfloat16* __restrict__ hi,
    __nv_bfloat16* __restrict__ lo)
{
    int i = blockIdx.x * blockDim.x + threadIdx.x;
    float4 v = ((const float4*)x)[i];
    uint32_t h01 = pack_bf16(v.x, v.y);
    uint32_t h23 = pack_bf16(v.z, v.w);
    uint32_t l01 = pack_bf16(v.x - bf16lo_f(h01), v.y - bf16hi_f(h01));
    uint32_t l23 = pack_bf16(v.z - bf16lo_f(h23), v.w - bf16hi_f(h23));
    ((uint2*)hi)[i] = make_uint2(h01, h23);
    ((uint2*)lo)[i] = make_uint2(l01, l23);
}

// ---------------------------------------------------------------------------
// Tensor-core GEMM, fp32 A input with fused hi/lo conversion.
// C[m,n] = sum_k A[m,k]*W[n,k] + bias[n]; W pre-split hi/lo bf16.
// Block 128x128x32, 8 warps (4Mx2N), warp tile 32x64.
// ---------------------------------------------------------------------------
#define GPAD 40
#define GTILEB (128 * GPAD * 2)             /* 10240 bytes per tile */
#define GEMM_SMEM_BYTES (8 * GTILEB)        /* 81920 */

__global__ __launch_bounds__(256, 2) void gemm_mma(
    const float* __restrict__ A,
    const __nv_bfloat16* __restrict__ Whi, const __nv_bfloat16* __restrict__ Wlo,
    const float* __restrict__ bias, float* __restrict__ C)
{
    extern __shared__ char smc[];
    const uint32_t sb = smem_u32(smc);

    const int tid = threadIdx.x;
    const int wid = tid >> 5, lane = tid & 31;
    const int group = lane >> 2, tig = lane & 3;
    const int wm = wid & 3, wn = wid >> 2;
    const int bm = blockIdx.y * 128;
    const int bn = blockIdx.x * 128;

    // smem regions (byte offsets): Ahi[s], Alo[s], Whi[s], Wlo[s]
    // Ahi(s)=s*10240, Alo(s)=20480+s*10240, Whi(s)=40960+s*10240, Wlo(s)=61440+s*10240

    float acc[2][8][4];
#pragma unroll
    for (int i = 0; i < 2; i++)
#pragma unroll
        for (int j = 0; j < 8; j++)
#pragma unroll
            for (int r = 0; r < 4; r++) acc[i][j][r] = 0.f;

    const int arow = tid >> 3, ac4 = tid & 7;      // A loader base (it stride 32 rows)
    float4 areg[4];

    auto ldgA = [&](int c) {
        const int k0 = c * 32;
#pragma unroll
        for (int it = 0; it < 4; ++it)
            areg[it] = *(const float4*)(A + (size_t)(bm + arow + it * 32) * D_SZ + k0 + ac4 * 4);
    };
    auto stsA = [&](int s) {
        const uint32_t hB = sb + (uint32_t)s * GTILEB;
        const uint32_t lB = sb + 20480u + (uint32_t)s * GTILEB;
#pragma unroll
        for (int it = 0; it < 4; ++it) {
            float4 v = areg[it];
            uint32_t h01 = pack_bf16(v.x, v.y);
            uint32_t h23 = pack_bf16(v.z, v.w);
            uint32_t l01 = pack_bf16(v.x - bf16lo_f(h01), v.y - bf16hi_f(h01));
            uint32_t l23 = pack_bf16(v.z - bf16lo_f(h23), v.w - bf16hi_f(h23));
            uint32_t off = (uint32_t)(((arow + it * 32) * GPAD + ac4 * 4) * 2);
            asm volatile("st.shared.v2.b32 [%0], {%1, %2};" :: "r"(hB + off), "r"(h01), "r"(h23));
            asm volatile("st.shared.v2.b32 [%0], {%1, %2};" :: "r"(lB + off), "r"(l01), "r"(l23));
        }
    };
    auto cpW = [&](int c, int s) {
        const int k0 = c * 32;
#pragma unroll
        for (int it = 0; it < 4; ++it) {
            int idx = tid + it * 256;
            int tile = idx >> 9;                  // compile-time per it
            int r = (idx >> 2) & 127;
            int c4 = idx & 3;
            const __nv_bfloat16* src = (tile ? Wlo : Whi) + (size_t)(bn + r) * D_SZ + k0 + c4 * 8;
            uint32_t dst = sb + (tile ? 61440u : 40960u) + (uint32_t)s * GTILEB
                         + (uint32_t)((r * GPAD + c4 * 8) * 2);
            cp_async16(dst, src);
        }
    };

    ldgA(0);
    cpW(0, 0);
    CP_COMMIT();

    for (int c = 0; c < D_SZ / 32; ++c) {
        const int s = c & 1;
        if (c + 1 < D_SZ / 32) { cpW(c + 1, s ^ 1); CP_COMMIT(); CP_WAIT(1); }
        else CP_WAIT(0);
        stsA(s);
        __syncthreads();
        if (c + 1 < D_SZ / 32) ldgA(c + 1);

        const uint32_t aHB = sb + (uint32_t)s * GTILEB;
        const uint32_t aLB = sb + 20480u + (uint32_t)s * GTILEB;
        const uint32_t wHB = sb + 40960u + (uint32_t)s * GTILEB;
        const uint32_t wLB = sb + 61440u + (uint32_t)s * GTILEB;
#pragma unroll
        for (int ks = 0; ks < 2; ++ks) {
            const int kk = ks * 16 + tig * 2;
            uint32_t aH[2][4], aL[2][4];
#pragma unroll
            for (int mt = 0; mt < 2; ++mt) {
                const int r0 = wm * 32 + mt * 16 + group;
                const uint32_t p = (uint32_t)((r0 * GPAD + kk) * 2);
                const uint32_t p8 = (uint32_t)(((r0 + 8) * GPAD + kk) * 2);
                aH[mt][0] = lds32(aHB + p);  aH[mt][1] = lds32(aHB + p8);
                aH[mt][2] = lds32(aHB + p + 16); aH[mt][3] = lds32(aHB + p8 + 16);
                aL[mt][0] = lds32(aLB + p);  aL[mt][1] = lds32(aLB + p8);
                aL[mt][2] = lds32(aLB + p + 16); aL[mt][3] = lds32(aLB + p8 + 16);
            }
#pragma unroll
            for (int nt = 0; nt < 8; ++nt) {
                const int nr = wn * 64 + nt * 8 + group;
                const uint32_t qo = (uint32_t)((nr * GPAD + kk) * 2);
                uint32_t wh0 = lds32(wHB + qo), wh1 = lds32(wHB + qo + 16);
                uint32_t wl0 = lds32(wLB + qo), wl1 = lds32(wLB + qo + 16);
#pragma unroll
                for (int mt = 0; mt < 2; ++mt) {
                    mma16816(acc[mt][nt][0], acc[mt][nt][1], acc[mt][nt][2], acc[mt][nt][3],
                             aH[mt][0], aH[mt][1], aH[mt][2], aH[mt][3], wh0, wh1);
                    mma16816(acc[mt][nt][0], acc[mt][nt][1], acc[mt][nt][2], acc[mt][nt][3],
                             aH[mt][0], aH[mt][1], aH[mt][2], aH[mt][3], wl0, wl1);
                    mma16816(acc[mt][nt][0], acc[mt][nt][1], acc[mt][nt][2], acc[mt][nt][3],
                             aL[mt][0], aL[mt][1], aL[mt][2], aL[mt][3], wh0, wh1);
                }
            }
        }
        __syncthreads();
    }

#pragma unroll
    for (int mt = 0; mt < 2; ++mt) {
        const int m0 = bm + wm * 32 + mt * 16 + group;
#pragma unroll
        for (int nt = 0; nt < 8; ++nt) {
            const int col = bn + wn * 64 + nt * 8 + tig * 2;
            const float bx = bias[col], by = bias[col + 1];
            *(float2*)(C + (size_t)m0 * D_SZ + col) =
                make_float2(acc[mt][nt][0] + bx, acc[mt][nt][1] + by);
            *(float2*)(C + (size_t)(m0 + 8) * D_SZ + col) =
                make_float2(acc[mt][nt][2] + bx, acc[mt][nt][3] + by);
        }
    }
}

// ---------------------------------------------------------------------------
// RoPE + hi/lo split: reads fp32 qp/kp, writes bf16 hi/lo pairs.
// blockIdx.y: 0 = q, 1 = k. One thread owns float4 at (d4, d4+512).
// ---------------------------------------------------------------------------
__global__ __launch_bounds__(256) void rope_split(
    const float* __restrict__ qp, const float* __restrict__ kp,
    const float* __restrict__ ct, const float* __restrict__ st,
    __nv_bfloat16* __restrict__ qhi_, __nv_bfloat16* __restrict__ qlo_,
    __nv_bfloat16* __restrict__ khi_, __nv_bfloat16* __restrict__ klo_)
{
    const int gid = blockIdx.x * 256 + threadIdx.x;
    const int d4 = (gid & 127) * 4;
    const int bs = gid >> 7;
    const int s = bs & (S_SZ - 1);
    const float* src = (blockIdx.y ? kp : qp) + (size_t)bs * D_SZ;
    __nv_bfloat16* dhi = blockIdx.y ? khi_ : qhi_;
    __nv_bfloat16* dlo = blockIdx.y ? klo_ : qlo_;

    float4 x1 = *(const float4*)(src + d4);
    float4 x2 = *(const float4*)(src + d4 + 512);
    float4 c1 = *(const float4*)(ct + (size_t)s * D_SZ + d4);
    float4 s1 = *(const float4*)(st + (size_t)s * D_SZ + d4);
    float4 c2 = *(const float4*)(ct + (size_t)s * D_SZ + d4 + 512);
    float4 s2 = *(const float4*)(st + (size_t)s * D_SZ + d4 + 512);

    float r1[4] = { x1.x * c1.x - x2.x * s1.x, x1.y * c1.y - x2.y * s1.y,
                    x1.z * c1.z - x2.z * s1.z, x1.w * c1.w - x2.w * s1.w };
    float r2[4] = { x2.x * c2.x + x1.x * s2.x, x2.y * c2.y + x1.y * s2.y,
                    x2.z * c2.z + x1.z * s2.z, x2.w * c2.w + x1.w * s2.w };

    uint32_t h01 = pack_bf16(r1[0], r1[1]), h23 = pack_bf16(r1[2], r1[3]);
    uint32_t l01 = pack_bf16(r1[0] - bf16lo_f(h01), r1[1] - bf16hi_f(h01));
    uint32_t l23 = pack_bf16(r1[2] - bf16lo_f(h23), r1[3] - bf16hi_f(h23));
    *(uint2*)(dhi + (size_t)bs * D_SZ + d4) = make_uint2(h01, h23);
    *(uint2*)(dlo + (size_t)bs * D_SZ + d4) = make_uint2(l01, l23);

    h01 = pack_bf16(r2[0], r2[1]); h23 = pack_bf16(r2[2], r2[3]);
    l01 = pack_bf16(r2[0] - bf16lo_f(h01), r2[1] - bf16hi_f(h01));
    l23 = pack_bf16(r2[2] - bf16lo_f(h23), r2[3] - bf16hi_f(h23));
    *(uint2*)(dhi + (size_t)bs * D_SZ + d4 + 512) = make_uint2(h01, h23);
    *(uint2*)(dlo + (size_t)bs * D_SZ + d4 + 512) = make_uint2(l01, l23);
}

// ---------------------------------------------------------------------------
// V transpose + hi/lo split: vp[b][s][h*64+d] -> vt[(b*16+h)*64+d][s] bf16
// ---------------------------------------------------------------------------
__global__ __launch_bounds__(256) void vsplit(
    const float* __restrict__ vp,
    __nv_bfloat16* __restrict__ vthi, __nv_bfloat16* __restrict__ vtlo)
{
    __shared__ float sT[64][65];
    const int tid = threadIdx.x;
    const int bh = blockIdx.y;
    const int b = bh >> 4, h = bh & 15;
    const int s0 = blockIdx.x * 64;

#pragma unroll
    for (int it = 0; it < 4; ++it) {
        int idx = tid + it * 256;
        int row = idx >> 4, c4 = idx & 15;
        float4 v = *(const float4*)(vp + (size_t)(b * S_SZ + s0 + row) * D_SZ + h * DK_SZ + c4 * 4);
        sT[row][c4 * 4 + 0] = v.x; sT[row][c4 * 4 + 1] = v.y;
        sT[row][c4 * 4 + 2] = v.z; sT[row][c4 * 4 + 3] = v.w;
    }
    __syncthreads();

    const int d = tid >> 2, sg = (tid & 3) * 16;
    uint32_t hv[8], lv[8];
#pragma unroll
    for (int j = 0; j < 8; ++j) {
        float v0 = sT[sg + 2 * j][d], v1 = sT[sg + 2 * j + 1][d];
        hv[j] = pack_bf16(v0, v1);
        lv[j] = pack_bf16(v0 - bf16lo_f(hv[j]), v1 - bf16hi_f(hv[j]));
    }
    const size_t base = ((size_t)bh * 64 + d) * S_SZ + s0 + sg;
    *(uint4*)(vthi + base)     = make_uint4(hv[0], hv[1], hv[2], hv[3]);
    *(uint4*)(vthi + base + 8) = make_uint4(hv[4], hv[5], hv[6], hv[7]);
    *(uint4*)(vtlo + base)     = make_uint4(lv[0], lv[1], lv[2], lv[3]);
    *(uint4*)(vtlo + base + 8) = make_uint4(lv[4], lv[5], lv[6], lv[7]);
}

// ---------------------------------------------------------------------------
// Flash attention on mma.sync, hi/lo 3-pass, cp.async double-buffered K/V.
// One block = one (b,h) x 64 query rows. 4 warps, 16 rows each.
// ---------------------------------------------------------------------------
#define APAD 72
#define ATILEB (64 * APAD * 2)               /* 9216 */
#define ATTN_SMEM_BYTES (8 * ATILEB)         /* 73728: K hi/lo x2 + V hi/lo x2 */

__global__ __launch_bounds__(128, 3) void attn_mma(
    const __nv_bfloat16* __restrict__ qhi_, const __nv_bfloat16* __restrict__ qlo_,
    const __nv_bfloat16* __restrict__ khi_, const __nv_bfloat16* __restrict__ klo_,
    const __nv_bfloat16* __restrict__ vthi_, const __nv_bfloat16* __restrict__ vtlo_,
    const float* __restrict__ mask, const float* __restrict__ prior_bias,
    float* __restrict__ out)
{
    extern __shared__ char asm_[];
    const uint32_t sb = smem_u32(asm_);
    // regions: sK[s][t] at (s*2+t)*9216; sV[s][t] at 36864 + (s*2+t)*9216

    const int tid = threadIdx.x;
    const int wid = tid >> 5, lane = tid & 31;
    const int group = lane >> 2, tig = lane & 3;
    const int bh = blockIdx.y, b = bh >> 4, h = bh & 15;
    const int q0 = blockIdx.x * 64;

    const float LOG2E = 1.4426950408889634f;
    float sig = 1.0f / (1.0f + __expf(-prior_bias[h]));
    sig *= LOG2E;
    const float scale = 0.125f * LOG2E;

    // Q fragments straight from global hi/lo
    uint32_t qh[4][4], ql[4][4];
    const int r0 = wid * 16 + group;
    {
        const size_t rowa = (size_t)(b * S_SZ + q0 + r0) * D_SZ + h * DK_SZ;
        const size_t rowb = rowa + 8 * D_SZ;
#pragma unroll
        for (int ks = 0; ks < 4; ++ks) {
            const int d0 = ks * 16 + tig * 2;
            qh[ks][0] = *(const uint32_t*)(qhi_ + rowa + d0);
            qh[ks][1] = *(const uint32_t*)(qhi_ + rowb + d0);
            qh[ks][2] = *(const uint32_t*)(qhi_ + rowa + d0 + 8);
            qh[ks][3] = *(const uint32_t*)(qhi_ + rowb + d0 + 8);
            ql[ks][0] = *(const uint32_t*)(qlo_ + rowa + d0);
            ql[ks][1] = *(const uint32_t*)(qlo_ + rowb + d0);
            ql[ks][2] = *(const uint32_t*)(qlo_ + rowa + d0 + 8);
            ql[ks][3] = *(const uint32_t*)(qlo_ + rowb + d0 + 8);
        }
    }

    auto stage = [&](int kt, int s) {
        const int k0 = kt * 64;
#pragma unroll
        for (int it = 0; it < 16; ++it) {
            const int tile = it >> 2;                       // 0 khi,1 klo,2 vhi,3 vlo
            const int idx = (it & 3) * 128 + tid;
            const int r = idx >> 3, c8 = idx & 7;
            const __nv_bfloat16* src;
            uint32_t dst;
            if (tile == 0) {
                src = khi_ + (size_t)(b * S_SZ + k0 + r) * D_SZ + h * DK_SZ + c8 * 8;
                dst = sb + (uint32_t)((s * 2 + 0) * ATILEB);
            } else if (tile == 1) {
                src = klo_ + (size_t)(b * S_SZ + k0 + r) * D_SZ + h * DK_SZ + c8 * 8;
                dst = sb + (uint32_t)((s * 2 + 1) * ATILEB);
            } else if (tile == 2) {
                src = vthi_ + (size_t)(bh * 64 + r) * S_SZ + k0 + c8 * 8;
                dst = sb + 36864u + (uint32_t)((s * 2 + 0) * ATILEB);
            } else {
                src = vtlo_ + (size_t)(bh * 64 + r) * S_SZ + k0 + c8 * 8;
                dst = sb + 36864u + (uint32_t)((s * 2 + 1) * ATILEB);
            }
            cp_async16(dst + (uint32_t)((r * APAD + c8 * 8) * 2), src);
        }
    };

    float o[8][4];
#pragma unroll
    for (int i = 0; i < 8; i++)
#pragma unroll
        for (int j = 0; j < 4; j++) o[i][j] = 0.f;
    float m0 = -1e30f, m1 = -1e30f, l0 = 0.f, l1 = 0.f;
    const float qr0f = (float)(q0 + r0);
    const float qr1f = qr0f + 8.f;

    stage(0, 0);
    CP_COMMIT();

    for (int kt = 0; kt < S_SZ / 64; ++kt) {
        const int s = kt & 1;
        const int k0 = kt * 64;
        if (kt + 1 < S_SZ / 64) { stage(kt + 1, s ^ 1); CP_COMMIT(); CP_WAIT(1); }
        else CP_WAIT(0);
        __syncthreads();

        const uint32_t kHB = sb + (uint32_t)((s * 2 + 0) * ATILEB);
        const uint32_t kLB = sb + (uint32_t)((s * 2 + 1) * ATILEB);
        const uint32_t vHB = sb + 36864u + (uint32_t)((s * 2 + 0) * ATILEB);
        const uint32_t vLB = sb + 36864u + (uint32_t)((s * 2 + 1) * ATILEB);

        // ---- S = Q K^T (3 passes hi/lo)
        float sc[8][4];
#pragma unroll
        for (int i = 0; i < 8; i++)
#pragma unroll
            for (int j = 0; j < 4; j++) sc[i][j] = 0.f;
#pragma unroll
        for (int ks = 0; ks < 4; ++ks) {
            const int d0 = ks * 16 + tig * 2;
#pragma unroll
            for (int nt = 0; nt < 8; ++nt) {
                const int kn = nt * 8 + group;
                const uint32_t po = (uint32_t)((kn * APAD + d0) * 2);
                uint32_t bh0 = lds32(kHB + po), bh1 = lds32(kHB + po + 16);
                uint32_t bl0 = lds32(kLB + po), bl1 = lds32(kLB + po + 16);
                mma16816(sc[nt][0], sc[nt][1], sc[nt][2], sc[nt][3],
                         qh[ks][0], qh[ks][1], qh[ks][2], qh[ks][3], bh0, bh1);
                mma16816(sc[nt][0], sc[nt][1], sc[nt][2], sc[nt][3],
                         qh[ks][0], qh[ks][1], qh[ks][2], qh[ks][3], bl0, bl1);
                mma16816(sc[nt][0], sc[nt][1], sc[nt][2], sc[nt][3],
                         ql[ks][0], ql[ks][1], ql[ks][2], ql[ks][3], bh0, bh1);
            }
        }

        // ---- bias + online softmax (base-2 domain)
        float mx0 = -1e30f, mx1 = -1e30f;
#pragma unroll
        for (int nt = 0; nt < 8; ++nt) {
            const int kl = nt * 8 + tig * 2;
            const float kf0 = (float)(k0 + kl), kf1 = kf0 + 1.f;
            const float mk0 = __ldg(mask + b * S_SZ + k0 + kl) * LOG2E;
            const float mk1 = __ldg(mask + b * S_SZ + k0 + kl + 1) * LOG2E;
            sc[nt][0] = sc[nt][0] * scale + mk0 - sig * fabsf(qr0f - kf0);
            sc[nt][1] = sc[nt][1] * scale + mk1 - sig * fabsf(qr0f - kf1);
            sc[nt][2] = sc[nt][2] * scale + mk0 - sig * fabsf(qr1f - kf0);
            sc[nt][3] = sc[nt][3] * scale + mk1 - sig * fabsf(qr1f - kf1);
            mx0 = fmaxf(mx0, fmaxf(sc[nt][0], sc[nt][1]));
            mx1 = fmaxf(mx1, fmaxf(sc[nt][2], sc[nt][3]));
        }
        mx0 = fmaxf(mx0, __shfl_xor_sync(0xffffffffu, mx0, 1));
        mx0 = fmaxf(mx0, __shfl_xor_sync(0xffffffffu, mx0, 2));
        mx1 = fmaxf(mx1, __shfl_xor_sync(0xffffffffu, mx1, 1));
        mx1 = fmaxf(mx1, __shfl_xor_sync(0xffffffffu, mx1, 2));
        const float nm0 = fmaxf(m0, mx0), nm1 = fmaxf(m1, mx1);
        const float a0 = ex2f(m0 - nm0), a1 = ex2f(m1 - nm1);
        m0 = nm0; m1 = nm1;

        float sum0 = 0.f, sum1 = 0.f;
#pragma unroll
        for (int nt = 0; nt < 8; ++nt) {
            sc[nt][0] = ex2f(sc[nt][0] - m0);
            sc[nt][1] = ex2f(sc[nt][1] - m0);
            sc[nt][2] = ex2f(sc[nt][2] - m1);
            sc[nt][3] = ex2f(sc[nt][3] - m1);
            sum0 += sc[nt][0] + sc[nt][1];
            sum1 += sc[nt][2] + sc[nt][3];
        }
        sum0 += __shfl_xor_sync(0xffffffffu, sum0, 1);
        sum0 += __shfl_xor_sync(0xffffffffu, sum0, 2);
        sum1 += __shfl_xor_sync(0xffffffffu, sum1, 1);
        sum1 += __shfl_xor_sync(0xffffffffu, sum1, 2);
        l0 = l0 * a0 + sum0;
        l1 = l1 * a1 + sum1;
#pragma unroll
        for (int nt = 0; nt < 8; ++nt) {
            o[nt][0] *= a0; o[nt][1] *= a0;
            o[nt][2] *= a1; o[nt][3] *= a1;
        }

        // ---- P hi fragments straight from accumulators
        uint32_t pa[4][4];
#pragma unroll
        for (int ks = 0; ks < 4; ++ks) {
            pa[ks][0] = pack_bf16(sc[2 * ks][0], sc[2 * ks][1]);
            pa[ks][1] = pack_bf16(sc[2 * ks][2], sc[2 * ks][3]);
            pa[ks][2] = pack_bf16(sc[2 * ks + 1][0], sc[2 * ks + 1][1]);
            pa[ks][3] = pack_bf16(sc[2 * ks + 1][2], sc[2 * ks + 1][3]);
        }
#pragma unroll
        for (int ks = 0; ks < 4; ++ks) {
            const int kk = ks * 16 + tig * 2;
#pragma unroll
            for (int nt = 0; nt < 8; ++nt) {
                const int dn = nt * 8 + group;
                const uint32_t po = (uint32_t)((dn * APAD + kk) * 2);
                uint32_t bh0 = lds32(vHB + po), bh1 = lds32(vHB + po + 16);
                uint32_t bl0 = lds32(vLB + po), bl1 = lds32(vLB + po + 16);
                mma16816(o[nt][0], o[nt][1], o[nt][2], o[nt][3],
                         pa[ks][0], pa[ks][1], pa[ks][2], pa[ks][3], bh0, bh1);
                mma16816(o[nt][0], o[nt][1], o[nt][2], o[nt][3],
                         pa[ks][0], pa[ks][1], pa[ks][2], pa[ks][3], bl0, bl1);
            }
        }
        // P residual fragments
#pragma unroll
        for (int ks = 0; ks < 4; ++ks) {
            pa[ks][0] = pack_bf16(sc[2 * ks][0] - bf16lo_f(pa[ks][0]),
                                  sc[2 * ks][1] - bf16hi_f(pa[ks][0]));
            pa[ks][1] = pack_bf16(sc[2 * ks][2] - bf16lo_f(pa[ks][1]),
                                  sc[2 * ks][3] - bf16hi_f(pa[ks][1]));
            pa[ks][2] = pack_bf16(sc[2 * ks + 1][0] - bf16lo_f(pa[ks][2]),
                                  sc[2 * ks + 1][1] - bf16hi_f(pa[ks][2]));
            pa[ks][3] = pack_bf16(sc[2 * ks + 1][2] - bf16lo_f(pa[ks][3]),
                                  sc[2 * ks + 1][3] - bf16hi_f(pa[ks][3]));
        }
#pragma unroll
        for (int ks = 0; ks < 4; ++ks) {
            const int kk = ks * 16 + tig * 2;
#pragma unroll
            for (int nt = 0; nt < 8; ++nt) {
                const int dn = nt * 8 + group;
                const uint32_t po = (uint32_t)((dn * APAD + kk) * 2);
                uint32_t bh0 = lds32(vHB + po), bh1 = lds32(vHB + po + 16);
                mma16816(o[nt][0], o[nt][1], o[nt][2], o[nt][3],
                         pa[ks][0], pa[ks][1], pa[ks][2], pa[ks][3], bh0, bh1);
            }
        }
        __syncthreads();
    }

    const float inv0 = 1.0f / l0, inv1 = 1.0f / l1;
    const int gr0 = b * S_SZ + q0 + r0;
#pragma unroll
    for (int nt = 0; nt < 8; ++nt) {
        const int col = h * DK_SZ + nt * 8 + tig * 2;
        *(float2*)(out + (size_t)gr0 * D_SZ + col) =
            make_float2(o[nt][0] * inv0, o[nt][1] * inv0);
        *(float2*)(out + (size_t)(gr0 + 8) * D_SZ + col) =
            make_float2(o[nt][2] * inv1, o[nt][3] * inv1);
    }
}

// ---------------------------------------------------------------------------
extern "C" void kernel_launch(void* const* d_in, const int* in_sizes, int n_in,
                              void* d_out, int out_size)
{
    const float* q     = (const float*)d_in[0];
    const float* k     = (const float*)d_in[1];
    const float* v     = (const float*)d_in[2];
    const float* cosp  = (const float*)d_in[3];
    const float* sinp  = (const float*)d_in[4];
    const float* maskp = (const float*)d_in[5];
    // d_in[6] = short_matrix (analytic: -|i-j|)
    const float* Wq = (const float*)d_in[7];
    const float* bq = (const float*)d_in[8];
    const float* Wk = (const float*)d_in[9];
    const float* bk = (const float*)d_in[10];
    const float* Wv = (const float*)d_in[11];
    const float* bv = (const float*)d_in[12];
    const float* Wo = (const float*)d_in[13];
    const float* bo = (const float*)d_in[14];
    const float* apb = (const float*)d_in[15];

    float *qp, *kp, *vp, *att;
    __nv_bfloat16 *whi, *wlo, *qhi, *qlo, *khi, *klo, *vthi, *vtlo;
    cudaGetSymbolAddress((void**)&qp,   g_qp);
    cudaGetSymbolAddress((void**)&kp,   g_kp);
    cudaGetSymbolAddress((void**)&vp,   g_vp);
    cudaGetSymbolAddress((void**)&att,  g_att);
    cudaGetSymbolAddress((void**)&whi,  g_whi);
    cudaGetSymbolAddress((void**)&wlo,  g_wlo);
    cudaGetSymbolAddress((void**)&qhi,  g_qhi);
    cudaGetSymbolAddress((void**)&qlo,  g_qlo);
    cudaGetSymbolAddress((void**)&khi,  g_khi);
    cudaGetSymbolAddress((void**)&klo,  g_klo);
    cudaGetSymbolAddress((void**)&vthi, g_vthi);
    cudaGetSymbolAddress((void**)&vtlo, g_vtlo);

    cudaFuncSetAttribute(gemm_mma, cudaFuncAttributeMaxDynamicSharedMemorySize,
                         GEMM_SMEM_BYTES);
    cudaFuncSetAttribute(attn_mma, cudaFuncAttributeMaxDynamicSharedMemorySize,
                         ATTN_SMEM_BYTES);

    const int WN = D_SZ * D_SZ;
    cvt_hilo<<<WN / 1024, 256>>>(Wq, whi + 0 * WN, wlo + 0 * WN);
    cvt_hilo<<<WN / 1024, 256>>>(Wk, whi + 1 * WN, wlo + 1 * WN);
    cvt_hilo<<<WN / 1024, 256>>>(Wv, whi + 2 * WN, wlo + 2 * WN);
    cvt_hilo<<<WN / 1024, 256>>>(Wo, whi + 3 * WN, wlo + 3 * WN);

    dim3 gg(D_SZ / 128, MROWS / 128);
    gemm_mma<<<gg, 256, GEMM_SMEM_BYTES>>>(q, whi + 0 * WN, wlo + 0 * WN, bq, qp);
    gemm_mma<<<gg, 256, GEMM_SMEM_BYTES>>>(k, whi + 1 * WN, wlo + 1 * WN, bk, kp);
    gemm_mma<<<gg, 256, GEMM_SMEM_BYTES>>>(v, whi + 2 * WN, wlo + 2 * WN, bv, vp);

    rope_split<<<dim3(MROWS * 128 / 256, 2), 256>>>(qp, kp, cosp, sinp,
                                                    qhi, qlo, khi, klo);
    vsplit<<<dim3(S_SZ / 64, B_SZ * H_SZ), 256>>>(vp, vthi, vtlo);

    attn_mma<<<dim3(S_SZ / 64, B_SZ * H_SZ), 128, ATTN_SMEM_BYTES>>>(
        qhi, qlo, khi, klo, vthi, vtlo, maskp, apb, att);

    gemm_mma<<<gg, 256, GEMM_SMEM_BYTES>>>(att, whi + 3 * WN, wlo + 3 * WN, bo,
                                           (float*)d_out);
}

// round 6
// speedup vs baseline: 4.7733x; 1.3366x over previous
#include <cuda_runtime.h>
#include <cuda_fp16.h>
#include <math_constants.h>
#include <cstdint>
#include <cstddef>

#define B_SZ 8
#define S_SZ 1024
#define D_SZ 1024
#define H_SZ 16
#define DK_SZ 64
#define MROWS (B_SZ * S_SZ)   /* 8192 */

// ---------------------------------------------------------------------------
// Scratch (allocation-free rule: __device__ globals)
// ---------------------------------------------------------------------------
__device__ float g_qp[MROWS * D_SZ];
__device__ float g_kp[MROWS * D_SZ];
__device__ float g_vp[MROWS * D_SZ];
__device__ float g_att[MROWS * D_SZ];
__device__ __half g_whi[4][D_SZ * D_SZ];
__device__ __half g_wlo[4][D_SZ * D_SZ];
__device__ __half g_qhi[MROWS * D_SZ];
__device__ __half g_khi[MROWS * D_SZ];
__device__ __half g_klo[MROWS * D_SZ];
__device__ __half g_vthi[MROWS * D_SZ];   // [b*h][d][s]
__device__ __half g_vtlo[MROWS * D_SZ];

// ---------------------------------------------------------------------------
__device__ __forceinline__ uint32_t smem_u32(const void* p) {
    uint32_t a;
    asm("{ .reg .u64 t; cvta.to.shared.u64 t, %1; cvt.u32.u64 %0, t; }"
        : "=r"(a) : "l"(p));
    return a;
}
__device__ __forceinline__ void cp_async16(uint32_t dst, const void* src) {
    asm volatile("cp.async.cg.shared.global [%0], [%1], 16;\n"
                 :: "r"(dst), "l"(src) : "memory");
}
#define CP_COMMIT() asm volatile("cp.async.commit_group;\n" ::: "memory")
#define CP_WAIT(n)  asm volatile("cp.async.wait_group %0;\n" :: "n"(n) : "memory")

__device__ __forceinline__ uint32_t lds32(uint32_t a) {
    uint32_t v;
    asm volatile("ld.shared.b32 %0, [%1];" : "=r"(v) : "r"(a));
    return v;
}
__device__ __forceinline__ void mma16816(
    float& d0, float& d1, float& d2, float& d3,
    uint32_t a0, uint32_t a1, uint32_t a2, uint32_t a3,
    uint32_t b0, uint32_t b1)
{
    asm volatile(
        "mma.sync.aligned.m16n8k16.row.col.f32.f16.f16.f32 "
        "{%0,%1,%2,%3}, {%4,%5,%6,%7}, {%8,%9}, {%0,%1,%2,%3};\n"
        : "+f"(d0), "+f"(d1), "+f"(d2), "+f"(d3)
        : "r"(a0), "r"(a1), "r"(a2), "r"(a3), "r"(b0), "r"(b1));
}
// pack two f32 -> f16x2 reg: low half = first arg
__device__ __forceinline__ uint32_t pack_f16(float lo, float hi) {
    uint32_t r;
    asm("cvt.rn.f16x2.f32 %0, %1, %2;" : "=r"(r) : "f"(hi), "f"(lo));
    return r;
}
__device__ __forceinline__ float2 unpack_f16(uint32_t p) {
    __half2 h = *reinterpret_cast<__half2*>(&p);
    return __half22float2(h);
}
__device__ __forceinline__ float ex2f(float x) {
    float y; asm("ex2.approx.ftz.f32 %0, %1;" : "=f"(y) : "f"(x)); return y;
}

// ---------------------------------------------------------------------------
// fp32 -> (f16 hi, f16 lo) split (weights only; done once, tiny)
// ---------------------------------------------------------------------------
__global__ __launch_bounds__(256) void cvt_hilo(
    const float* __restrict__ x, __half* __restrict__ hi,
    __half* __restrict__ lo)
{
    int i = blockIdx.x * blockDim.x + threadIdx.x;
    float4 v = ((const float4*)x)[i];
    uint32_t h01 = pack_f16(v.x, v.y);
    uint32_t h23 = pack_f16(v.z, v.w);
    float2 f01 = unpack_f16(h01), f23 = unpack_f16(h23);
    uint32_t l01 = pack_f16(v.x - f01.x, v.y - f01.y);
    uint32_t l23 = pack_f16(v.z - f23.x, v.w - f23.y);
    ((uint2*)hi)[i] = make_uint2(h01, h23);
    ((uint2*)lo)[i] = make_uint2(l01, l23);
}

// ---------------------------------------------------------------------------
// Tensor-core GEMM, fp32 A input with fused f16 conversion (A single-rounded).
// C[m,n] = sum_k A[m,k]*W[n,k] + bias[n]; W pre-split hi/lo f16 (2 passes).
// Block 128x128x32, 8 warps (4Mx2N), warp tile 32x64.
// ---------------------------------------------------------------------------
#define GPAD 40
#define GTILEB (128 * GPAD * 2)             /* 10240 bytes per tile */
#define GEMM_SMEM_BYTES (6 * GTILEB)        /* 61440: A x2, Whi x2, Wlo x2 */

__global__ __launch_bounds__(256, 2) void gemm_mma(
    const float* __restrict__ A,
    const __half* __restrict__ Whi, const __half* __restrict__ Wlo,
    const float* __restrict__ bias, float* __restrict__ C)
{
    extern __shared__ char smc[];
    const uint32_t sb = smem_u32(smc);

    const int tid = threadIdx.x;
    const int wid = tid >> 5, lane = tid & 31;
    const int group = lane >> 2, tig = lane & 3;
    const int wm = wid & 3, wn = wid >> 2;
    const int bm = blockIdx.y * 128;
    const int bn = blockIdx.x * 128;

    float acc[2][8][4];
#pragma unroll
    for (int i = 0; i < 2; i++)
#pragma unroll
        for (int j = 0; j < 8; j++)
#pragma unroll
            for (int r = 0; r < 4; r++) acc[i][j][r] = 0.f;

    const int arow = tid >> 3, ac4 = tid & 7;
    float4 areg[4];

    auto ldgA = [&](int c) {
        const int k0 = c * 32;
#pragma unroll
        for (int it = 0; it < 4; ++it)
            areg[it] = *(const float4*)(A + (size_t)(bm + arow + it * 32) * D_SZ + k0 + ac4 * 4);
    };
    auto stsA = [&](int s) {
        const uint32_t aB = sb + (uint32_t)s * GTILEB;
#pragma unroll
        for (int it = 0; it < 4; ++it) {
            float4 v = areg[it];
            uint32_t h01 = pack_f16(v.x, v.y);
            uint32_t h23 = pack_f16(v.z, v.w);
            uint32_t off = (uint32_t)(((arow + it * 32) * GPAD + ac4 * 4) * 2);
            asm volatile("st.shared.v2.b32 [%0], {%1, %2};" :: "r"(aB + off), "r"(h01), "r"(h23));
        }
    };
    auto cpW = [&](int c, int s) {
        const int k0 = c * 32;
#pragma unroll
        for (int it = 0; it < 4; ++it) {
            int idx = tid + it * 256;
            int tile = idx >> 9;
            int r = (idx >> 2) & 127;
            int c4 = idx & 3;
            const __half* src = (tile ? Wlo : Whi) + (size_t)(bn + r) * D_SZ + k0 + c4 * 8;
            uint32_t dst = sb + (tile ? 40960u : 20480u) + (uint32_t)s * GTILEB
                         + (uint32_t)((r * GPAD + c4 * 8) * 2);
            cp_async16(dst, src);
        }
    };

    ldgA(0);
    cpW(0, 0);
    CP_COMMIT();

    for (int c = 0; c < D_SZ / 32; ++c) {
        const int s = c & 1;
        if (c + 1 < D_SZ / 32) { cpW(c + 1, s ^ 1); CP_COMMIT(); CP_WAIT(1); }
        else CP_WAIT(0);
        stsA(s);
        __syncthreads();
        if (c + 1 < D_SZ / 32) ldgA(c + 1);

        const uint32_t aB  = sb + (uint32_t)s * GTILEB;
        const uint32_t wHB = sb + 20480u + (uint32_t)s * GTILEB;
        const uint32_t wLB = sb + 40960u + (uint32_t)s * GTILEB;
#pragma unroll
        for (int ks = 0; ks < 2; ++ks) {
            const int kk = ks * 16 + tig * 2;
            uint32_t aF[2][4];
#pragma unroll
            for (int mt = 0; mt < 2; ++mt) {
                const int r0 = wm * 32 + mt * 16 + group;
                const uint32_t p = (uint32_t)((r0 * GPAD + kk) * 2);
                const uint32_t p8 = (uint32_t)(((r0 + 8) * GPAD + kk) * 2);
                aF[mt][0] = lds32(aB + p);  aF[mt][1] = lds32(aB + p8);
                aF[mt][2] = lds32(aB + p + 16); aF[mt][3] = lds32(aB + p8 + 16);
            }
#pragma unroll
            for (int nt = 0; nt < 8; ++nt) {
                const int nr = wn * 64 + nt * 8 + group;
                const uint32_t qo = (uint32_t)((nr * GPAD + kk) * 2);
                uint32_t wh0 = lds32(wHB + qo), wh1 = lds32(wHB + qo + 16);
                uint32_t wl0 = lds32(wLB + qo), wl1 = lds32(wLB + qo + 16);
#pragma unroll
                for (int mt = 0; mt < 2; ++mt) {
                    mma16816(acc[mt][nt][0], acc[mt][nt][1], acc[mt][nt][2], acc[mt][nt][3],
                             aF[mt][0], aF[mt][1], aF[mt][2], aF[mt][3], wh0, wh1);
                    mma16816(acc[mt][nt][0], acc[mt][nt][1], acc[mt][nt][2], acc[mt][nt][3],
                             aF[mt][0], aF[mt][1], aF[mt][2], aF[mt][3], wl0, wl1);
                }
            }
        }
        __syncthreads();
    }

#pragma unroll
    for (int mt = 0; mt < 2; ++mt) {
        const int m0 = bm + wm * 32 + mt * 16 + group;
#pragma unroll
        for (int nt = 0; nt < 8; ++nt) {
            const int col = bn + wn * 64 + nt * 8 + tig * 2;
            const float bx = bias[col], by = bias[col + 1];
            *(float2*)(C + (size_t)m0 * D_SZ + col) =
                make_float2(acc[mt][nt][0] + bx, acc[mt][nt][1] + by);
            *(float2*)(C + (size_t)(m0 + 8) * D_SZ + col) =
                make_float2(acc[mt][nt][2] + bx, acc[mt][nt][3] + by);
        }
    }
}

// ---------------------------------------------------------------------------
// RoPE + f16 conversion: q -> single f16 (A-side), k -> hi/lo f16 (B-side).
// blockIdx.y: 0 = q, 1 = k. One thread owns float4 at (d4, d4+512).
// ---------------------------------------------------------------------------
__global__ __launch_bounds__(256) void rope_split(
    const float* __restrict__ qp, const float* __restrict__ kp,
    const float* __restrict__ ct, const float* __restrict__ st,
    __half* __restrict__ qhi_, __half* __restrict__ khi_,
    __half* __restrict__ klo_)
{
    const int gid = blockIdx.x * 256 + threadIdx.x;
    const int d4 = (gid & 127) * 4;
    const int bs = gid >> 7;
    const int s = bs & (S_SZ - 1);
    const bool isK = blockIdx.y != 0;
    const float* src = (isK ? kp : qp) + (size_t)bs * D_SZ;

    float4 x1 = *(const float4*)(src + d4);
    float4 x2 = *(const float4*)(src + d4 + 512);
    float4 c1 = *(const float4*)(ct + (size_t)s * D_SZ + d4);
    float4 s1 = *(const float4*)(st + (size_t)s * D_SZ + d4);
    float4 c2 = *(const float4*)(ct + (size_t)s * D_SZ + d4 + 512);
    float4 s2 = *(const float4*)(st + (size_t)s * D_SZ + d4 + 512);

    float r1[4] = { x1.x * c1.x - x2.x * s1.x, x1.y * c1.y - x2.y * s1.y,
                    x1.z * c1.z - x2.z * s1.z, x1.w * c1.w - x2.w * s1.w };
    float r2[4] = { x2.x * c2.x + x1.x * s2.x, x2.y * c2.y + x1.y * s2.y,
                    x2.z * c2.z + x1.z * s2.z, x2.w * c2.w + x1.w * s2.w };

    uint32_t h01 = pack_f16(r1[0], r1[1]), h23 = pack_f16(r1[2], r1[3]);
    uint32_t g01 = pack_f16(r2[0], r2[1]), g23 = pack_f16(r2[2], r2[3]);
    if (!isK) {
        *(uint2*)(qhi_ + (size_t)bs * D_SZ + d4)       = make_uint2(h01, h23);
        *(uint2*)(qhi_ + (size_t)bs * D_SZ + d4 + 512) = make_uint2(g01, g23);
    } else {
        *(uint2*)(khi_ + (size_t)bs * D_SZ + d4)       = make_uint2(h01, h23);
        *(uint2*)(khi_ + (size_t)bs * D_SZ + d4 + 512) = make_uint2(g01, g23);
        float2 f01 = unpack_f16(h01), f23 = unpack_f16(h23);
        float2 e01 = unpack_f16(g01), e23 = unpack_f16(g23);
        uint32_t l01 = pack_f16(r1[0] - f01.x, r1[1] - f01.y);
        uint32_t l23 = pack_f16(r1[2] - f23.x, r1[3] - f23.y);
        uint32_t m01 = pack_f16(r2[0] - e01.x, r2[1] - e01.y);
        uint32_t m23 = pack_f16(r2[2] - e23.x, r2[3] - e23.y);
        *(uint2*)(klo_ + (size_t)bs * D_SZ + d4)       = make_uint2(l01, l23);
        *(uint2*)(klo_ + (size_t)bs * D_SZ + d4 + 512) = make_uint2(m01, m23);
    }
}

// ---------------------------------------------------------------------------
// V transpose + hi/lo f16 split: vp[b][s][h*64+d] -> vt[(b*16+h)*64+d][s]
// ---------------------------------------------------------------------------
__global__ __launch_bounds__(256) void vsplit(
    const float* __restrict__ vp,
    __half* __restrict__ vthi, __half* __restrict__ vtlo)
{
    __shared__ float sT[64][65];
    const int tid = threadIdx.x;
    const int bh = blockIdx.y;
    const int b = bh >> 4, h = bh & 15;
    const int s0 = blockIdx.x * 64;

#pragma unroll
    for (int it = 0; it < 4; ++it) {
        int idx = tid + it * 256;
        int row = idx >> 4, c4 = idx & 15;
        float4 v = *(const float4*)(vp + (size_t)(b * S_SZ + s0 + row) * D_SZ + h * DK_SZ + c4 * 4);
        sT[row][c4 * 4 + 0] = v.x; sT[row][c4 * 4 + 1] = v.y;
        sT[row][c4 * 4 + 2] = v.z; sT[row][c4 * 4 + 3] = v.w;
    }
    __syncthreads();

    const int d = tid >> 2, sg = (tid & 3) * 16;
    uint32_t hv[8], lv[8];
#pragma unroll
    for (int j = 0; j < 8; ++j) {
        float v0 = sT[sg + 2 * j][d], v1 = sT[sg + 2 * j + 1][d];
        hv[j] = pack_f16(v0, v1);
        float2 f = unpack_f16(hv[j]);
        lv[j] = pack_f16(v0 - f.x, v1 - f.y);
    }
    const size_t base = ((size_t)bh * 64 + d) * S_SZ + s0 + sg;
    *(uint4*)(vthi + base)     = make_uint4(hv[0], hv[1], hv[2], hv[3]);
    *(uint4*)(vthi + base + 8) = make_uint4(hv[4], hv[5], hv[6], hv[7]);
    *(uint4*)(vtlo + base)     = make_uint4(lv[0], lv[1], lv[2], lv[3]);
    *(uint4*)(vtlo + base + 8) = make_uint4(lv[4], lv[5], lv[6], lv[7]);
}

// ---------------------------------------------------------------------------
// Flash attention on mma.sync f16, 2-pass hi/lo (B-side split only).
// One block = one (b,h) x 64 query rows. 4 warps, 16 rows each.
// ---------------------------------------------------------------------------
#define APAD 72
#define ATILEB (64 * APAD * 2)               /* 9216 */
#define ATTN_SMEM_BYTES (8 * ATILEB)         /* 73728 */

__global__ __launch_bounds__(128, 3) void attn_mma(
    const __half* __restrict__ qhi_,
    const __half* __restrict__ khi_, const __half* __restrict__ klo_,
    const __half* __restrict__ vthi_, const __half* __restrict__ vtlo_,
    const float* __restrict__ mask, const float* __restrict__ prior_bias,
    float* __restrict__ out)
{
    extern __shared__ char asm_[];
    const uint32_t sb = smem_u32(asm_);

    const int tid = threadIdx.x;
    const int wid = tid >> 5, lane = tid & 31;
    const int group = lane >> 2, tig = lane & 3;
    const int bh = blockIdx.y, b = bh >> 4, h = bh & 15;
    const int q0 = blockIdx.x * 64;

    const float LOG2E = 1.4426950408889634f;
    float sig = 1.0f / (1.0f + __expf(-prior_bias[h]));
    sig *= LOG2E;
    const float scale = 0.125f * LOG2E;

    uint32_t qh[4][4];
    const int r0 = wid * 16 + group;
    {
        const size_t rowa = (size_t)(b * S_SZ + q0 + r0) * D_SZ + h * DK_SZ;
        const size_t rowb = rowa + 8 * D_SZ;
#pragma unroll
        for (int ks = 0; ks < 4; ++ks) {
            const int d0 = ks * 16 + tig * 2;
            qh[ks][0] = *(const uint32_t*)(qhi_ + rowa + d0);
            qh[ks][1] = *(const uint32_t*)(qhi_ + rowb + d0);
            qh[ks][2] = *(const uint32_t*)(qhi_ + rowa + d0 + 8);
            qh[ks][3] = *(const uint32_t*)(qhi_ + rowb + d0 + 8);
        }
    }

    auto stage = [&](int kt, int s) {
        const int k0 = kt * 64;
#pragma unroll
        for (int it = 0; it < 16; ++it) {
            const int tile = it >> 2;                       // 0 khi,1 klo,2 vhi,3 vlo
            const int idx = (it & 3) * 128 + tid;
            const int r = idx >> 3, c8 = idx & 7;
            const __half* src;
            uint32_t dst;
            if (tile == 0) {
                src = khi_ + (size_t)(b * S_SZ + k0 + r) * D_SZ + h * DK_SZ + c8 * 8;
                dst = sb + (uint32_t)((s * 2 + 0) * ATILEB);
            } else if (tile == 1) {
                src = klo_ + (size_t)(b * S_SZ + k0 + r) * D_SZ + h * DK_SZ + c8 * 8;
                dst = sb + (uint32_t)((s * 2 + 1) * ATILEB);
            } else if (tile == 2) {
                src = vthi_ + (size_t)(bh * 64 + r) * S_SZ + k0 + c8 * 8;
                dst = sb + 36864u + (uint32_t)((s * 2 + 0) * ATILEB);
            } else {
                src = vtlo_ + (size_t)(bh * 64 + r) * S_SZ + k0 + c8 * 8;
                dst = sb + 36864u + (uint32_t)((s * 2 + 1) * ATILEB);
            }
            cp_async16(dst + (uint32_t)((r * APAD + c8 * 8) * 2), src);
        }
    };

    float o[8][4];
#pragma unroll
    for (int i = 0; i < 8; i++)
#pragma unroll
        for (int j = 0; j < 4; j++) o[i][j] = 0.f;
    float m0 = -1e30f, m1 = -1e30f, l0 = 0.f, l1 = 0.f;
    const float qr0f = (float)(q0 + r0);
    const float qr1f = qr0f + 8.f;

    stage(0, 0);
    CP_COMMIT();

    for (int kt = 0; kt < S_SZ / 64; ++kt) {
        const int s = kt & 1;
        const int k0 = kt * 64;
        if (kt + 1 < S_SZ / 64) { stage(kt + 1, s ^ 1); CP_COMMIT(); CP_WAIT(1); }
        else CP_WAIT(0);
        __syncthreads();

        const uint32_t kHB = sb + (uint32_t)((s * 2 + 0) * ATILEB);
        const uint32_t kLB = sb + (uint32_t)((s * 2 + 1) * ATILEB);
        const uint32_t vHB = sb + 36864u + (uint32_t)((s * 2 + 0) * ATILEB);
        const uint32_t vLB = sb + 36864u + (uint32_t)((s * 2 + 1) * ATILEB);

        // ---- S = Q K^T (2 passes: K hi + K lo)
        float sc[8][4];
#pragma unroll
        for (int i = 0; i < 8; i++)
#pragma unroll
            for (int j = 0; j < 4; j++) sc[i][j] = 0.f;
#pragma unroll
        for (int ks = 0; ks < 4; ++ks) {
            const int d0 = ks * 16 + tig * 2;
#pragma unroll
            for (int nt = 0; nt < 8; ++nt) {
                const int kn = nt * 8 + group;
                const uint32_t po = (uint32_t)((kn * APAD + d0) * 2);
                uint32_t bh0 = lds32(kHB + po), bh1 = lds32(kHB + po + 16);
                uint32_t bl0 = lds32(kLB + po), bl1 = lds32(kLB + po + 16);
                mma16816(sc[nt][0], sc[nt][1], sc[nt][2], sc[nt][3],
                         qh[ks][0], qh[ks][1], qh[ks][2], qh[ks][3], bh0, bh1);
                mma16816(sc[nt][0], sc[nt][1], sc[nt][2], sc[nt][3],
                         qh[ks][0], qh[ks][1], qh[ks][2], qh[ks][3], bl0, bl1);
            }
        }

        // ---- bias + online softmax (base-2 domain)
        float mx0 = -1e30f, mx1 = -1e30f;
#pragma unroll
        for (int nt = 0; nt < 8; ++nt) {
            const int kl = nt * 8 + tig * 2;
            const float kf0 = (float)(k0 + kl), kf1 = kf0 + 1.f;
            const float mk0 = __ldg(mask + b * S_SZ + k0 + kl) * LOG2E;
            const float mk1 = __ldg(mask + b * S_SZ + k0 + kl + 1) * LOG2E;
            sc[nt][0] = sc[nt][0] * scale + mk0 - sig * fabsf(qr0f - kf0);
            sc[nt][1] = sc[nt][1] * scale + mk1 - sig * fabsf(qr0f - kf1);
            sc[nt][2] = sc[nt][2] * scale + mk0 - sig * fabsf(qr1f - kf0);
            sc[nt][3] = sc[nt][3] * scale + mk1 - sig * fabsf(qr1f - kf1);
            mx0 = fmaxf(mx0, fmaxf(sc[nt][0], sc[nt][1]));
            mx1 = fmaxf(mx1, fmaxf(sc[nt][2], sc[nt][3]));
        }
        mx0 = fmaxf(mx0, __shfl_xor_sync(0xffffffffu, mx0, 1));
        mx0 = fmaxf(mx0, __shfl_xor_sync(0xffffffffu, mx0, 2));
        mx1 = fmaxf(mx1, __shfl_xor_sync(0xffffffffu, mx1, 1));
        mx1 = fmaxf(mx1, __shfl_xor_sync(0xffffffffu, mx1, 2));
        const float nm0 = fmaxf(m0, mx0), nm1 = fmaxf(m1, mx1);
        const float a0 = ex2f(m0 - nm0), a1 = ex2f(m1 - nm1);
        m0 = nm0; m1 = nm1;

        float sum0 = 0.f, sum1 = 0.f;
#pragma unroll
        for (int nt = 0; nt < 8; ++nt) {
            sc[nt][0] = ex2f(sc[nt][0] - m0);
            sc[nt][1] = ex2f(sc[nt][1] - m0);
            sc[nt][2] = ex2f(sc[nt][2] - m1);
            sc[nt][3] = ex2f(sc[nt][3] - m1);
            sum0 += sc[nt][0] + sc[nt][1];
            sum1 += sc[nt][2] + sc[nt][3];
        }
        sum0 += __shfl_xor_sync(0xffffffffu, sum0, 1);
        sum0 += __shfl_xor_sync(0xffffffffu, sum0, 2);
        sum1 += __shfl_xor_sync(0xffffffffu, sum1, 1);
        sum1 += __shfl_xor_sync(0xffffffffu, sum1, 2);
        l0 = l0 * a0 + sum0;
        l1 = l1 * a1 + sum1;
#pragma unroll
        for (int nt = 0; nt < 8; ++nt) {
            o[nt][0] *= a0; o[nt][1] *= a0;
            o[nt][2] *= a1; o[nt][3] *= a1;
        }

        // ---- P fragments straight from accumulators (single f16)
        uint32_t pa[4][4];
#pragma unroll
        for (int ks = 0; ks < 4; ++ks) {
            pa[ks][0] = pack_f16(sc[2 * ks][0], sc[2 * ks][1]);
            pa[ks][1] = pack_f16(sc[2 * ks][2], sc[2 * ks][3]);
            pa[ks][2] = pack_f16(sc[2 * ks + 1][0], sc[2 * ks + 1][1]);
            pa[ks][3] = pack_f16(sc[2 * ks + 1][2], sc[2 * ks + 1][3]);
        }
        // ---- O += P V (2 passes: V hi + V lo)
#pragma unroll
        for (int ks = 0; ks < 4; ++ks) {
            const int kk = ks * 16 + tig * 2;
#pragma unroll
            for (int nt = 0; nt < 8; ++nt) {
                const int dn = nt * 8 + group;
                const uint32_t po = (uint32_t)((dn * APAD + kk) * 2);
                uint32_t bh0 = lds32(vHB + po), bh1 = lds32(vHB + po + 16);
                uint32_t bl0 = lds32(vLB + po), bl1 = lds32(vLB + po + 16);
                mma16816(o[nt][0], o[nt][1], o[nt][2], o[nt][3],
                         pa[ks][0], pa[ks][1], pa[ks][2], pa[ks][3], bh0, bh1);
                mma16816(o[nt][0], o[nt][1], o[nt][2], o[nt][3],
                         pa[ks][0], pa[ks][1], pa[ks][2], pa[ks][3], bl0, bl1);
            }
        }
        __syncthreads();
    }

    const float inv0 = 1.0f / l0, inv1 = 1.0f / l1;
    const int gr0 = b * S_SZ + q0 + r0;
#pragma unroll
    for (int nt = 0; nt < 8; ++nt) {
        const int col = h * DK_SZ + nt * 8 + tig * 2;
        *(float2*)(out + (size_t)gr0 * D_SZ + col) =
            make_float2(o[nt][0] * inv0, o[nt][1] * inv0);
        *(float2*)(out + (size_t)(gr0 + 8) * D_SZ + col) =
            make_float2(o[nt][2] * inv1, o[nt][3] * inv1);
    }
}

// ---------------------------------------------------------------------------
extern "C" void kernel_launch(void* const* d_in, const int* in_sizes, int n_in,
                              void* d_out, int out_size)
{
    const float* q     = (const float*)d_in[0];
    const float* k     = (const float*)d_in[1];
    const float* v     = (const float*)d_in[2];
    const float* cosp  = (const float*)d_in[3];
    const float* sinp  = (const float*)d_in[4];
    const float* maskp = (const float*)d_in[5];
    // d_in[6] = short_matrix (analytic: -|i-j|)
    const float* Wq = (const float*)d_in[7];
    const float* bq = (const float*)d_in[8];
    const float* Wk = (const float*)d_in[9];
    const float* bk = (const float*)d_in[10];
    const float* Wv = (const float*)d_in[11];
    const float* bv = (const float*)d_in[12];
    const float* Wo = (const float*)d_in[13];
    const float* bo = (const float*)d_in[14];
    const float* apb = (const float*)d_in[15];

    float *qp, *kp, *vp, *att;
    __half *whi, *wlo, *qhi, *khi, *klo, *vthi, *vtlo;
    cudaGetSymbolAddress((void**)&qp,   g_qp);
    cudaGetSymbolAddress((void**)&kp,   g_kp);
    cudaGetSymbolAddress((void**)&vp,   g_vp);
    cudaGetSymbolAddress((void**)&att,  g_att);
    cudaGetSymbolAddress((void**)&whi,  g_whi);
    cudaGetSymbolAddress((void**)&wlo,  g_wlo);
    cudaGetSymbolAddress((void**)&qhi,  g_qhi);
    cudaGetSymbolAddress((void**)&khi,  g_khi);
    cudaGetSymbolAddress((void**)&klo,  g_klo);
    cudaGetSymbolAddress((void**)&vthi, g_vthi);
    cudaGetSymbolAddress((void**)&vtlo, g_vtlo);

    cudaFuncSetAttribute(gemm_mma, cudaFuncAttributeMaxDynamicSharedMemorySize,
                         GEMM_SMEM_BYTES);
    cudaFuncSetAttribute(attn_mma, cudaFuncAttributeMaxDynamicSharedMemorySize,
                         ATTN_SMEM_BYTES);

    const int WN = D_SZ * D_SZ;
    cvt_hilo<<<WN / 1024, 256>>>(Wq, whi + 0 * WN, wlo + 0 * WN);
    cvt_hilo<<<WN / 1024, 256>>>(Wk, whi + 1 * WN, wlo + 1 * WN);
    cvt_hilo<<<WN / 1024, 256>>>(Wv, whi + 2 * WN, wlo + 2 * WN);
    cvt_hilo<<<WN / 1024, 256>>>(Wo, whi + 3 * WN, wlo + 3 * WN);

    dim3 gg(D_SZ / 128, MROWS / 128);
    gemm_mma<<<gg, 256, GEMM_SMEM_BYTES>>>(q, whi + 0 * WN, wlo + 0 * WN, bq, qp);
    gemm_mma<<<gg, 256, GEMM_SMEM_BYTES>>>(k, whi + 1 * WN, wlo + 1 * WN, bk, kp);
    gemm_mma<<<gg, 256, GEMM_SMEM_BYTES>>>(v, whi + 2 * WN, wlo + 2 * WN, bv, vp);

    rope_split<<<dim3(MROWS * 128 / 256, 2), 256>>>(qp, kp, cosp, sinp,
                                                    qhi, khi, klo);
    vsplit<<<dim3(S_SZ / 64, B_SZ * H_SZ), 256>>>(vp, vthi, vtlo);

    attn_mma<<<dim3(S_SZ / 64, B_SZ * H_SZ), 128, ATTN_SMEM_BYTES>>>(
        qhi, khi, klo, vthi, vtlo, maskp, apb, att);

    gemm_mma<<<gg, 256, GEMM_SMEM_BYTES>>>(att, whi + 3 * WN, wlo + 3 * WN, bo,
                                           (float*)d_out);
}

// round 7
// speedup vs baseline: 7.3563x; 1.5411x over previous
#include <cuda_runtime.h>
#include <cuda_fp16.h>
#include <math_constants.h>
#include <cstdint>
#include <cstddef>

#define B_SZ 8
#define S_SZ 1024
#define D_SZ 1024
#define H_SZ 16
#define DK_SZ 64
#define MROWS (B_SZ * S_SZ)   /* 8192 */

// ---------------------------------------------------------------------------
// Scratch (allocation-free rule: __device__ globals)
// ---------------------------------------------------------------------------
__device__ float g_qp[MROWS * D_SZ];
__device__ float g_kp[MROWS * D_SZ];
__device__ float g_vp[MROWS * D_SZ];
__device__ float g_att[MROWS * D_SZ];
__device__ __half g_w16[4][D_SZ * D_SZ];
__device__ __half g_q16[MROWS * D_SZ];
__device__ __half g_k16[MROWS * D_SZ];
__device__ __half g_vt16[MROWS * D_SZ];   // [b*h][d][s]

// ---------------------------------------------------------------------------
__device__ __forceinline__ uint32_t smem_u32(const void* p) {
    uint32_t a;
    asm("{ .reg .u64 t; cvta.to.shared.u64 t, %1; cvt.u32.u64 %0, t; }"
        : "=r"(a) : "l"(p));
    return a;
}
__device__ __forceinline__ void cp_async16(uint32_t dst, const void* src) {
    asm volatile("cp.async.cg.shared.global [%0], [%1], 16;\n"
                 :: "r"(dst), "l"(src) : "memory");
}
#define CP_COMMIT() asm volatile("cp.async.commit_group;\n" ::: "memory")
#define CP_WAIT(n)  asm volatile("cp.async.wait_group %0;\n" :: "n"(n) : "memory")

__device__ __forceinline__ uint32_t lds32(uint32_t a) {
    uint32_t v;
    asm volatile("ld.shared.b32 %0, [%1];" : "=r"(v) : "r"(a));
    return v;
}
__device__ __forceinline__ void mma16816(
    float& d0, float& d1, float& d2, float& d3,
    uint32_t a0, uint32_t a1, uint32_t a2, uint32_t a3,
    uint32_t b0, uint32_t b1)
{
    asm volatile(
        "mma.sync.aligned.m16n8k16.row.col.f32.f16.f16.f32 "
        "{%0,%1,%2,%3}, {%4,%5,%6,%7}, {%8,%9}, {%0,%1,%2,%3};\n"
        : "+f"(d0), "+f"(d1), "+f"(d2), "+f"(d3)
        : "r"(a0), "r"(a1), "r"(a2), "r"(a3), "r"(b0), "r"(b1));
}
// pack two f32 -> f16x2 reg: low half = first arg
__device__ __forceinline__ uint32_t pack_f16(float lo, float hi) {
    uint32_t r;
    asm("cvt.rn.f16x2.f32 %0, %1, %2;" : "=r"(r) : "f"(hi), "f"(lo));
    return r;
}
__device__ __forceinline__ float ex2f(float x) {
    float y; asm("ex2.approx.ftz.f32 %0, %1;" : "=f"(y) : "f"(x)); return y;
}

// ---------------------------------------------------------------------------
// fp32 -> f16 (weights only; done once, tiny)
// ---------------------------------------------------------------------------
__global__ __launch_bounds__(256) void cvt_f16(
    const float* __restrict__ x, __half* __restrict__ y)
{
    int i = blockIdx.x * blockDim.x + threadIdx.x;
    float4 v = ((const float4*)x)[i];
    ((uint2*)y)[i] = make_uint2(pack_f16(v.x, v.y), pack_f16(v.z, v.w));
}

// ---------------------------------------------------------------------------
// Tensor-core GEMM, fp32 A input with fused f16 conversion, W f16, 1 pass.
// C[m,n] = sum_k A[m,k]*W[n,k] + bias[n]
// Block 128x128x32, 8 warps (4Mx2N), warp tile 32x64.
// ---------------------------------------------------------------------------
#define GPAD 40
#define GTILEB (128 * GPAD * 2)             /* 10240 bytes per tile */
#define GEMM_SMEM_BYTES (4 * GTILEB)        /* 40960: A x2, W x2 */

__global__ __launch_bounds__(256, 2) void gemm_mma(
    const float* __restrict__ A, const __half* __restrict__ W,
    const float* __restrict__ bias, float* __restrict__ C)
{
    extern __shared__ char smc[];
    const uint32_t sb = smem_u32(smc);

    const int tid = threadIdx.x;
    const int wid = tid >> 5, lane = tid & 31;
    const int group = lane >> 2, tig = lane & 3;
    const int wm = wid & 3, wn = wid >> 2;
    const int bm = blockIdx.y * 128;
    const int bn = blockIdx.x * 128;

    float acc[2][8][4];
#pragma unroll
    for (int i = 0; i < 2; i++)
#pragma unroll
        for (int j = 0; j < 8; j++)
#pragma unroll
            for (int r = 0; r < 4; r++) acc[i][j][r] = 0.f;

    const int arow = tid >> 3, ac4 = tid & 7;
    float4 areg[4];

    auto ldgA = [&](int c) {
        const int k0 = c * 32;
#pragma unroll
        for (int it = 0; it < 4; ++it)
            areg[it] = *(const float4*)(A + (size_t)(bm + arow + it * 32) * D_SZ + k0 + ac4 * 4);
    };
    auto stsA = [&](int s) {
        const uint32_t aB = sb + (uint32_t)s * GTILEB;
#pragma unroll
        for (int it = 0; it < 4; ++it) {
            float4 v = areg[it];
            uint32_t h01 = pack_f16(v.x, v.y);
            uint32_t h23 = pack_f16(v.z, v.w);
            uint32_t off = (uint32_t)(((arow + it * 32) * GPAD + ac4 * 4) * 2);
            asm volatile("st.shared.v2.b32 [%0], {%1, %2};" :: "r"(aB + off), "r"(h01), "r"(h23));
        }
    };
    auto cpW = [&](int c, int s) {
        const int k0 = c * 32;
#pragma unroll
        for (int it = 0; it < 2; ++it) {
            int idx = tid + it * 256;
            int r = idx >> 2;
            int c4 = idx & 3;
            const __half* src = W + (size_t)(bn + r) * D_SZ + k0 + c4 * 8;
            uint32_t dst = sb + 2u * GTILEB + (uint32_t)s * GTILEB
                         + (uint32_t)((r * GPAD + c4 * 8) * 2);
            cp_async16(dst, src);
        }
    };

    ldgA(0);
    cpW(0, 0);
    CP_COMMIT();

    for (int c = 0; c < D_SZ / 32; ++c) {
        const int s = c & 1;
        if (c + 1 < D_SZ / 32) { cpW(c + 1, s ^ 1); CP_COMMIT(); CP_WAIT(1); }
        else CP_WAIT(0);
        stsA(s);
        __syncthreads();
        if (c + 1 < D_SZ / 32) ldgA(c + 1);

        const uint32_t aB = sb + (uint32_t)s * GTILEB;
        const uint32_t wB = sb + 2u * GTILEB + (uint32_t)s * GTILEB;
#pragma unroll
        for (int ks = 0; ks < 2; ++ks) {
            const int kk = ks * 16 + tig * 2;
            uint32_t aF[2][4];
#pragma unroll
            for (int mt = 0; mt < 2; ++mt) {
                const int r0 = wm * 32 + mt * 16 + group;
                const uint32_t p = (uint32_t)((r0 * GPAD + kk) * 2);
                const uint32_t p8 = (uint32_t)(((r0 + 8) * GPAD + kk) * 2);
                aF[mt][0] = lds32(aB + p);  aF[mt][1] = lds32(aB + p8);
                aF[mt][2] = lds32(aB + p + 16); aF[mt][3] = lds32(aB + p8 + 16);
            }
#pragma unroll
            for (int nt = 0; nt < 8; ++nt) {
                const int nr = wn * 64 + nt * 8 + group;
                const uint32_t qo = (uint32_t)((nr * GPAD + kk) * 2);
                uint32_t w0 = lds32(wB + qo), w1 = lds32(wB + qo + 16);
#pragma unroll
                for (int mt = 0; mt < 2; ++mt)
                    mma16816(acc[mt][nt][0], acc[mt][nt][1], acc[mt][nt][2], acc[mt][nt][3],
                             aF[mt][0], aF[mt][1], aF[mt][2], aF[mt][3], w0, w1);
            }
        }
        __syncthreads();
    }

#pragma unroll
    for (int mt = 0; mt < 2; ++mt) {
        const int m0 = bm + wm * 32 + mt * 16 + group;
#pragma unroll
        for (int nt = 0; nt < 8; ++nt) {
            const int col = bn + wn * 64 + nt * 8 + tig * 2;
            const float bx = bias[col], by = bias[col + 1];
            *(float2*)(C + (size_t)m0 * D_SZ + col) =
                make_float2(acc[mt][nt][0] + bx, acc[mt][nt][1] + by);
            *(float2*)(C + (size_t)(m0 + 8) * D_SZ + col) =
                make_float2(acc[mt][nt][2] + bx, acc[mt][nt][3] + by);
        }
    }
}

// ---------------------------------------------------------------------------
// RoPE + f16 conversion (single-rounded both q and k).
// blockIdx.y: 0 = q, 1 = k. One thread owns float4 at (d4, d4+512).
// ---------------------------------------------------------------------------
__global__ __launch_bounds__(256) void rope_split(
    const float* __restrict__ qp, const float* __restrict__ kp,
    const float* __restrict__ ct, const float* __restrict__ st,
    __half* __restrict__ q16_, __half* __restrict__ k16_)
{
    const int gid = blockIdx.x * 256 + threadIdx.x;
    const int d4 = (gid & 127) * 4;
    const int bs = gid >> 7;
    const int s = bs & (S_SZ - 1);
    const bool isK = blockIdx.y != 0;
    const float* src = (isK ? kp : qp) + (size_t)bs * D_SZ;
    __half* dst = isK ? k16_ : q16_;

    float4 x1 = *(const float4*)(src + d4);
    float4 x2 = *(const float4*)(src + d4 + 512);
    float4 c1 = *(const float4*)(ct + (size_t)s * D_SZ + d4);
    float4 s1 = *(const float4*)(st + (size_t)s * D_SZ + d4);
    float4 c2 = *(const float4*)(ct + (size_t)s * D_SZ + d4 + 512);
    float4 s2 = *(const float4*)(st + (size_t)s * D_SZ + d4 + 512);

    float r1[4] = { x1.x * c1.x - x2.x * s1.x, x1.y * c1.y - x2.y * s1.y,
                    x1.z * c1.z - x2.z * s1.z, x1.w * c1.w - x2.w * s1.w };
    float r2[4] = { x2.x * c2.x + x1.x * s2.x, x2.y * c2.y + x1.y * s2.y,
                    x2.z * c2.z + x1.z * s2.z, x2.w * c2.w + x1.w * s2.w };

    *(uint2*)(dst + (size_t)bs * D_SZ + d4) =
        make_uint2(pack_f16(r1[0], r1[1]), pack_f16(r1[2], r1[3]));
    *(uint2*)(dst + (size_t)bs * D_SZ + d4 + 512) =
        make_uint2(pack_f16(r2[0], r2[1]), pack_f16(r2[2], r2[3]));
}

// ---------------------------------------------------------------------------
// V transpose + f16: vp[b][s][h*64+d] -> vt[(b*16+h)*64+d][s]
// ---------------------------------------------------------------------------
__global__ __launch_bounds__(256) void vsplit(
    const float* __restrict__ vp, __half* __restrict__ vt16)
{
    __shared__ float sT[64][65];
    const int tid = threadIdx.x;
    const int bh = blockIdx.y;
    const int b = bh >> 4, h = bh & 15;
    const int s0 = blockIdx.x * 64;

#pragma unroll
    for (int it = 0; it < 4; ++it) {
        int idx = tid + it * 256;
        int row = idx >> 4, c4 = idx & 15;
        float4 v = *(const float4*)(vp + (size_t)(b * S_SZ + s0 + row) * D_SZ + h * DK_SZ + c4 * 4);
        sT[row][c4 * 4 + 0] = v.x; sT[row][c4 * 4 + 1] = v.y;
        sT[row][c4 * 4 + 2] = v.z; sT[row][c4 * 4 + 3] = v.w;
    }
    __syncthreads();

    const int d = tid >> 2, sg = (tid & 3) * 16;
    uint32_t hv[8];
#pragma unroll
    for (int j = 0; j < 8; ++j)
        hv[j] = pack_f16(sT[sg + 2 * j][d], sT[sg + 2 * j + 1][d]);
    const size_t base = ((size_t)bh * 64 + d) * S_SZ + s0 + sg;
    *(uint4*)(vt16 + base)     = make_uint4(hv[0], hv[1], hv[2], hv[3]);
    *(uint4*)(vt16 + base + 8) = make_uint4(hv[4], hv[5], hv[6], hv[7]);
}

// ---------------------------------------------------------------------------
// Flash attention on mma.sync f16, single pass per stage.
// One block = one (b,h) x 64 query rows. 4 warps, 16 rows each.
// ---------------------------------------------------------------------------
#define APAD 72
#define ATILEB (64 * APAD * 2)               /* 9216 */
#define ATTN_SMEM_BYTES (4 * ATILEB)         /* 36864: K x2 stages, Vt x2 */

__global__ __launch_bounds__(128, 3) void attn_mma(
    const __half* __restrict__ q16_, const __half* __restrict__ k16_,
    const __half* __restrict__ vt16_,
    const float* __restrict__ mask, const float* __restrict__ prior_bias,
    float* __restrict__ out)
{
    extern __shared__ char asm_[];
    const uint32_t sb = smem_u32(asm_);

    const int tid = threadIdx.x;
    const int wid = tid >> 5, lane = tid & 31;
    const int group = lane >> 2, tig = lane & 3;
    const int bh = blockIdx.y, b = bh >> 4, h = bh & 15;
    const int q0 = blockIdx.x * 64;

    const float LOG2E = 1.4426950408889634f;
    float sig = 1.0f / (1.0f + __expf(-prior_bias[h]));
    sig *= LOG2E;
    const float scale = 0.125f * LOG2E;

    uint32_t qh[4][4];
    const int r0 = wid * 16 + group;
    {
        const size_t rowa = (size_t)(b * S_SZ + q0 + r0) * D_SZ + h * DK_SZ;
        const size_t rowb = rowa + 8 * D_SZ;
#pragma unroll
        for (int ks = 0; ks < 4; ++ks) {
            const int d0 = ks * 16 + tig * 2;
            qh[ks][0] = *(const uint32_t*)(q16_ + rowa + d0);
            qh[ks][1] = *(const uint32_t*)(q16_ + rowb + d0);
            qh[ks][2] = *(const uint32_t*)(q16_ + rowa + d0 + 8);
            qh[ks][3] = *(const uint32_t*)(q16_ + rowb + d0 + 8);
        }
    }

    auto stage = [&](int kt, int s) {
        const int k0 = kt * 64;
#pragma unroll
        for (int it = 0; it < 8; ++it) {
            const int tile = it >> 2;                       // 0 k, 1 vt
            const int idx = (it & 3) * 128 + tid;           // 0..511
            const int r = idx >> 3, c8 = idx & 7;
            const __half* src;
            uint32_t dst;
            if (tile == 0) {
                src = k16_ + (size_t)(b * S_SZ + k0 + r) * D_SZ + h * DK_SZ + c8 * 8;
                dst = sb + (uint32_t)(s * ATILEB);
            } else {
                src = vt16_ + (size_t)(bh * 64 + r) * S_SZ + k0 + c8 * 8;
                dst = sb + 18432u + (uint32_t)(s * ATILEB);
            }
            cp_async16(dst + (uint32_t)((r * APAD + c8 * 8) * 2), src);
        }
    };

    float o[8][4];
#pragma unroll
    for (int i = 0; i < 8; i++)
#pragma unroll
        for (int j = 0; j < 4; j++) o[i][j] = 0.f;
    float m0 = -1e30f, m1 = -1e30f, l0 = 0.f, l1 = 0.f;
    const float qr0f = (float)(q0 + r0);
    const float qr1f = qr0f + 8.f;

    stage(0, 0);
    CP_COMMIT();

    for (int kt = 0; kt < S_SZ / 64; ++kt) {
        const int s = kt & 1;
        const int k0 = kt * 64;
        if (kt + 1 < S_SZ / 64) { stage(kt + 1, s ^ 1); CP_COMMIT(); CP_WAIT(1); }
        else CP_WAIT(0);
        __syncthreads();

        const uint32_t kB = sb + (uint32_t)(s * ATILEB);
        const uint32_t vB = sb + 18432u + (uint32_t)(s * ATILEB);

        // ---- S = Q K^T (single pass)
        float sc[8][4];
#pragma unroll
        for (int i = 0; i < 8; i++)
#pragma unroll
            for (int j = 0; j < 4; j++) sc[i][j] = 0.f;
#pragma unroll
        for (int ks = 0; ks < 4; ++ks) {
            const int d0 = ks * 16 + tig * 2;
#pragma unroll
            for (int nt = 0; nt < 8; ++nt) {
                const int kn = nt * 8 + group;
                const uint32_t po = (uint32_t)((kn * APAD + d0) * 2);
                uint32_t b0 = lds32(kB + po), b1 = lds32(kB + po + 16);
                mma16816(sc[nt][0], sc[nt][1], sc[nt][2], sc[nt][3],
                         qh[ks][0], qh[ks][1], qh[ks][2], qh[ks][3], b0, b1);
            }
        }

        // ---- bias + online softmax (base-2 domain)
        float mx0 = -1e30f, mx1 = -1e30f;
#pragma unroll
        for (int nt = 0; nt < 8; ++nt) {
            const int kl = nt * 8 + tig * 2;
            const float kf0 = (float)(k0 + kl), kf1 = kf0 + 1.f;
            const float mk0 = __ldg(mask + b * S_SZ + k0 + kl) * LOG2E;
            const float mk1 = __ldg(mask + b * S_SZ + k0 + kl + 1) * LOG2E;
            sc[nt][0] = sc[nt][0] * scale + mk0 - sig * fabsf(qr0f - kf0);
            sc[nt][1] = sc[nt][1] * scale + mk1 - sig * fabsf(qr0f - kf1);
            sc[nt][2] = sc[nt][2] * scale + mk0 - sig * fabsf(qr1f - kf0);
            sc[nt][3] = sc[nt][3] * scale + mk1 - sig * fabsf(qr1f - kf1);
            mx0 = fmaxf(mx0, fmaxf(sc[nt][0], sc[nt][1]));
            mx1 = fmaxf(mx1, fmaxf(sc[nt][2], sc[nt][3]));
        }
        mx0 = fmaxf(mx0, __shfl_xor_sync(0xffffffffu, mx0, 1));
        mx0 = fmaxf(mx0, __shfl_xor_sync(0xffffffffu, mx0, 2));
        mx1 = fmaxf(mx1, __shfl_xor_sync(0xffffffffu, mx1, 1));
        mx1 = fmaxf(mx1, __shfl_xor_sync(0xffffffffu, mx1, 2));
        const float nm0 = fmaxf(m0, mx0), nm1 = fmaxf(m1, mx1);
        const float a0 = ex2f(m0 - nm0), a1 = ex2f(m1 - nm1);
        m0 = nm0; m1 = nm1;

        float sum0 = 0.f, sum1 = 0.f;
#pragma unroll
        for (int nt = 0; nt < 8; ++nt) {
            sc[nt][0] = ex2f(sc[nt][0] - m0);
            sc[nt][1] = ex2f(sc[nt][1] - m0);
            sc[nt][2] = ex2f(sc[nt][2] - m1);
            sc[nt][3] = ex2f(sc[nt][3] - m1);
            sum0 += sc[nt][0] + sc[nt][1];
            sum1 += sc[nt][2] + sc[nt][3];
        }
        sum0 += __shfl_xor_sync(0xffffffffu, sum0, 1);
        sum0 += __shfl_xor_sync(0xffffffffu, sum0, 2);
        sum1 += __shfl_xor_sync(0xffffffffu, sum1, 1);
        sum1 += __shfl_xor_sync(0xffffffffu, sum1, 2);
        l0 = l0 * a0 + sum0;
        l1 = l1 * a1 + sum1;
#pragma unroll
        for (int nt = 0; nt < 8; ++nt) {
            o[nt][0] *= a0; o[nt][1] *= a0;
            o[nt][2] *= a1; o[nt][3] *= a1;
        }

        // ---- P fragments straight from accumulators (single f16)
        uint32_t pa[4][4];
#pragma unroll
        for (int ks = 0; ks < 4; ++ks) {
            pa[ks][0] = pack_f16(sc[2 * ks][0], sc[2 * ks][1]);
            pa[ks][1] = pack_f16(sc[2 * ks][2], sc[2 * ks][3]);
            pa[ks][2] = pack_f16(sc[2 * ks + 1][0], sc[2 * ks + 1][1]);
            pa[ks][3] = pack_f16(sc[2 * ks + 1][2], sc[2 * ks + 1][3]);
        }
        // ---- O += P V (single pass)
#pragma unroll
        for (int ks = 0; ks < 4; ++ks) {
            const int kk = ks * 16 + tig * 2;
#pragma unroll
            for (int nt = 0; nt < 8; ++nt) {
                const int dn = nt * 8 + group;
                const uint32_t po = (uint32_t)((dn * APAD + kk) * 2);
                uint32_t b0 = lds32(vB + po), b1 = lds32(vB + po + 16);
                mma16816(o[nt][0], o[nt][1], o[nt][2], o[nt][3],
                         pa[ks][0], pa[ks][1], pa[ks][2], pa[ks][3], b0, b1);
            }
        }
        __syncthreads();
    }

    const float inv0 = 1.0f / l0, inv1 = 1.0f / l1;
    const int gr0 = b * S_SZ + q0 + r0;
#pragma unroll
    for (int nt = 0; nt < 8; ++nt) {
        const int col = h * DK_SZ + nt * 8 + tig * 2;
        *(float2*)(out + (size_t)gr0 * D_SZ + col) =
            make_float2(o[nt][0] * inv0, o[nt][1] * inv0);
        *(float2*)(out + (size_t)(gr0 + 8) * D_SZ + col) =
            make_float2(o[nt][2] * inv1, o[nt][3] * inv1);
    }
}

// ---------------------------------------------------------------------------
extern "C" void kernel_launch(void* const* d_in, const int* in_sizes, int n_in,
                              void* d_out, int out_size)
{
    const float* q     = (const float*)d_in[0];
    const float* k     = (const float*)d_in[1];
    const float* v     = (const float*)d_in[2];
    const float* cosp  = (const float*)d_in[3];
    const float* sinp  = (const float*)d_in[4];
    const float* maskp = (const float*)d_in[5];
    // d_in[6] = short_matrix (analytic: -|i-j|)
    const float* Wq = (const float*)d_in[7];
    const float* bq = (const float*)d_in[8];
    const float* Wk = (const float*)d_in[9];
    const float* bk = (const float*)d_in[10];
    const float* Wv = (const float*)d_in[11];
    const float* bv = (const float*)d_in[12];
    const float* Wo = (const float*)d_in[13];
    const float* bo = (const float*)d_in[14];
    const float* apb = (const float*)d_in[15];

    float *qp, *kp, *vp, *att;
    __half *w16, *q16, *k16, *vt16;
    cudaGetSymbolAddress((void**)&qp,   g_qp);
    cudaGetSymbolAddress((void**)&kp,   g_kp);
    cudaGetSymbolAddress((void**)&vp,   g_vp);
    cudaGetSymbolAddress((void**)&att,  g_att);
    cudaGetSymbolAddress((void**)&w16,  g_w16);
    cudaGetSymbolAddress((void**)&q16,  g_q16);
    cudaGetSymbolAddress((void**)&k16,  g_k16);
    cudaGetSymbolAddress((void**)&vt16, g_vt16);

    cudaFuncSetAttribute(gemm_mma, cudaFuncAttributeMaxDynamicSharedMemorySize,
                         GEMM_SMEM_BYTES);
    cudaFuncSetAttribute(attn_mma, cudaFuncAttributeMaxDynamicSharedMemorySize,
                         ATTN_SMEM_BYTES);

    const int WN = D_SZ * D_SZ;
    cvt_f16<<<WN / 1024, 256>>>(Wq, w16 + 0 * WN);
    cvt_f16<<<WN / 1024, 256>>>(Wk, w16 + 1 * WN);
    cvt_f16<<<WN / 1024, 256>>>(Wv, w16 + 2 * WN);
    cvt_f16<<<WN / 1024, 256>>>(Wo, w16 + 3 * WN);

    dim3 gg(D_SZ / 128, MROWS / 128);
    gemm_mma<<<gg, 256, GEMM_SMEM_BYTES>>>(q, w16 + 0 * WN, bq, qp);
    gemm_mma<<<gg, 256, GEMM_SMEM_BYTES>>>(k, w16 + 1 * WN, bk, kp);
    gemm_mma<<<gg, 256, GEMM_SMEM_BYTES>>>(v, w16 + 2 * WN, bv, vp);

    rope_split<<<dim3(MROWS * 128 / 256, 2), 256>>>(qp, kp, cosp, sinp, q16, k16);
    vsplit<<<dim3(S_SZ / 64, B_SZ * H_SZ), 256>>>(vp, vt16);

    attn_mma<<<dim3(S_SZ / 64, B_SZ * H_SZ), 128, ATTN_SMEM_BYTES>>>(
        q16, k16, vt16, maskp, apb, att);

    gemm_mma<<<gg, 256, GEMM_SMEM_BYTES>>>(att, w16 + 3 * WN, bo, (float*)d_out);
}

// round 8
// speedup vs baseline: 7.8356x; 1.0651x over previous
#include <cuda_runtime.h>
#include <cuda_fp16.h>
#include <math_constants.h>
#include <cstdint>
#include <cstddef>

#define B_SZ 8
#define S_SZ 1024
#define D_SZ 1024
#define H_SZ 16
#define DK_SZ 64
#define MROWS (B_SZ * S_SZ)   /* 8192 */
#define WN (D_SZ * D_SZ)

// ---------------------------------------------------------------------------
// Scratch (allocation-free rule: __device__ globals)
// ---------------------------------------------------------------------------
__device__ __half g_w16[4][WN];
__device__ __half g_q16[MROWS * D_SZ];
__device__ __half g_k16[MROWS * D_SZ];
__device__ __half g_vt16[MROWS * D_SZ];   // [b*h][d][s]
__device__ __half g_att16[MROWS * D_SZ];

// ---------------------------------------------------------------------------
__device__ __forceinline__ uint32_t smem_u32(const void* p) {
    uint32_t a;
    asm("{ .reg .u64 t; cvta.to.shared.u64 t, %1; cvt.u32.u64 %0, t; }"
        : "=r"(a) : "l"(p));
    return a;
}
__device__ __forceinline__ void cp_async16(uint32_t dst, const void* src) {
    asm volatile("cp.async.cg.shared.global [%0], [%1], 16;\n"
                 :: "r"(dst), "l"(src) : "memory");
}
#define CP_COMMIT() asm volatile("cp.async.commit_group;\n" ::: "memory")
#define CP_WAIT(n)  asm volatile("cp.async.wait_group %0;\n" :: "n"(n) : "memory")

__device__ __forceinline__ uint32_t lds32(uint32_t a) {
    uint32_t v;
    asm volatile("ld.shared.b32 %0, [%1];" : "=r"(v) : "r"(a));
    return v;
}
__device__ __forceinline__ void mma16816(
    float& d0, float& d1, float& d2, float& d3,
    uint32_t a0, uint32_t a1, uint32_t a2, uint32_t a3,
    uint32_t b0, uint32_t b1)
{
    asm volatile(
        "mma.sync.aligned.m16n8k16.row.col.f32.f16.f16.f32 "
        "{%0,%1,%2,%3}, {%4,%5,%6,%7}, {%8,%9}, {%0,%1,%2,%3};\n"
        : "+f"(d0), "+f"(d1), "+f"(d2), "+f"(d3)
        : "r"(a0), "r"(a1), "r"(a2), "r"(a3), "r"(b0), "r"(b1));
}
// pack two f32 -> f16x2 reg: low half = first arg
__device__ __forceinline__ uint32_t pack_f16(float lo, float hi) {
    uint32_t r;
    asm("cvt.rn.f16x2.f32 %0, %1, %2;" : "=r"(r) : "f"(hi), "f"(lo));
    return r;
}
__device__ __forceinline__ float ex2f(float x) {
    float y; asm("ex2.approx.ftz.f32 %0, %1;" : "=f"(y) : "f"(x)); return y;
}

// ---------------------------------------------------------------------------
// fp32 -> f16 (weights only; done once, tiny)
// ---------------------------------------------------------------------------
__global__ __launch_bounds__(256) void cvt_f16(
    const float* __restrict__ x, __half* __restrict__ y)
{
    int i = blockIdx.x * blockDim.x + threadIdx.x;
    float4 v = ((const float4*)x)[i];
    ((uint2*)y)[i] = make_uint2(pack_f16(v.x, v.y), pack_f16(v.z, v.w));
}

// ---------------------------------------------------------------------------
// Fused QKV projection GEMM.
// z = 0: Q proj, paired-N tile, epilogue bias+RoPE -> q16 (f16)
// z = 1: K proj, paired-N tile, epilogue bias+RoPE -> k16 (f16)
// z = 2: V proj, plain-N tile, epilogue bias + smem transpose -> vt16
// Block 128x128x32, 8 warps (4Mx2N), warp tile 32x64.
// Paired-N: local col l -> global col: w = l & 63, wn = l >> 6;
//   w < 32 : bn*64 + wn*32 + w          (lower half d)
//   w >= 32: 512 + bn*64 + wn*32 + w-32 (upper half d+512)
// so a thread's nt and nt+4 fragments hold the (d, d+512) RoPE pair.
// ---------------------------------------------------------------------------
#define GPAD 40
#define GTILEB (128 * GPAD * 2)             /* 10240 bytes per tile */
#define GEMM_SMEM_BYTES 40960               /* A x2, W x2 */
#define VPAD 136

__global__ __launch_bounds__(256, 2) void qkv_gemm(
    const float* __restrict__ q, const float* __restrict__ k,
    const float* __restrict__ v, const __half* __restrict__ w16,
    const float* __restrict__ bq, const float* __restrict__ bk,
    const float* __restrict__ bv,
    const float* __restrict__ ct, const float* __restrict__ st,
    __half* __restrict__ q16, __half* __restrict__ k16,
    __half* __restrict__ vt16)
{
    extern __shared__ char smc[];
    const uint32_t sb = smem_u32(smc);

    const int tid = threadIdx.x;
    const int wid = tid >> 5, lane = tid & 31;
    const int group = lane >> 2, tig = lane & 3;
    const int wm = wid & 3, wn = wid >> 2;
    const int bn = blockIdx.x;
    const int bm = blockIdx.y * 128;
    const int z = blockIdx.z;

    const float* A = (z == 0) ? q : (z == 1) ? k : v;
    const __half* W = w16 + (size_t)z * WN;
    const float* bias = (z == 0) ? bq : (z == 1) ? bk : bv;

    float acc[2][8][4];
#pragma unroll
    for (int i = 0; i < 2; i++)
#pragma unroll
        for (int j = 0; j < 8; j++)
#pragma unroll
            for (int r = 0; r < 4; r++) acc[i][j][r] = 0.f;

    const int arow = tid >> 3, ac4 = tid & 7;
    float4 areg[4];

    auto ldgA = [&](int c) {
        const int k0 = c * 32;
#pragma unroll
        for (int it = 0; it < 4; ++it)
            areg[it] = *(const float4*)(A + (size_t)(bm + arow + it * 32) * D_SZ + k0 + ac4 * 4);
    };
    auto stsA = [&](int s) {
        const uint32_t aB = sb + (uint32_t)s * GTILEB;
#pragma unroll
        for (int it = 0; it < 4; ++it) {
            float4 vv = areg[it];
            uint32_t h01 = pack_f16(vv.x, vv.y);
            uint32_t h23 = pack_f16(vv.z, vv.w);
            uint32_t off = (uint32_t)(((arow + it * 32) * GPAD + ac4 * 4) * 2);
            asm volatile("st.shared.v2.b32 [%0], {%1, %2};" :: "r"(aB + off), "r"(h01), "r"(h23));
        }
    };
    auto cpW = [&](int c, int s) {
        const int k0 = c * 32;
#pragma unroll
        for (int it = 0; it < 2; ++it) {
            int idx = tid + it * 256;
            int r = idx >> 2;
            int c4 = idx & 3;
            int grow;
            if (z < 2) {
                int w = r & 63, wnr = r >> 6;
                grow = (w < 32) ? (bn * 64 + wnr * 32 + w)
                                : (512 + bn * 64 + wnr * 32 + (w - 32));
            } else {
                grow = bn * 128 + r;
            }
            const __half* src = W + (size_t)grow * D_SZ + k0 + c4 * 8;
            uint32_t dst = sb + 2u * GTILEB + (uint32_t)s * GTILEB
                         + (uint32_t)((r * GPAD + c4 * 8) * 2);
            cp_async16(dst, src);
        }
    };

    ldgA(0);
    cpW(0, 0);
    CP_COMMIT();

    for (int c = 0; c < D_SZ / 32; ++c) {
        const int s = c & 1;
        if (c + 1 < D_SZ / 32) { cpW(c + 1, s ^ 1); CP_COMMIT(); CP_WAIT(1); }
        else CP_WAIT(0);
        stsA(s);
        __syncthreads();
        if (c + 1 < D_SZ / 32) ldgA(c + 1);

        const uint32_t aB = sb + (uint32_t)s * GTILEB;
        const uint32_t wB = sb + 2u * GTILEB + (uint32_t)s * GTILEB;
#pragma unroll
        for (int ks = 0; ks < 2; ++ks) {
            const int kk = ks * 16 + tig * 2;
            uint32_t aF[2][4];
#pragma unroll
            for (int mt = 0; mt < 2; ++mt) {
                const int r0 = wm * 32 + mt * 16 + group;
                const uint32_t p = (uint32_t)((r0 * GPAD + kk) * 2);
                const uint32_t p8 = (uint32_t)(((r0 + 8) * GPAD + kk) * 2);
                aF[mt][0] = lds32(aB + p);  aF[mt][1] = lds32(aB + p8);
                aF[mt][2] = lds32(aB + p + 16); aF[mt][3] = lds32(aB + p8 + 16);
            }
#pragma unroll
            for (int nt = 0; nt < 8; ++nt) {
                const int nr = wn * 64 + nt * 8 + group;
                const uint32_t qo = (uint32_t)((nr * GPAD + kk) * 2);
                uint32_t w0 = lds32(wB + qo), w1 = lds32(wB + qo + 16);
#pragma unroll
                for (int mt = 0; mt < 2; ++mt)
                    mma16816(acc[mt][nt][0], acc[mt][nt][1], acc[mt][nt][2], acc[mt][nt][3],
                             aF[mt][0], aF[mt][1], aF[mt][2], aF[mt][3], w0, w1);
            }
        }
        __syncthreads();
    }

    if (z < 2) {
        // ---- epilogue: bias + RoPE -> f16 [m][D]
        __half* dst16 = (z == 0) ? q16 : k16;
#pragma unroll
        for (int mt = 0; mt < 2; ++mt) {
#pragma unroll
            for (int nt = 0; nt < 4; ++nt) {
                const int dl = bn * 64 + wn * 32 + nt * 8 + tig * 2;
                const int du = dl + 512;
                const float bl0 = bias[dl], bl1 = bias[dl + 1];
                const float bu0 = bias[du], bu1 = bias[du + 1];
#pragma unroll
                for (int rr = 0; rr < 2; ++rr) {
                    const int m = bm + wm * 32 + mt * 16 + group + rr * 8;
                    const int sq = m & (S_SZ - 1);
                    const float xl0 = acc[mt][nt][2 * rr]     + bl0;
                    const float xl1 = acc[mt][nt][2 * rr + 1] + bl1;
                    const float xu0 = acc[mt][nt + 4][2 * rr]     + bu0;
                    const float xu1 = acc[mt][nt + 4][2 * rr + 1] + bu1;
                    const float2 cl = *(const float2*)(ct + (size_t)sq * D_SZ + dl);
                    const float2 sl = *(const float2*)(st + (size_t)sq * D_SZ + dl);
                    const float2 cu = *(const float2*)(ct + (size_t)sq * D_SZ + du);
                    const float2 su = *(const float2*)(st + (size_t)sq * D_SZ + du);
                    const float ol0 = xl0 * cl.x - xu0 * sl.x;
                    const float ol1 = xl1 * cl.y - xu1 * sl.y;
                    const float ou0 = xu0 * cu.x + xl0 * su.x;
                    const float ou1 = xu1 * cu.y + xl1 * su.y;
                    *(uint32_t*)(dst16 + (size_t)m * D_SZ + dl) = pack_f16(ol0, ol1);
                    *(uint32_t*)(dst16 + (size_t)m * D_SZ + du) = pack_f16(ou0, ou1);
                }
            }
        }
    } else {
        // ---- epilogue: bias + transpose -> vt16[(b*16+h)*64+dk][s]
        __half* sv = (__half*)smc;
#pragma unroll
        for (int mt = 0; mt < 2; ++mt) {
#pragma unroll
            for (int nt = 0; nt < 8; ++nt) {
                const int c = wn * 64 + nt * 8 + tig * 2;
                const float b0 = bias[bn * 128 + c], b1 = bias[bn * 128 + c + 1];
                const int m0 = wm * 32 + mt * 16 + group;
                sv[(c)     * VPAD + m0]     = __float2half_rn(acc[mt][nt][0] + b0);
                sv[(c + 1) * VPAD + m0]     = __float2half_rn(acc[mt][nt][1] + b1);
                sv[(c)     * VPAD + m0 + 8] = __float2half_rn(acc[mt][nt][2] + b0);
                sv[(c + 1) * VPAD + m0 + 8] = __float2half_rn(acc[mt][nt][3] + b1);
            }
        }
        __syncthreads();
        const int b = bm >> 10;
        const int sbase = bm & (S_SZ - 1);
#pragma unroll
        for (int it = 0; it < 8; ++it) {
            const int idx = tid + it * 256;
            const int n = idx >> 4, seg = idx & 15;
            uint4 vv = *(const uint4*)(sv + n * VPAD + seg * 8);
            const int dg = bn * 128 + n;
            const int h = dg >> 6, dk = dg & 63;
            *(uint4*)(vt16 + ((size_t)((b * 16 + h) * 64 + dk)) * S_SZ + sbase + seg * 8) = vv;
        }
    }
}

// ---------------------------------------------------------------------------
// Output GEMM: f16 A (att16) x f16 W -> fp32 out + bias. Pure cp.async.
// ---------------------------------------------------------------------------
__global__ __launch_bounds__(256, 2) void gemm_out(
    const __half* __restrict__ A16, const __half* __restrict__ W,
    const float* __restrict__ bias, float* __restrict__ C)
{
    extern __shared__ char smc[];
    const uint32_t sb = smem_u32(smc);

    const int tid = threadIdx.x;
    const int wid = tid >> 5, lane = tid & 31;
    const int group = lane >> 2, tig = lane & 3;
    const int wm = wid & 3, wn = wid >> 2;
    const int bm = blockIdx.y * 128;
    const int bn = blockIdx.x * 128;

    float acc[2][8][4];
#pragma unroll
    for (int i = 0; i < 2; i++)
#pragma unroll
        for (int j = 0; j < 8; j++)
#pragma unroll
            for (int r = 0; r < 4; r++) acc[i][j][r] = 0.f;

    auto cpAW = [&](int c, int s) {
        const int k0 = c * 32;
#pragma unroll
        for (int it = 0; it < 4; ++it) {
            int idx = tid + (it & 1) * 256;
            int r = idx >> 2;
            int c4 = idx & 3;
            const __half* src;
            uint32_t dst;
            if (it < 2) {
                src = A16 + (size_t)(bm + r) * D_SZ + k0 + c4 * 8;
                dst = sb + (uint32_t)s * GTILEB;
            } else {
                src = W + (size_t)(bn + r) * D_SZ + k0 + c4 * 8;
                dst = sb + 2u * GTILEB + (uint32_t)s * GTILEB;
            }
            cp_async16(dst + (uint32_t)((r * GPAD + c4 * 8) * 2), src);
        }
    };

    cpAW(0, 0);
    CP_COMMIT();

    for (int c = 0; c < D_SZ / 32; ++c) {
        const int s = c & 1;
        if (c + 1 < D_SZ / 32) { cpAW(c + 1, s ^ 1); CP_COMMIT(); CP_WAIT(1); }
        else CP_WAIT(0);
        __syncthreads();

        const uint32_t aB = sb + (uint32_t)s * GTILEB;
        const uint32_t wB = sb + 2u * GTILEB + (uint32_t)s * GTILEB;
#pragma unroll
        for (int ks = 0; ks < 2; ++ks) {
            const int kk = ks * 16 + tig * 2;
            uint32_t aF[2][4];
#pragma unroll
            for (int mt = 0; mt < 2; ++mt) {
                const int r0 = wm * 32 + mt * 16 + group;
                const uint32_t p = (uint32_t)((r0 * GPAD + kk) * 2);
                const uint32_t p8 = (uint32_t)(((r0 + 8) * GPAD + kk) * 2);
                aF[mt][0] = lds32(aB + p);  aF[mt][1] = lds32(aB + p8);
                aF[mt][2] = lds32(aB + p + 16); aF[mt][3] = lds32(aB + p8 + 16);
            }
#pragma unroll
            for (int nt = 0; nt < 8; ++nt) {
                const int nr = wn * 64 + nt * 8 + group;
                const uint32_t qo = (uint32_t)((nr * GPAD + kk) * 2);
                uint32_t w0 = lds32(wB + qo), w1 = lds32(wB + qo + 16);
#pragma unroll
                for (int mt = 0; mt < 2; ++mt)
                    mma16816(acc[mt][nt][0], acc[mt][nt][1], acc[mt][nt][2], acc[mt][nt][3],
                             aF[mt][0], aF[mt][1], aF[mt][2], aF[mt][3], w0, w1);
            }
        }
        __syncthreads();
    }

#pragma unroll
    for (int mt = 0; mt < 2; ++mt) {
        const int m0 = bm + wm * 32 + mt * 16 + group;
#pragma unroll
        for (int nt = 0; nt < 8; ++nt) {
            const int col = bn + wn * 64 + nt * 8 + tig * 2;
            const float bx = bias[col], by = bias[col + 1];
            *(float2*)(C + (size_t)m0 * D_SZ + col) =
                make_float2(acc[mt][nt][0] + bx, acc[mt][nt][1] + by);
            *(float2*)(C + (size_t)(m0 + 8) * D_SZ + col) =
                make_float2(acc[mt][nt][2] + bx, acc[mt][nt][3] + by);
        }
    }
}

// ---------------------------------------------------------------------------
// Flash attention on mma.sync f16. One block = one (b,h) x 64 query rows.
// Writes f16 att16 [m][D] (concat layout).
// ---------------------------------------------------------------------------
#define APAD 72
#define ATILEB (64 * APAD * 2)               /* 9216 */
#define ATTN_SMEM_BYTES (4 * ATILEB)         /* 36864 */

__global__ __launch_bounds__(128, 3) void attn_mma(
    const __half* __restrict__ q16_, const __half* __restrict__ k16_,
    const __half* __restrict__ vt16_,
    const float* __restrict__ mask, const float* __restrict__ prior_bias,
    __half* __restrict__ out16)
{
    extern __shared__ char asm_[];
    const uint32_t sb = smem_u32(asm_);

    const int tid = threadIdx.x;
    const int wid = tid >> 5, lane = tid & 31;
    const int group = lane >> 2, tig = lane & 3;
    const int bh = blockIdx.y, b = bh >> 4, h = bh & 15;
    const int q0 = blockIdx.x * 64;

    const float LOG2E = 1.4426950408889634f;
    float sig = 1.0f / (1.0f + __expf(-prior_bias[h]));
    sig *= LOG2E;
    const float scale = 0.125f * LOG2E;

    uint32_t qh[4][4];
    const int r0 = wid * 16 + group;
    {
        const size_t rowa = (size_t)(b * S_SZ + q0 + r0) * D_SZ + h * DK_SZ;
        const size_t rowb = rowa + 8 * D_SZ;
#pragma unroll
        for (int ks = 0; ks < 4; ++ks) {
            const int d0 = ks * 16 + tig * 2;
            qh[ks][0] = *(const uint32_t*)(q16_ + rowa + d0);
            qh[ks][1] = *(const uint32_t*)(q16_ + rowb + d0);
            qh[ks][2] = *(const uint32_t*)(q16_ + rowa + d0 + 8);
            qh[ks][3] = *(const uint32_t*)(q16_ + rowb + d0 + 8);
        }
    }

    auto stage = [&](int kt, int s) {
        const int k0 = kt * 64;
#pragma unroll
        for (int it = 0; it < 8; ++it) {
            const int tile = it >> 2;                       // 0 k, 1 vt
            const int idx = (it & 3) * 128 + tid;
            const int r = idx >> 3, c8 = idx & 7;
            const __half* src;
            uint32_t dst;
            if (tile == 0) {
                src = k16_ + (size_t)(b * S_SZ + k0 + r) * D_SZ + h * DK_SZ + c8 * 8;
                dst = sb + (uint32_t)(s * ATILEB);
            } else {
                src = vt16_ + (size_t)(bh * 64 + r) * S_SZ + k0 + c8 * 8;
                dst = sb + 18432u + (uint32_t)(s * ATILEB);
            }
            cp_async16(dst + (uint32_t)((r * APAD + c8 * 8) * 2), src);
        }
    };

    float o[8][4];
#pragma unroll
    for (int i = 0; i < 8; i++)
#pragma unroll
        for (int j = 0; j < 4; j++) o[i][j] = 0.f;
    float m0 = -1e30f, m1 = -1e30f, l0 = 0.f, l1 = 0.f;
    const float qr0f = (float)(q0 + r0);
    const float qr1f = qr0f + 8.f;

    stage(0, 0);
    CP_COMMIT();

    for (int kt = 0; kt < S_SZ / 64; ++kt) {
        const int s = kt & 1;
        const int k0 = kt * 64;
        if (kt + 1 < S_SZ / 64) { stage(kt + 1, s ^ 1); CP_COMMIT(); CP_WAIT(1); }
        else CP_WAIT(0);
        __syncthreads();

        const uint32_t kB = sb + (uint32_t)(s * ATILEB);
        const uint32_t vB = sb + 18432u + (uint32_t)(s * ATILEB);

        float sc[8][4];
#pragma unroll
        for (int i = 0; i < 8; i++)
#pragma unroll
            for (int j = 0; j < 4; j++) sc[i][j] = 0.f;
#pragma unroll
        for (int ks = 0; ks < 4; ++ks) {
            const int d0 = ks * 16 + tig * 2;
#pragma unroll
            for (int nt = 0; nt < 8; ++nt) {
                const int kn = nt * 8 + group;
                const uint32_t po = (uint32_t)((kn * APAD + d0) * 2);
                uint32_t b0 = lds32(kB + po), b1 = lds32(kB + po + 16);
                mma16816(sc[nt][0], sc[nt][1], sc[nt][2], sc[nt][3],
                         qh[ks][0], qh[ks][1], qh[ks][2], qh[ks][3], b0, b1);
            }
        }

        float mx0 = -1e30f, mx1 = -1e30f;
#pragma unroll
        for (int nt = 0; nt < 8; ++nt) {
            const int kl = nt * 8 + tig * 2;
            const float kf0 = (float)(k0 + kl), kf1 = kf0 + 1.f;
            const float mk0 = __ldg(mask + b * S_SZ + k0 + kl) * LOG2E;
            const float mk1 = __ldg(mask + b * S_SZ + k0 + kl + 1) * LOG2E;
            sc[nt][0] = sc[nt][0] * scale + mk0 - sig * fabsf(qr0f - kf0);
            sc[nt][1] = sc[nt][1] * scale + mk1 - sig * fabsf(qr0f - kf1);
            sc[nt][2] = sc[nt][2] * scale + mk0 - sig * fabsf(qr1f - kf0);
            sc[nt][3] = sc[nt][3] * scale + mk1 - sig * fabsf(qr1f - kf1);
            mx0 = fmaxf(mx0, fmaxf(sc[nt][0], sc[nt][1]));
            mx1 = fmaxf(mx1, fmaxf(sc[nt][2], sc[nt][3]));
        }
        mx0 = fmaxf(mx0, __shfl_xor_sync(0xffffffffu, mx0, 1));
        mx0 = fmaxf(mx0, __shfl_xor_sync(0xffffffffu, mx0, 2));
        mx1 = fmaxf(mx1, __shfl_xor_sync(0xffffffffu, mx1, 1));
        mx1 = fmaxf(mx1, __shfl_xor_sync(0xffffffffu, mx1, 2));
        const float nm0 = fmaxf(m0, mx0), nm1 = fmaxf(m1, mx1);
        const float a0 = ex2f(m0 - nm0), a1 = ex2f(m1 - nm1);
        m0 = nm0; m1 = nm1;

        float sum0 = 0.f, sum1 = 0.f;
#pragma unroll
        for (int nt = 0; nt < 8; ++nt) {
            sc[nt][0] = ex2f(sc[nt][0] - m0);
            sc[nt][1] = ex2f(sc[nt][1] - m0);
            sc[nt][2] = ex2f(sc[nt][2] - m1);
            sc[nt][3] = ex2f(sc[nt][3] - m1);
            sum0 += sc[nt][0] + sc[nt][1];
            sum1 += sc[nt][2] + sc[nt][3];
        }
        sum0 += __shfl_xor_sync(0xffffffffu, sum0, 1);
        sum0 += __shfl_xor_sync(0xffffffffu, sum0, 2);
        sum1 += __shfl_xor_sync(0xffffffffu, sum1, 1);
        sum1 += __shfl_xor_sync(0xffffffffu, sum1, 2);
        l0 = l0 * a0 + sum0;
        l1 = l1 * a1 + sum1;
#pragma unroll
        for (int nt = 0; nt < 8; ++nt) {
            o[nt][0] *= a0; o[nt][1] *= a0;
            o[nt][2] *= a1; o[nt][3] *= a1;
        }

        uint32_t pa[4][4];
#pragma unroll
        for (int ks = 0; ks < 4; ++ks) {
            pa[ks][0] = pack_f16(sc[2 * ks][0], sc[2 * ks][1]);
            pa[ks][1] = pack_f16(sc[2 * ks][2], sc[2 * ks][3]);
            pa[ks][2] = pack_f16(sc[2 * ks + 1][0], sc[2 * ks + 1][1]);
            pa[ks][3] = pack_f16(sc[2 * ks + 1][2], sc[2 * ks + 1][3]);
        }
#pragma unroll
        for (int ks = 0; ks < 4; ++ks) {
            const int kk = ks * 16 + tig * 2;
#pragma unroll
            for (int nt = 0; nt < 8; ++nt) {
                const int dn = nt * 8 + group;
                const uint32_t po = (uint32_t)((dn * APAD + kk) * 2);
                uint32_t b0 = lds32(vB + po), b1 = lds32(vB + po + 16);
                mma16816(o[nt][0], o[nt][1], o[nt][2], o[nt][3],
                         pa[ks][0], pa[ks][1], pa[ks][2], pa[ks][3], b0, b1);
            }
        }
        __syncthreads();
    }

    const float inv0 = 1.0f / l0, inv1 = 1.0f / l1;
    const int gr0 = b * S_SZ + q0 + r0;
#pragma unroll
    for (int nt = 0; nt < 8; ++nt) {
        const int col = h * DK_SZ + nt * 8 + tig * 2;
        *(uint32_t*)(out16 + (size_t)gr0 * D_SZ + col) =
            pack_f16(o[nt][0] * inv0, o[nt][1] * inv0);
        *(uint32_t*)(out16 + (size_t)(gr0 + 8) * D_SZ + col) =
            pack_f16(o[nt][2] * inv1, o[nt][3] * inv1);
    }
}

// ---------------------------------------------------------------------------
extern "C" void kernel_launch(void* const* d_in, const int* in_sizes, int n_in,
                              void* d_out, int out_size)
{
    const float* q     = (const float*)d_in[0];
    const float* k     = (const float*)d_in[1];
    const float* v     = (const float*)d_in[2];
    const float* cosp  = (const float*)d_in[3];
    const float* sinp  = (const float*)d_in[4];
    const float* maskp = (const float*)d_in[5];
    // d_in[6] = short_matrix (analytic: -|i-j|)
    const float* Wq = (const float*)d_in[7];
    const float* bq = (const float*)d_in[8];
    const float* Wk = (const float*)d_in[9];
    const float* bk = (const float*)d_in[10];
    const float* Wv = (const float*)d_in[11];
    const float* bv = (const float*)d_in[12];
    const float* Wo = (const float*)d_in[13];
    const float* bo = (const float*)d_in[14];
    const float* apb = (const float*)d_in[15];

    __half *w16, *q16, *k16, *vt16, *att16;
    cudaGetSymbolAddress((void**)&w16,   g_w16);
    cudaGetSymbolAddress((void**)&q16,   g_q16);
    cudaGetSymbolAddress((void**)&k16,   g_k16);
    cudaGetSymbolAddress((void**)&vt16,  g_vt16);
    cudaGetSymbolAddress((void**)&att16, g_att16);

    cudaFuncSetAttribute(qkv_gemm, cudaFuncAttributeMaxDynamicSharedMemorySize,
                         GEMM_SMEM_BYTES);
    cudaFuncSetAttribute(gemm_out, cudaFuncAttributeMaxDynamicSharedMemorySize,
                         GEMM_SMEM_BYTES);
    cudaFuncSetAttribute(attn_mma, cudaFuncAttributeMaxDynamicSharedMemorySize,
                         ATTN_SMEM_BYTES);

    cvt_f16<<<WN / 1024, 256>>>(Wq, w16 + 0 * (size_t)WN);
    cvt_f16<<<WN / 1024, 256>>>(Wk, w16 + 1 * (size_t)WN);
    cvt_f16<<<WN / 1024, 256>>>(Wv, w16 + 2 * (size_t)WN);
    cvt_f16<<<WN / 1024, 256>>>(Wo, w16 + 3 * (size_t)WN);

    qkv_gemm<<<dim3(8, 64, 3), 256, GEMM_SMEM_BYTES>>>(
        q, k, v, w16, bq, bk, bv, cosp, sinp, q16, k16, vt16);

    attn_mma<<<dim3(S_SZ / 64, B_SZ * H_SZ), 128, ATTN_SMEM_BYTES>>>(
        q16, k16, vt16, maskp, apb, att16);

    gemm_out<<<dim3(8, 64), 256, GEMM_SMEM_BYTES>>>(
        att16, w16 + 3 * (size_t)WN, bo, (float*)d_out);
}

// round 9
// speedup vs baseline: 8.2169x; 1.0487x over previous
#include <cuda_runtime.h>
#include <cuda_fp16.h>
#include <math_constants.h>
#include <cstdint>
#include <cstddef>

#define B_SZ 8
#define S_SZ 1024
#define D_SZ 1024
#define H_SZ 16
#define DK_SZ 64
#define MROWS (B_SZ * S_SZ)   /* 8192 */
#define WN (D_SZ * D_SZ)

// ---------------------------------------------------------------------------
// Scratch (allocation-free rule: __device__ globals)
// ---------------------------------------------------------------------------
__device__ __half g_w16[4][WN];
__device__ __half g_q16[MROWS * D_SZ];
__device__ __half g_k16[MROWS * D_SZ];
__device__ __half g_vt16[MROWS * D_SZ];   // [b*h][d][s]
__device__ __half g_att16[MROWS * D_SZ];

// ---------------------------------------------------------------------------
__device__ __forceinline__ uint32_t smem_u32(const void* p) {
    uint32_t a;
    asm("{ .reg .u64 t; cvta.to.shared.u64 t, %1; cvt.u32.u64 %0, t; }"
        : "=r"(a) : "l"(p));
    return a;
}
__device__ __forceinline__ void cp_async16(uint32_t dst, const void* src) {
    asm volatile("cp.async.cg.shared.global [%0], [%1], 16;\n"
                 :: "r"(dst), "l"(src) : "memory");
}
#define CP_COMMIT() asm volatile("cp.async.commit_group;\n" ::: "memory")
#define CP_WAIT(n)  asm volatile("cp.async.wait_group %0;\n" :: "n"(n) : "memory")

__device__ __forceinline__ void ldsm_x4(uint32_t& r0, uint32_t& r1,
                                        uint32_t& r2, uint32_t& r3, uint32_t a) {
    asm volatile("ldmatrix.sync.aligned.m8n8.x4.shared.b16 {%0,%1,%2,%3}, [%4];"
                 : "=r"(r0), "=r"(r1), "=r"(r2), "=r"(r3) : "r"(a));
}
__device__ __forceinline__ void mma16816(
    float& d0, float& d1, float& d2, float& d3,
    uint32_t a0, uint32_t a1, uint32_t a2, uint32_t a3,
    uint32_t b0, uint32_t b1)
{
    asm volatile(
        "mma.sync.aligned.m16n8k16.row.col.f32.f16.f16.f32 "
        "{%0,%1,%2,%3}, {%4,%5,%6,%7}, {%8,%9}, {%0,%1,%2,%3};\n"
        : "+f"(d0), "+f"(d1), "+f"(d2), "+f"(d3)
        : "r"(a0), "r"(a1), "r"(a2), "r"(a3), "r"(b0), "r"(b1));
}
// pack two f32 -> f16x2 reg: low half = first arg
__device__ __forceinline__ uint32_t pack_f16(float lo, float hi) {
    uint32_t r;
    asm("cvt.rn.f16x2.f32 %0, %1, %2;" : "=r"(r) : "f"(hi), "f"(lo));
    return r;
}
__device__ __forceinline__ float ex2f(float x) {
    float y; asm("ex2.approx.ftz.f32 %0, %1;" : "=f"(y) : "f"(x)); return y;
}

// ---------------------------------------------------------------------------
// fp32 -> f16, all 4 weights in one launch
// ---------------------------------------------------------------------------
__global__ __launch_bounds__(256) void cvt_f16_all(
    const float* __restrict__ w0, const float* __restrict__ w1,
    const float* __restrict__ w2, const float* __restrict__ w3,
    __half* __restrict__ y)
{
    const int z = blockIdx.y;
    const float* x = (z == 0) ? w0 : (z == 1) ? w1 : (z == 2) ? w2 : w3;
    int i = blockIdx.x * blockDim.x + threadIdx.x;
    float4 v = ((const float4*)x)[i];
    ((uint2*)(y + (size_t)z * WN))[i] =
        make_uint2(pack_f16(v.x, v.y), pack_f16(v.z, v.w));
}

// ---------------------------------------------------------------------------
// Fused QKV projection GEMM (see round-8 header for layout docs).
// z=0/1: Q/K proj, paired-N tile, epilogue bias+RoPE -> q16/k16
// z=2:   V proj, epilogue bias + smem transpose -> vt16
// ---------------------------------------------------------------------------
#define GPAD 40
#define GTILEB (128 * GPAD * 2)             /* 10240 bytes per tile */
#define GEMM_SMEM_BYTES 40960               /* A x2, W x2 */
#define VPAD 136

__global__ __launch_bounds__(256, 2) void qkv_gemm(
    const float* __restrict__ q, const float* __restrict__ k,
    const float* __restrict__ v, const __half* __restrict__ w16,
    const float* __restrict__ bq, const float* __restrict__ bk,
    const float* __restrict__ bv,
    const float* __restrict__ ct, const float* __restrict__ st,
    __half* __restrict__ q16, __half* __restrict__ k16,
    __half* __restrict__ vt16)
{
    extern __shared__ char smc[];
    const uint32_t sb = smem_u32(smc);

    const int tid = threadIdx.x;
    const int wid = tid >> 5, lane = tid & 31;
    const int group = lane >> 2, tig = lane & 3;
    const int wm = wid & 3, wn = wid >> 2;
    const int bn = blockIdx.x;
    const int bm = blockIdx.y * 128;
    const int z = blockIdx.z;

    const float* A = (z == 0) ? q : (z == 1) ? k : v;
    const __half* W = w16 + (size_t)z * WN;
    const float* bias = (z == 0) ? bq : (z == 1) ? bk : bv;

    // ldmatrix lane offsets (bytes)
    const uint32_t aln = (uint32_t)((((lane & 7) + ((lane >> 3) & 1) * 8) * GPAD
                                    + (lane >> 4) * 8) * 2);
    const uint32_t bln = (uint32_t)((((lane & 7) + (lane >> 4) * 8) * GPAD
                                    + ((lane >> 3) & 1) * 8) * 2);

    float acc[2][8][4];
#pragma unroll
    for (int i = 0; i < 2; i++)
#pragma unroll
        for (int j = 0; j < 8; j++)
#pragma unroll
            for (int r = 0; r < 4; r++) acc[i][j][r] = 0.f;

    const int arow = tid >> 3, ac4 = tid & 7;
    float4 areg[4];

    auto ldgA = [&](int c) {
        const int k0 = c * 32;
#pragma unroll
        for (int it = 0; it < 4; ++it)
            areg[it] = *(const float4*)(A + (size_t)(bm + arow + it * 32) * D_SZ + k0 + ac4 * 4);
    };
    auto stsA = [&](int s) {
        const uint32_t aB = sb + (uint32_t)s * GTILEB;
#pragma unroll
        for (int it = 0; it < 4; ++it) {
            float4 vv = areg[it];
            uint32_t h01 = pack_f16(vv.x, vv.y);
            uint32_t h23 = pack_f16(vv.z, vv.w);
            uint32_t off = (uint32_t)(((arow + it * 32) * GPAD + ac4 * 4) * 2);
            asm volatile("st.shared.v2.b32 [%0], {%1, %2};" :: "r"(aB + off), "r"(h01), "r"(h23));
        }
    };
    auto cpW = [&](int c, int s) {
        const int k0 = c * 32;
#pragma unroll
        for (int it = 0; it < 2; ++it) {
            int idx = tid + it * 256;
            int r = idx >> 2;
            int c4 = idx & 3;
            int grow;
            if (z < 2) {
                int w = r & 63, wnr = r >> 6;
                grow = (w < 32) ? (bn * 64 + wnr * 32 + w)
                                : (512 + bn * 64 + wnr * 32 + (w - 32));
            } else {
                grow = bn * 128 + r;
            }
            const __half* src = W + (size_t)grow * D_SZ + k0 + c4 * 8;
            uint32_t dst = sb + 2u * GTILEB + (uint32_t)s * GTILEB
                         + (uint32_t)((r * GPAD + c4 * 8) * 2);
            cp_async16(dst, src);
        }
    };

    ldgA(0);
    cpW(0, 0);
    CP_COMMIT();

    for (int c = 0; c < D_SZ / 32; ++c) {
        const int s = c & 1;
        if (c + 1 < D_SZ / 32) { cpW(c + 1, s ^ 1); CP_COMMIT(); CP_WAIT(1); }
        else CP_WAIT(0);
        stsA(s);
        __syncthreads();
        if (c + 1 < D_SZ / 32) ldgA(c + 1);

        const uint32_t aB = sb + (uint32_t)s * GTILEB;
        const uint32_t wB = sb + 2u * GTILEB + (uint32_t)s * GTILEB;
#pragma unroll
        for (int ks = 0; ks < 2; ++ks) {
            uint32_t aF[2][4];
#pragma unroll
            for (int mt = 0; mt < 2; ++mt)
                ldsm_x4(aF[mt][0], aF[mt][1], aF[mt][2], aF[mt][3],
                        aB + (uint32_t)(((wm * 32 + mt * 16) * GPAD + ks * 16) * 2) + aln);
#pragma unroll
            for (int np = 0; np < 4; ++np) {
                uint32_t b0, b1, b2, b3;
                ldsm_x4(b0, b1, b2, b3,
                        wB + (uint32_t)(((wn * 64 + np * 16) * GPAD + ks * 16) * 2) + bln);
#pragma unroll
                for (int mt = 0; mt < 2; ++mt) {
                    mma16816(acc[mt][2 * np][0], acc[mt][2 * np][1],
                             acc[mt][2 * np][2], acc[mt][2 * np][3],
                             aF[mt][0], aF[mt][1], aF[mt][2], aF[mt][3], b0, b1);
                    mma16816(acc[mt][2 * np + 1][0], acc[mt][2 * np + 1][1],
                             acc[mt][2 * np + 1][2], acc[mt][2 * np + 1][3],
                             aF[mt][0], aF[mt][1], aF[mt][2], aF[mt][3], b2, b3);
                }
            }
        }
        __syncthreads();
    }

    if (z < 2) {
        // ---- epilogue: bias + RoPE -> f16 [m][D]
        __half* dst16 = (z == 0) ? q16 : k16;
#pragma unroll
        for (int mt = 0; mt < 2; ++mt) {
#pragma unroll
            for (int nt = 0; nt < 4; ++nt) {
                const int dl = bn * 64 + wn * 32 + nt * 8 + tig * 2;
                const int du = dl + 512;
                const float bl0 = bias[dl], bl1 = bias[dl + 1];
                const float bu0 = bias[du], bu1 = bias[du + 1];
#pragma unroll
                for (int rr = 0; rr < 2; ++rr) {
                    const int m = bm + wm * 32 + mt * 16 + group + rr * 8;
                    const int sq = m & (S_SZ - 1);
                    const float xl0 = acc[mt][nt][2 * rr]     + bl0;
                    const float xl1 = acc[mt][nt][2 * rr + 1] + bl1;
                    const float xu0 = acc[mt][nt + 4][2 * rr]     + bu0;
                    const float xu1 = acc[mt][nt + 4][2 * rr + 1] + bu1;
                    const float2 cl = *(const float2*)(ct + (size_t)sq * D_SZ + dl);
                    const float2 sl = *(const float2*)(st + (size_t)sq * D_SZ + dl);
                    const float2 cu = *(const float2*)(ct + (size_t)sq * D_SZ + du);
                    const float2 su = *(const float2*)(st + (size_t)sq * D_SZ + du);
                    const float ol0 = xl0 * cl.x - xu0 * sl.x;
                    const float ol1 = xl1 * cl.y - xu1 * sl.y;
                    const float ou0 = xu0 * cu.x + xl0 * su.x;
                    const float ou1 = xu1 * cu.y + xl1 * su.y;
                    *(uint32_t*)(dst16 + (size_t)m * D_SZ + dl) = pack_f16(ol0, ol1);
                    *(uint32_t*)(dst16 + (size_t)m * D_SZ + du) = pack_f16(ou0, ou1);
                }
            }
        }
    } else {
        // ---- epilogue: bias + transpose -> vt16[(b*16+h)*64+dk][s]
        __half* sv = (__half*)smc;
#pragma unroll
        for (int mt = 0; mt < 2; ++mt) {
#pragma unroll
            for (int nt = 0; nt < 8; ++nt) {
                const int c = wn * 64 + nt * 8 + tig * 2;
                const float b0 = bias[bn * 128 + c], b1 = bias[bn * 128 + c + 1];
                const int m0 = wm * 32 + mt * 16 + group;
                sv[(c)     * VPAD + m0]     = __float2half_rn(acc[mt][nt][0] + b0);
                sv[(c + 1) * VPAD + m0]     = __float2half_rn(acc[mt][nt][1] + b1);
                sv[(c)     * VPAD + m0 + 8] = __float2half_rn(acc[mt][nt][2] + b0);
                sv[(c + 1) * VPAD + m0 + 8] = __float2half_rn(acc[mt][nt][3] + b1);
            }
        }
        __syncthreads();
        const int b = bm >> 10;
        const int sbase = bm & (S_SZ - 1);
#pragma unroll
        for (int it = 0; it < 8; ++it) {
            const int idx = tid + it * 256;
            const int n = idx >> 4, seg = idx & 15;
            uint4 vv = *(const uint4*)(sv + n * VPAD + seg * 8);
            const int dg = bn * 128 + n;
            const int h = dg >> 6, dk = dg & 63;
            *(uint4*)(vt16 + ((size_t)((b * 16 + h) * 64 + dk)) * S_SZ + sbase + seg * 8) = vv;
        }
    }
}

// ---------------------------------------------------------------------------
// Output GEMM: f16 A (att16) x f16 W -> fp32 out + bias. Pure cp.async.
// ---------------------------------------------------------------------------
__global__ __launch_bounds__(256, 2) void gemm_out(
    const __half* __restrict__ A16, const __half* __restrict__ W,
    const float* __restrict__ bias, float* __restrict__ C)
{
    extern __shared__ char smc[];
    const uint32_t sb = smem_u32(smc);

    const int tid = threadIdx.x;
    const int wid = tid >> 5, lane = tid & 31;
    const int group = lane >> 2, tig = lane & 3;
    const int wm = wid & 3, wn = wid >> 2;
    const int bm = blockIdx.y * 128;
    const int bn = blockIdx.x * 128;

    const uint32_t aln = (uint32_t)((((lane & 7) + ((lane >> 3) & 1) * 8) * GPAD
                                    + (lane >> 4) * 8) * 2);
    const uint32_t bln = (uint32_t)((((lane & 7) + (lane >> 4) * 8) * GPAD
                                    + ((lane >> 3) & 1) * 8) * 2);

    float acc[2][8][4];
#pragma unroll
    for (int i = 0; i < 2; i++)
#pragma unroll
        for (int j = 0; j < 8; j++)
#pragma unroll
            for (int r = 0; r < 4; r++) acc[i][j][r] = 0.f;

    auto cpAW = [&](int c, int s) {
        const int k0 = c * 32;
#pragma unroll
        for (int it = 0; it < 4; ++it) {
            int idx = tid + (it & 1) * 256;
            int r = idx >> 2;
            int c4 = idx & 3;
            const __half* src;
            uint32_t dst;
            if (it < 2) {
                src = A16 + (size_t)(bm + r) * D_SZ + k0 + c4 * 8;
                dst = sb + (uint32_t)s * GTILEB;
            } else {
                src = W + (size_t)(bn + r) * D_SZ + k0 + c4 * 8;
                dst = sb + 2u * GTILEB + (uint32_t)s * GTILEB;
            }
            cp_async16(dst + (uint32_t)((r * GPAD + c4 * 8) * 2), src);
        }
    };

    cpAW(0, 0);
    CP_COMMIT();

    for (int c = 0; c < D_SZ / 32; ++c) {
        const int s = c & 1;
        if (c + 1 < D_SZ / 32) { cpAW(c + 1, s ^ 1); CP_COMMIT(); CP_WAIT(1); }
        else CP_WAIT(0);
        __syncthreads();

        const uint32_t aB = sb + (uint32_t)s * GTILEB;
        const uint32_t wB = sb + 2u * GTILEB + (uint32_t)s * GTILEB;
#pragma unroll
        for (int ks = 0; ks < 2; ++ks) {
            uint32_t aF[2][4];
#pragma unroll
            for (int mt = 0; mt < 2; ++mt)
                ldsm_x4(aF[mt][0], aF[mt][1], aF[mt][2], aF[mt][3],
                        aB + (uint32_t)(((wm * 32 + mt * 16) * GPAD + ks * 16) * 2) + aln);
#pragma unroll
            for (int np = 0; np < 4; ++np) {
                uint32_t b0, b1, b2, b3;
                ldsm_x4(b0, b1, b2, b3,
                        wB + (uint32_t)(((wn * 64 + np * 16) * GPAD + ks * 16) * 2) + bln);
#pragma unroll
                for (int mt = 0; mt < 2; ++mt) {
                    mma16816(acc[mt][2 * np][0], acc[mt][2 * np][1],
                             acc[mt][2 * np][2], acc[mt][2 * np][3],
                             aF[mt][0], aF[mt][1], aF[mt][2], aF[mt][3], b0, b1);
                    mma16816(acc[mt][2 * np + 1][0], acc[mt][2 * np + 1][1],
                             acc[mt][2 * np + 1][2], acc[mt][2 * np + 1][3],
                             aF[mt][0], aF[mt][1], aF[mt][2], aF[mt][3], b2, b3);
                }
            }
        }
        __syncthreads();
    }

#pragma unroll
    for (int mt = 0; mt < 2; ++mt) {
        const int m0 = bm + wm * 32 + mt * 16 + group;
#pragma unroll
        for (int nt = 0; nt < 8; ++nt) {
            const int col = bn + wn * 64 + nt * 8 + tig * 2;
            const float bx = bias[col], by = bias[col + 1];
            *(float2*)(C + (size_t)m0 * D_SZ + col) =
                make_float2(acc[mt][nt][0] + bx, acc[mt][nt][1] + by);
            *(float2*)(C + (size_t)(m0 + 8) * D_SZ + col) =
                make_float2(acc[mt][nt][2] + bx, acc[mt][nt][3] + by);
        }
    }
}

// ---------------------------------------------------------------------------
// Flash attention on mma.sync f16, ldmatrix fragment loads.
// One block = one (b,h) x 64 query rows. Writes f16 att16 [m][D].
// ---------------------------------------------------------------------------
#define APAD 72
#define ATILEB (64 * APAD * 2)               /* 9216 */
#define ATTN_SMEM_BYTES (4 * ATILEB)         /* 36864 */

__global__ __launch_bounds__(128, 3) void attn_mma(
    const __half* __restrict__ q16_, const __half* __restrict__ k16_,
    const __half* __restrict__ vt16_,
    const float* __restrict__ mask, const float* __restrict__ prior_bias,
    __half* __restrict__ out16)
{
    extern __shared__ char asm_[];
    const uint32_t sb = smem_u32(asm_);

    const int tid = threadIdx.x;
    const int wid = tid >> 5, lane = tid & 31;
    const int group = lane >> 2, tig = lane & 3;
    const int bh = blockIdx.y, b = bh >> 4, h = bh & 15;
    const int q0 = blockIdx.x * 64;

    const uint32_t bln = (uint32_t)((((lane & 7) + (lane >> 4) * 8) * APAD
                                    + ((lane >> 3) & 1) * 8) * 2);

    const float LOG2E = 1.4426950408889634f;
    float sig = 1.0f / (1.0f + __expf(-prior_bias[h]));
    sig *= LOG2E;
    const float scale = 0.125f * LOG2E;

    uint32_t qh[4][4];
    const int r0 = wid * 16 + group;
    {
        const size_t rowa = (size_t)(b * S_SZ + q0 + r0) * D_SZ + h * DK_SZ;
        const size_t rowb = rowa + 8 * D_SZ;
#pragma unroll
        for (int ks = 0; ks < 4; ++ks) {
            const int d0 = ks * 16 + tig * 2;
            qh[ks][0] = *(const uint32_t*)(q16_ + rowa + d0);
            qh[ks][1] = *(const uint32_t*)(q16_ + rowb + d0);
            qh[ks][2] = *(const uint32_t*)(q16_ + rowa + d0 + 8);
            qh[ks][3] = *(const uint32_t*)(q16_ + rowb + d0 + 8);
        }
    }

    auto stage = [&](int kt, int s) {
        const int k0 = kt * 64;
#pragma unroll
        for (int it = 0; it < 8; ++it) {
            const int tile = it >> 2;                       // 0 k, 1 vt
            const int idx = (it & 3) * 128 + tid;
            const int r = idx >> 3, c8 = idx & 7;
            const __half* src;
            uint32_t dst;
            if (tile == 0) {
                src = k16_ + (size_t)(b * S_SZ + k0 + r) * D_SZ + h * DK_SZ + c8 * 8;
                dst = sb + (uint32_t)(s * ATILEB);
            } else {
                src = vt16_ + (size_t)(bh * 64 + r) * S_SZ + k0 + c8 * 8;
                dst = sb + 18432u + (uint32_t)(s * ATILEB);
            }
            cp_async16(dst + (uint32_t)((r * APAD + c8 * 8) * 2), src);
        }
    };

    float o[8][4];
#pragma unroll
    for (int i = 0; i < 8; i++)
#pragma unroll
        for (int j = 0; j < 4; j++) o[i][j] = 0.f;
    float m0 = -1e30f, m1 = -1e30f, l0 = 0.f, l1 = 0.f;
    const float qr0f = (float)(q0 + r0);
    const float qr1f = qr0f + 8.f;

    stage(0, 0);
    CP_COMMIT();

    for (int kt = 0; kt < S_SZ / 64; ++kt) {
        const int s = kt & 1;
        const int k0 = kt * 64;
        if (kt + 1 < S_SZ / 64) { stage(kt + 1, s ^ 1); CP_COMMIT(); CP_WAIT(1); }
        else CP_WAIT(0);
        __syncthreads();

        const uint32_t kB = sb + (uint32_t)(s * ATILEB);
        const uint32_t vB = sb + 18432u + (uint32_t)(s * ATILEB);

        float sc[8][4];
#pragma unroll
        for (int i = 0; i < 8; i++)
#pragma unroll
            for (int j = 0; j < 4; j++) sc[i][j] = 0.f;
#pragma unroll
        for (int ks = 0; ks < 4; ++ks) {
#pragma unroll
            for (int np = 0; np < 4; ++np) {
                uint32_t b0, b1, b2, b3;
                ldsm_x4(b0, b1, b2, b3,
                        kB + (uint32_t)(((np * 16) * APAD + ks * 16) * 2) + bln);
                mma16816(sc[2 * np][0], sc[2 * np][1], sc[2 * np][2], sc[2 * np][3],
                         qh[ks][0], qh[ks][1], qh[ks][2], qh[ks][3], b0, b1);
                mma16816(sc[2 * np + 1][0], sc[2 * np + 1][1],
                         sc[2 * np + 1][2], sc[2 * np + 1][3],
                         qh[ks][0], qh[ks][1], qh[ks][2], qh[ks][3], b2, b3);
            }
        }

        float mx0 = -1e30f, mx1 = -1e30f;
#pragma unroll
        for (int nt = 0; nt < 8; ++nt) {
            const int kl = nt * 8 + tig * 2;
            const float kf0 = (float)(k0 + kl), kf1 = kf0 + 1.f;
            const float mk0 = __ldg(mask + b * S_SZ + k0 + kl) * LOG2E;
            const float mk1 = __ldg(mask + b * S_SZ + k0 + kl + 1) * LOG2E;
            sc[nt][0] = sc[nt][0] * scale + mk0 - sig * fabsf(qr0f - kf0);
            sc[nt][1] = sc[nt][1] * scale + mk1 - sig * fabsf(qr0f - kf1);
            sc[nt][2] = sc[nt][2] * scale + mk0 - sig * fabsf(qr1f - kf0);
            sc[nt][3] = sc[nt][3] * scale + mk1 - sig * fabsf(qr1f - kf1);
            mx0 = fmaxf(mx0, fmaxf(sc[nt][0], sc[nt][1]));
            mx1 = fmaxf(mx1, fmaxf(sc[nt][2], sc[nt][3]));
        }
        mx0 = fmaxf(mx0, __shfl_xor_sync(0xffffffffu, mx0, 1));
        mx0 = fmaxf(mx0, __shfl_xor_sync(0xffffffffu, mx0, 2));
        mx1 = fmaxf(mx1, __shfl_xor_sync(0xffffffffu, mx1, 1));
        mx1 = fmaxf(mx1, __shfl_xor_sync(0xffffffffu, mx1, 2));
        const float nm0 = fmaxf(m0, mx0), nm1 = fmaxf(m1, mx1);
        const float a0 = ex2f(m0 - nm0), a1 = ex2f(m1 - nm1);
        m0 = nm0; m1 = nm1;

        float sum0 = 0.f, sum1 = 0.f;
#pragma unroll
        for (int nt = 0; nt < 8; ++nt) {
            sc[nt][0] = ex2f(sc[nt][0] - m0);
            sc[nt][1] = ex2f(sc[nt][1] - m0);
            sc[nt][2] = ex2f(sc[nt][2] - m1);
            sc[nt][3] = ex2f(sc[nt][3] - m1);
            sum0 += sc[nt][0] + sc[nt][1];
            sum1 += sc[nt][2] + sc[nt][3];
        }
        sum0 += __shfl_xor_sync(0xffffffffu, sum0, 1);
        sum0 += __shfl_xor_sync(0xffffffffu, sum0, 2);
        sum1 += __shfl_xor_sync(0xffffffffu, sum1, 1);
        sum1 += __shfl_xor_sync(0xffffffffu, sum1, 2);
        l0 = l0 * a0 + sum0;
        l1 = l1 * a1 + sum1;
#pragma unroll
        for (int nt = 0; nt < 8; ++nt) {
            o[nt][0] *= a0; o[nt][1] *= a0;
            o[nt][2] *= a1; o[nt][3] *= a1;
        }

        uint32_t pa[4][4];
#pragma unroll
        for (int ks = 0; ks < 4; ++ks) {
            pa[ks][0] = pack_f16(sc[2 * ks][0], sc[2 * ks][1]);
            pa[ks][1] = pack_f16(sc[2 * ks][2], sc[2 * ks][3]);
            pa[ks][2] = pack_f16(sc[2 * ks + 1][0], sc[2 * ks + 1][1]);
            pa[ks][3] = pack_f16(sc[2 * ks + 1][2], sc[2 * ks + 1][3]);
        }
#pragma unroll
        for (int ks = 0; ks < 4; ++ks) {
#pragma unroll
            for (int np = 0; np < 4; ++np) {
                uint32_t b0, b1, b2, b3;
                ldsm_x4(b0, b1, b2, b3,
                        vB + (uint32_t)(((np * 16) * APAD + ks * 16) * 2) + bln);
                mma16816(o[2 * np][0], o[2 * np][1], o[2 * np][2], o[2 * np][3],
                         pa[ks][0], pa[ks][1], pa[ks][2], pa[ks][3], b0, b1);
                mma16816(o[2 * np + 1][0], o[2 * np + 1][1],
                         o[2 * np + 1][2], o[2 * np + 1][3],
                         pa[ks][0], pa[ks][1], pa[ks][2], pa[ks][3], b2, b3);
            }
        }
        __syncthreads();
    }

    const float inv0 = 1.0f / l0, inv1 = 1.0f / l1;
    const int gr0 = b * S_SZ + q0 + r0;
#pragma unroll
    for (int nt = 0; nt < 8; ++nt) {
        const int col = h * DK_SZ + nt * 8 + tig * 2;
        *(uint32_t*)(out16 + (size_t)gr0 * D_SZ + col) =
            pack_f16(o[nt][0] * inv0, o[nt][1] * inv0);
        *(uint32_t*)(out16 + (size_t)(gr0 + 8) * D_SZ + col) =
            pack_f16(o[nt][2] * inv1, o[nt][3] * inv1);
    }
}

// ---------------------------------------------------------------------------
extern "C" void kernel_launch(void* const* d_in, const int* in_sizes, int n_in,
                              void* d_out, int out_size)
{
    const float* q     = (const float*)d_in[0];
    const float* k     = (const float*)d_in[1];
    const float* v     = (const float*)d_in[2];
    const float* cosp  = (const float*)d_in[3];
    const float* sinp  = (const float*)d_in[4];
    const float* maskp = (const float*)d_in[5];
    // d_in[6] = short_matrix (analytic: -|i-j|)
    const float* Wq = (const float*)d_in[7];
    const float* bq = (const float*)d_in[8];
    const float* Wk = (const float*)d_in[9];
    const float* bk = (const float*)d_in[10];
    const float* Wv = (const float*)d_in[11];
    const float* bv = (const float*)d_in[12];
    const float* Wo = (const float*)d_in[13];
    const float* bo = (const float*)d_in[14];
    const float* apb = (const float*)d_in[15];

    __half *w16, *q16, *k16, *vt16, *att16;
    cudaGetSymbolAddress((void**)&w16,   g_w16);
    cudaGetSymbolAddress((void**)&q16,   g_q16);
    cudaGetSymbolAddress((void**)&k16,   g_k16);
    cudaGetSymbolAddress((void**)&vt16,  g_vt16);
    cudaGetSymbolAddress((void**)&att16, g_att16);

    cudaFuncSetAttribute(qkv_gemm, cudaFuncAttributeMaxDynamicSharedMemorySize,
                         GEMM_SMEM_BYTES);
    cudaFuncSetAttribute(gemm_out, cudaFuncAttributeMaxDynamicSharedMemorySize,
                         GEMM_SMEM_BYTES);
    cudaFuncSetAttribute(attn_mma, cudaFuncAttributeMaxDynamicSharedMemorySize,
                         ATTN_SMEM_BYTES);

    cvt_f16_all<<<dim3(WN / 1024, 4), 256>>>(Wq, Wk, Wv, Wo, w16);

    qkv_gemm<<<dim3(8, 64, 3), 256, GEMM_SMEM_BYTES>>>(
        q, k, v, w16, bq, bk, bv, cosp, sinp, q16, k16, vt16);

    attn_mma<<<dim3(S_SZ / 64, B_SZ * H_SZ), 128, ATTN_SMEM_BYTES>>>(
        q16, k16, vt16, maskp, apb, att16);

    gemm_out<<<dim3(8, 64), 256, GEMM_SMEM_BYTES>>>(
        att16, w16 + 3 * (size_t)WN, bo, (float*)d_out);
}